// round 1
// baseline (speedup 1.0000x reference)
#include <cuda_runtime.h>
#include <math.h>

#define NP   8192
#define DIN_ 1024
#define DH_  256
#define NEG_INF (-3.402823466e38f)

// ---------------- scratch (allocation-free: __device__ globals) ----------------
__device__ float g_x [NP*DH_];
__device__ float g_eh[NP*DH_];
__device__ float g_et[NP*DH_];
__device__ float g_logits[(size_t)NP*NP];        // 256 MB
__device__ float g_a [NP*DH_];
__device__ float g_m [NP*DH_];
__device__ float g_h [NP*(DH_/2)];
__device__ float g_mean[DH_];
__device__ float g_s[NP];
__device__ float g_stat[2];

__device__ __forceinline__ float leaky_f(float v) { return v > 0.f ? v : 0.01f * v; }

__device__ __forceinline__ float warp_sum(float v) {
    #pragma unroll
    for (int o = 16; o > 0; o >>= 1) v += __shfl_down_sync(0xffffffffu, v, o);
    return v;
}

// ---------------- zero init (mean accumulator + e_g output) ----------------
__global__ void zero_kernel(float* eg) {
    int t = threadIdx.x;
    g_mean[t] = 0.f;
    eg[t] = 0.f;
}

// ---------------- generic NN GEMM: C = [ADD? Cin +] act(A@B + bias) ----------------
// A: M x K row-major, B: K x N row-major. BM=128, BN=64, BK=16, 256 threads, 8x4 micro.
template<bool LEAKY, bool ADD>
__global__ __launch_bounds__(256)
void gemm_nn(const float* __restrict__ A, const float* __restrict__ B,
             const float* __restrict__ bias, const float* __restrict__ Cin,
             float* __restrict__ C, int M, int N, int K)
{
    const int BM = 128, BN = 64, BK = 16;
    __shared__ float As[BK][BM + 4];
    __shared__ float Bs[BK][BN];
    int tid = threadIdx.x;
    int tx = tid & 15, ty = tid >> 4;
    int aRow = tid >> 2, aCol = (tid & 3) * 4;
    int bRow = tid >> 4, bCol = (tid & 15) * 4;
    const float* Ab = A + (size_t)(blockIdx.y * BM) * K;
    const float* Bb = B + blockIdx.x * BN;

    float acc[8][4];
    #pragma unroll
    for (int i = 0; i < 8; i++)
        #pragma unroll
        for (int j = 0; j < 4; j++) acc[i][j] = 0.f;

    for (int k0 = 0; k0 < K; k0 += BK) {
        #pragma unroll
        for (int r = 0; r < 2; r++) {
            int row = aRow + r * 64;
            float4 v = *(const float4*)(Ab + (size_t)row * K + k0 + aCol);
            As[aCol + 0][row] = v.x; As[aCol + 1][row] = v.y;
            As[aCol + 2][row] = v.z; As[aCol + 3][row] = v.w;
        }
        float4 vb = *(const float4*)(Bb + (size_t)(k0 + bRow) * N + bCol);
        *(float4*)&Bs[bRow][bCol] = vb;
        __syncthreads();
        #pragma unroll
        for (int k = 0; k < BK; k++) {
            float4 a0 = *(const float4*)&As[k][ty * 8];
            float4 a1 = *(const float4*)&As[k][ty * 8 + 4];
            float4 b0 = *(const float4*)&Bs[k][tx * 4];
            float ra[8] = {a0.x, a0.y, a0.z, a0.w, a1.x, a1.y, a1.z, a1.w};
            float rb[4] = {b0.x, b0.y, b0.z, b0.w};
            #pragma unroll
            for (int i = 0; i < 8; i++)
                #pragma unroll
                for (int j = 0; j < 4; j++) acc[i][j] = fmaf(ra[i], rb[j], acc[i][j]);
        }
        __syncthreads();
    }

    int row0 = blockIdx.y * BM + ty * 8;
    int col0 = blockIdx.x * BN + tx * 4;
    #pragma unroll
    for (int i = 0; i < 8; i++) {
        #pragma unroll
        for (int j = 0; j < 4; j++) {
            float v = acc[i][j] + bias[col0 + j];
            if (LEAKY) v = leaky_f(v);
            if (ADD)   v += Cin[(size_t)(row0 + i) * N + col0 + j];
            C[(size_t)(row0 + i) * N + col0 + j] = v;
        }
    }
}

// ---------------- NT GEMM (attention logits): C = SCALE * A @ B^T ----------------
// A,B: 8192 x 256 row-major. BM=BN=128, BK=16, 256 threads, 8x8 micro.
__global__ __launch_bounds__(256)
void gemm_nt(const float* __restrict__ A, const float* __restrict__ B,
             float* __restrict__ C)
{
    const int BK = 16;
    __shared__ float As[BK][128 + 4];
    __shared__ float Bs[BK][128 + 4];
    int tid = threadIdx.x;
    int tx = tid & 15, ty = tid >> 4;
    int lRow = tid >> 2, lCol = (tid & 3) * 4;
    const float* Ab = A + (size_t)(blockIdx.y * 128) * DH_;
    const float* Bb = B + (size_t)(blockIdx.x * 128) * DH_;

    float acc[8][8];
    #pragma unroll
    for (int i = 0; i < 8; i++)
        #pragma unroll
        for (int j = 0; j < 8; j++) acc[i][j] = 0.f;

    for (int k0 = 0; k0 < DH_; k0 += BK) {
        #pragma unroll
        for (int r = 0; r < 2; r++) {
            int row = lRow + r * 64;
            float4 va = *(const float4*)(Ab + (size_t)row * DH_ + k0 + lCol);
            As[lCol + 0][row] = va.x; As[lCol + 1][row] = va.y;
            As[lCol + 2][row] = va.z; As[lCol + 3][row] = va.w;
            float4 vb = *(const float4*)(Bb + (size_t)row * DH_ + k0 + lCol);
            Bs[lCol + 0][row] = vb.x; Bs[lCol + 1][row] = vb.y;
            Bs[lCol + 2][row] = vb.z; Bs[lCol + 3][row] = vb.w;
        }
        __syncthreads();
        #pragma unroll
        for (int k = 0; k < BK; k++) {
            float4 a0 = *(const float4*)&As[k][ty * 8];
            float4 a1 = *(const float4*)&As[k][ty * 8 + 4];
            float4 b0 = *(const float4*)&Bs[k][tx * 8];
            float4 b1 = *(const float4*)&Bs[k][tx * 8 + 4];
            float ra[8] = {a0.x, a0.y, a0.z, a0.w, a1.x, a1.y, a1.z, a1.w};
            float rb[8] = {b0.x, b0.y, b0.z, b0.w, b1.x, b1.y, b1.z, b1.w};
            #pragma unroll
            for (int i = 0; i < 8; i++)
                #pragma unroll
                for (int j = 0; j < 8; j++) acc[i][j] = fmaf(ra[i], rb[j], acc[i][j]);
        }
        __syncthreads();
    }

    size_t row0 = (size_t)blockIdx.y * 128 + ty * 8;
    int col0 = blockIdx.x * 128 + tx * 8;
    #pragma unroll
    for (int i = 0; i < 8; i++) {
        float* cp = C + (row0 + i) * NP + col0;
        float4 o0 = make_float4(acc[i][0]*0.0625f, acc[i][1]*0.0625f, acc[i][2]*0.0625f, acc[i][3]*0.0625f);
        float4 o1 = make_float4(acc[i][4]*0.0625f, acc[i][5]*0.0625f, acc[i][6]*0.0625f, acc[i][7]*0.0625f);
        *(float4*)(cp + 0) = o0;
        *(float4*)(cp + 4) = o1;
    }
}

// ---------------- column sums of g_x (for mean mixing) ----------------
__global__ void colsum_kernel() {
    int t = threadIdx.x;               // 256 = column
    int r0 = blockIdx.x * 256;         // 32 blocks
    float s = 0.f;
    for (int r = 0; r < 256; r++) s += g_x[(size_t)(r0 + r) * DH_ + t];
    atomicAdd(&g_mean[t], s);
}

__global__ void mix_kernel() {
    int idx = blockIdx.x * blockDim.x + threadIdx.x;  // 2048 x 1024
    float mean = g_mean[idx & (DH_ - 1)] * (1.f / (float)NP);
    g_x[idx] = (g_x[idx] + mean) * 0.5f;
}

// ---------------- fused top-k + softmax + gather + message construction ----------------
// One block (128 threads) per row i. Writes g_a = e_h + e_Nh, g_m = e_h * e_Nh.
__global__ __launch_bounds__(128)
void topk_msg_kernel() {
    int i = blockIdx.x;
    int t = threadIdx.x;
    const float* row = g_logits + (size_t)i * NP;

    // per-thread top-6 (sorted descending), all-constant indexing
    float lv[6]; int li[6];
    #pragma unroll
    for (int k = 0; k < 6; k++) { lv[k] = NEG_INF; li[k] = 0; }
    for (int c = t; c < NP; c += 128) {
        float v = row[c];
        if (v > lv[5]) {
            lv[5] = v; li[5] = c;
            #pragma unroll
            for (int k = 5; k > 0; k--) {
                if (lv[k] > lv[k - 1]) {
                    float tv = lv[k]; lv[k] = lv[k - 1]; lv[k - 1] = tv;
                    int   ti = li[k]; li[k] = li[k - 1]; li[k - 1] = ti;
                }
            }
        }
    }

    // merge: 6 rounds of block argmax over each thread's current head
    __shared__ float sv[128]; __shared__ int si[128];
    __shared__ float topv[6]; __shared__ int topi[6];
    for (int r = 0; r < 6; r++) {
        sv[t] = lv[0]; si[t] = t;
        __syncthreads();
        #pragma unroll
        for (int o = 64; o > 0; o >>= 1) {
            if (t < o && sv[t + o] > sv[t]) { sv[t] = sv[t + o]; si[t] = si[t + o]; }
            __syncthreads();
        }
        if (t == si[0]) {
            topv[r] = lv[0]; topi[r] = li[0];
            #pragma unroll
            for (int k = 0; k < 5; k++) { lv[k] = lv[k + 1]; li[k] = li[k + 1]; }
            lv[5] = NEG_INF;
        }
        __syncthreads();
    }

    // softmax p over top-6 (redundant per thread)
    float tv[6]; int ti[6];
    #pragma unroll
    for (int k = 0; k < 6; k++) { tv[k] = topv[k]; ti[k] = topi[k]; }
    float pm = tv[0];
    #pragma unroll
    for (int k = 1; k < 6; k++) pm = fmaxf(pm, tv[k]);
    float pk[6], ps = 0.f;
    #pragma unroll
    for (int k = 0; k < 6; k++) { pk[k] = expf(tv[k] - pm); ps += pk[k]; }
    float pinv = 1.f / ps;
    #pragma unroll
    for (int k = 0; k < 6; k++) pk[k] *= pinv;

    // message phase: each thread owns dims d = t, t+128
    float ehv[2]; float nb[6][2];
    #pragma unroll
    for (int u = 0; u < 2; u++) ehv[u] = g_eh[(size_t)i * DH_ + t + u * 128];
    #pragma unroll
    for (int k = 0; k < 6; k++)
        #pragma unroll
        for (int u = 0; u < 2; u++)
            nb[k][u] = g_et[(size_t)ti[k] * DH_ + t + u * 128];

    float sN[6], sG[6];
    #pragma unroll
    for (int k = 0; k < 6; k++) { sN[k] = 0.f; sG[k] = 0.f; }
    #pragma unroll
    for (int k = 0; k < 6; k++) {
        #pragma unroll
        for (int u = 0; u < 2; u++) {
            float ehr = pk[k] * nb[k][u] + (1.f - pk[k]) * ehv[u];
            float gt  = tanhf(ehv[u] + ehr);
            sN[k] += nb[k][u];
            sG[k] += gt;
        }
    }

    // block reduce 12 partials
    __shared__ float part[4][12];
    __shared__ float tot[12];
    int lane = t & 31, wp = t >> 5;
    #pragma unroll
    for (int q = 0; q < 6; q++) {
        float v = warp_sum(sN[q]); if (lane == 0) part[wp][q]     = v;
        float w = warp_sum(sG[q]); if (lane == 0) part[wp][6 + q] = w;
    }
    __syncthreads();
    if (t < 12) tot[t] = part[0][t] + part[1][t] + part[2][t] + part[3][t];
    __syncthreads();

    float kw[6], km = NEG_INF;
    #pragma unroll
    for (int k = 0; k < 6; k++) { kw[k] = tot[k] * tot[6 + k]; km = fmaxf(km, kw[k]); }
    float kp[6], ks = 0.f;
    #pragma unroll
    for (int k = 0; k < 6; k++) { kp[k] = expf(kw[k] - km); ks += kp[k]; }
    float kinv = 1.f / ks;

    #pragma unroll
    for (int u = 0; u < 2; u++) {
        float eN = 0.f;
        #pragma unroll
        for (int k = 0; k < 6; k++) eN += kp[k] * kinv * nb[k][u];
        int d = t + u * 128;
        float e = ehv[u];
        g_a[(size_t)i * DH_ + d] = e + eN;
        g_m[(size_t)i * DH_ + d] = e * eN;
    }
}

// ---------------- readout score: s_i = h_i . Ag2 + bg2 ----------------
__global__ __launch_bounds__(128)
void score_kernel(const float* __restrict__ Ag2, const float* __restrict__ bg2) {
    int i = blockIdx.x, t = threadIdx.x;  // 128
    float v = g_h[(size_t)i * 128 + t] * Ag2[t];
    v = warp_sum(v);
    __shared__ float p[4];
    if ((t & 31) == 0) p[t >> 5] = v;
    __syncthreads();
    if (t == 0) g_s[i] = p[0] + p[1] + p[2] + p[3] + bg2[0];
}

// ---------------- softmax stats over 8192 scores ----------------
__global__ __launch_bounds__(1024)
void stat_kernel() {
    int t = threadIdx.x;
    __shared__ float sm[1024];
    float m = NEG_INF;
    for (int i = t; i < NP; i += 1024) m = fmaxf(m, g_s[i]);
    sm[t] = m; __syncthreads();
    for (int o = 512; o > 0; o >>= 1) { if (t < o) sm[t] = fmaxf(sm[t], sm[t + o]); __syncthreads(); }
    float mx = sm[0];
    __syncthreads();
    float e = 0.f;
    for (int i = t; i < NP; i += 1024) e += expf(g_s[i] - mx);
    sm[t] = e; __syncthreads();
    for (int o = 512; o > 0; o >>= 1) { if (t < o) sm[t] += sm[t + o]; __syncthreads(); }
    if (t == 0) { g_stat[0] = mx; g_stat[1] = sm[0]; }
}

// ---------------- weighted sum: e_g = sum_i softmax(s)_i * e_msg_i ----------------
__global__ __launch_bounds__(256)
void accum_kernel(const float* __restrict__ emsg, float* __restrict__ eg) {
    int t = threadIdx.x;                 // column
    int r0 = blockIdx.x * 256;           // 32 blocks
    __shared__ float w[256];
    float mx = g_stat[0], inv = 1.f / g_stat[1];
    w[t] = expf(g_s[r0 + t] - mx) * inv;
    __syncthreads();
    float acc = 0.f;
    for (int r = 0; r < 256; r++) acc += w[r] * emsg[(size_t)(r0 + r) * DH_ + t];
    atomicAdd(&eg[t], acc);
}

// ---------------- launcher ----------------
extern "C" void kernel_launch(void* const* d_in, const int* in_sizes, int n_in,
                              void* d_out, int out_size) {
    const float* x_path = (const float*)d_in[0];
    const float* fc1_W  = (const float*)d_in[1];
    const float* fc1_b  = (const float*)d_in[2];
    const float* Wh     = (const float*)d_in[3];
    const float* bh     = (const float*)d_in[4];
    const float* Wt     = (const float*)d_in[5];
    const float* bt     = (const float*)d_in[6];
    const float* W1     = (const float*)d_in[7];
    const float* b1     = (const float*)d_in[8];
    const float* W2     = (const float*)d_in[9];
    const float* b2     = (const float*)d_in[10];
    const float* Ag1    = (const float*)d_in[11];
    const float* bg1    = (const float*)d_in[12];
    const float* Ag2    = (const float*)d_in[13];
    const float* bg2    = (const float*)d_in[14];

    float* out    = (float*)d_out;               // e_msg: 8192 x 256
    float* out_eg = out + (size_t)NP * DH_;      // e_g: 256

    void *px, *peh, *pet, *plog, *pa, *pm, *ph;
    cudaGetSymbolAddress(&px,  g_x);
    cudaGetSymbolAddress(&peh, g_eh);
    cudaGetSymbolAddress(&pet, g_et);
    cudaGetSymbolAddress(&plog, g_logits);
    cudaGetSymbolAddress(&pa,  g_a);
    cudaGetSymbolAddress(&pm,  g_m);
    cudaGetSymbolAddress(&ph,  g_h);

    zero_kernel<<<1, 256>>>(out_eg);

    // fc1 + leaky
    gemm_nn<true, false><<<dim3(4, 64), 256>>>(x_path, fc1_W, fc1_b, nullptr,
                                               (float*)px, NP, DH_, DIN_);
    // mean-mix
    colsum_kernel<<<32, 256>>>();
    mix_kernel<<<2048, 1024>>>();

    // e_h, e_t
    gemm_nn<false, false><<<dim3(4, 64), 256>>>((const float*)px, Wh, bh, nullptr,
                                                (float*)peh, NP, DH_, DH_);
    gemm_nn<false, false><<<dim3(4, 64), 256>>>((const float*)px, Wt, bt, nullptr,
                                                (float*)pet, NP, DH_, DH_);

    // attention logits (dominant GEMM)
    gemm_nt<<<dim3(64, 64), 256>>>((const float*)peh, (const float*)pet, (float*)plog);

    // fused top-k + message construction
    topk_msg_kernel<<<NP, 128>>>();

    // e_msg = leaky(a@W1+b1) + leaky(m@W2+b2), written into d_out
    gemm_nn<true, false><<<dim3(4, 64), 256>>>((const float*)pa, W1, b1, nullptr,
                                               out, NP, DH_, DH_);
    gemm_nn<true, true><<<dim3(4, 64), 256>>>((const float*)pm, W2, b2, out,
                                              out, NP, DH_, DH_);

    // readout
    gemm_nn<true, false><<<dim3(2, 64), 256>>>(out, Ag1, bg1, nullptr,
                                               (float*)ph, NP, DH_ / 2, DH_);
    score_kernel<<<NP, 128>>>(Ag2, bg2);
    stat_kernel<<<1, 1024>>>();
    accum_kernel<<<32, 256>>>(out, out_eg);
}

// round 3
// speedup vs baseline: 1.3602x; 1.3602x over previous
#include <cuda_runtime.h>
#include <cuda_bf16.h>
#include <math.h>
#include <stdint.h>

#define NP   8192
#define DIN_ 1024
#define DH_  256
#define KSPLIT 768              // [hi|hi|lo] x [hi|lo|hi]
#define CANDS 384               // 64 col-blocks x 6
#define NEG_INF (-3.402823466e38f)

// ---------------- scratch (allocation-free: __device__ globals) ----------------
__device__ float g_x [NP*DH_];
__device__ float g_eh[NP*DH_];
__device__ float g_et[NP*DH_];
__device__ __nv_bfloat16 g_Ahl[(size_t)NP*KSPLIT];   // e_h split, K-major
__device__ __nv_bfloat16 g_Bhl[(size_t)NP*KSPLIT];   // e_t split, K-major
__device__ float g_candv[(size_t)NP*CANDS];
__device__ int   g_candi[(size_t)NP*CANDS];
__device__ float g_a [NP*DH_];
__device__ float g_m [NP*DH_];
__device__ float g_h [NP*(DH_/2)];
__device__ float g_mean[DH_];
__device__ float g_s[NP];
__device__ float g_stat[2];

__device__ __forceinline__ float leaky_f(float v) { return v > 0.f ? v : 0.01f * v; }

__device__ __forceinline__ float warp_sum(float v) {
    #pragma unroll
    for (int o = 16; o > 0; o >>= 1) v += __shfl_down_sync(0xffffffffu, v, o);
    return v;
}

// ---------------- PTX helpers (cp.async / ldmatrix / mma.sync) ----------------
__device__ __forceinline__ uint32_t smem_u32(const void* p) {
    uint32_t a;
    asm("{ .reg .u64 t; cvta.to.shared.u64 t, %1; cvt.u32.u64 %0, t; }" : "=r"(a) : "l"(p));
    return a;
}
__device__ __forceinline__ void cp16(uint32_t dst, const void* src) {
    asm volatile("cp.async.cg.shared.global [%0], [%1], 16;" :: "r"(dst), "l"(src));
}
#define CP_COMMIT()  asm volatile("cp.async.commit_group;" ::: "memory")
#define CP_WAIT2()   asm volatile("cp.async.wait_group 2;" ::: "memory")

__device__ __forceinline__ void ldsm_x4(uint32_t (&r)[4], uint32_t addr) {
    asm volatile("ldmatrix.sync.aligned.m8n8.x4.shared.b16 {%0,%1,%2,%3}, [%4];"
                 : "=r"(r[0]), "=r"(r[1]), "=r"(r[2]), "=r"(r[3]) : "r"(addr));
}
__device__ __forceinline__ void mma_bf16(float (&d)[4], const uint32_t (&a)[4],
                                         const uint32_t* b) {
    asm volatile("mma.sync.aligned.m16n8k16.row.col.f32.bf16.bf16.f32 "
                 "{%0,%1,%2,%3}, {%4,%5,%6,%7}, {%8,%9}, {%0,%1,%2,%3};"
                 : "+f"(d[0]), "+f"(d[1]), "+f"(d[2]), "+f"(d[3])
                 : "r"(a[0]), "r"(a[1]), "r"(a[2]), "r"(a[3]), "r"(b[0]), "r"(b[1]));
}

// ---------------- zero init ----------------
__global__ void zero_kernel(float* eg) {
    int t = threadIdx.x;
    g_mean[t] = 0.f;
    eg[t] = 0.f;
}

// ---------------- generic NN GEMM (SIMT fp32) ----------------
template<bool LEAKY, bool ADD>
__global__ __launch_bounds__(256)
void gemm_nn(const float* __restrict__ A, const float* __restrict__ B,
             const float* __restrict__ bias, const float* __restrict__ Cin,
             float* __restrict__ C, int M, int N, int K)
{
    const int BM = 128, BN = 64, BK = 16;
    __shared__ float As[BK][BM + 4];
    __shared__ float Bs[BK][BN];
    int tid = threadIdx.x;
    int tx = tid & 15, ty = tid >> 4;
    int aRow = tid >> 2, aCol = (tid & 3) * 4;
    int bRow = tid >> 4, bCol = (tid & 15) * 4;
    const float* Ab = A + (size_t)(blockIdx.y * BM) * K;
    const float* Bb = B + blockIdx.x * BN;

    float acc[8][4];
    #pragma unroll
    for (int i = 0; i < 8; i++)
        #pragma unroll
        for (int j = 0; j < 4; j++) acc[i][j] = 0.f;

    for (int k0 = 0; k0 < K; k0 += BK) {
        #pragma unroll
        for (int r = 0; r < 2; r++) {
            int row = aRow + r * 64;
            float4 v = *(const float4*)(Ab + (size_t)row * K + k0 + aCol);
            As[aCol + 0][row] = v.x; As[aCol + 1][row] = v.y;
            As[aCol + 2][row] = v.z; As[aCol + 3][row] = v.w;
        }
        float4 vb = *(const float4*)(Bb + (size_t)(k0 + bRow) * N + bCol);
        *(float4*)&Bs[bRow][bCol] = vb;
        __syncthreads();
        #pragma unroll
        for (int k = 0; k < BK; k++) {
            float4 a0 = *(const float4*)&As[k][ty * 8];
            float4 a1 = *(const float4*)&As[k][ty * 8 + 4];
            float4 b0 = *(const float4*)&Bs[k][tx * 4];
            float ra[8] = {a0.x, a0.y, a0.z, a0.w, a1.x, a1.y, a1.z, a1.w};
            float rb[4] = {b0.x, b0.y, b0.z, b0.w};
            #pragma unroll
            for (int i = 0; i < 8; i++)
                #pragma unroll
                for (int j = 0; j < 4; j++) acc[i][j] = fmaf(ra[i], rb[j], acc[i][j]);
        }
        __syncthreads();
    }

    int row0 = blockIdx.y * BM + ty * 8;
    int col0 = blockIdx.x * BN + tx * 4;
    #pragma unroll
    for (int i = 0; i < 8; i++) {
        #pragma unroll
        for (int j = 0; j < 4; j++) {
            float v = acc[i][j] + bias[col0 + j];
            if (LEAKY) v = leaky_f(v);
            if (ADD)   v += Cin[(size_t)(row0 + i) * N + col0 + j];
            C[(size_t)(row0 + i) * N + col0 + j] = v;
        }
    }
}

// ---------------- column sums / mean mix ----------------
__global__ void colsum_kernel() {
    int t = threadIdx.x;
    int r0 = blockIdx.x * 256;
    float s = 0.f;
    for (int r = 0; r < 256; r++) s += g_x[(size_t)(r0 + r) * DH_ + t];
    atomicAdd(&g_mean[t], s);
}

__global__ void mix_kernel() {
    int idx = blockIdx.x * blockDim.x + threadIdx.x;
    float mean = g_mean[idx & (DH_ - 1)] * (1.f / (float)NP);
    g_x[idx] = (g_x[idx] + mean) * 0.5f;
}

// ---------------- fp32 -> bf16 hi/lo split into K=768 layout ----------------
__global__ __launch_bounds__(256)
void convert_kernel() {
    int idx = blockIdx.x * 256 + threadIdx.x;   // NP*DH elems
    int row = idx >> 8, col = idx & 255;
    size_t b = (size_t)row * KSPLIT;

    float vh = g_eh[idx];
    __nv_bfloat16 h = __float2bfloat16(vh);
    __nv_bfloat16 l = __float2bfloat16(vh - __bfloat162float(h));
    g_Ahl[b + col]       = h;
    g_Ahl[b + 256 + col] = h;
    g_Ahl[b + 512 + col] = l;

    float vt = g_et[idx];
    __nv_bfloat16 th = __float2bfloat16(vt);
    __nv_bfloat16 tl = __float2bfloat16(vt - __bfloat162float(th));
    g_Bhl[b + col]       = th;
    g_Bhl[b + 256 + col] = tl;
    g_Bhl[b + 512 + col] = th;
}

// ---------------- mma.sync NT GEMM + fused per-block top-6 ----------------
// C[8192,8192] = (1/16) * Ahl @ Bhl^T.  Per CTA: 128x128 tile, K=768 in 24
// chunks of 32, 3-stage cp.async pipeline. Epilogue stages accums via smem and
// emits per-row top-6 over this CTA's 128 columns.
#define STAGE_B 20480                 // A 128x80 + B 128x80
#define SMEM_DYN (3 * STAGE_B)        // 61440; epilogue (64x129 f32) reuses it

__global__ __launch_bounds__(256, 2)
void gemm_nt_mma() {
    extern __shared__ char smem[];
    float (*sEpi)[129] = (float(*)[129])smem;
    const int tid = threadIdx.x;
    const int wid = tid >> 5, lane = tid & 31;
    const int wr = wid >> 2, wc = wid & 3;     // warp grid 2x4
    const int bx = blockIdx.x, by = blockIdx.y;

    uint32_t sb = smem_u32(smem);
    const char* Abase = ((const char*)g_Ahl) + (size_t)(by * 128) * (KSPLIT * 2);
    const char* Bbase = ((const char*)g_Bhl) + (size_t)(bx * 128) * (KSPLIT * 2);

    auto load_chunk = [&](int c, int s) {
        uint32_t aSt = sb + s * STAGE_B;
        uint32_t bSt = aSt + 10240;
        int coff = c * 64;
        #pragma unroll
        for (int j = 0; j < 2; j++) {
            int q = tid + j * 256;
            int r = q >> 2, cc = q & 3;
            cp16(aSt + r * 80 + cc * 16, Abase + (size_t)r * (KSPLIT*2) + coff + cc * 16);
            cp16(bSt + r * 80 + cc * 16, Bbase + (size_t)r * (KSPLIT*2) + coff + cc * 16);
        }
    };

    float d[4][4][4];
    #pragma unroll
    for (int mf = 0; mf < 4; mf++)
        #pragma unroll
        for (int nf = 0; nf < 4; nf++)
            #pragma unroll
            for (int q = 0; q < 4; q++) d[mf][nf][q] = 0.f;

    load_chunk(0, 0); CP_COMMIT();
    load_chunk(1, 1); CP_COMMIT();
    load_chunk(2, 2); CP_COMMIT();

    // ldmatrix address components (constant across iterations)
    const int arow_j = ((lane >> 3) & 1) * 8 + (lane & 7);
    const int akb    = (lane >> 4) * 16;
    const int bj     = lane >> 3;
    const int bn_off = (bj >> 1) * 8 + (lane & 7);
    const int bkb    = (bj & 1) * 16;

    for (int c = 0; c < 24; c++) {
        CP_WAIT2();
        __syncthreads();
        int s = c % 3;
        uint32_t aSt = sb + s * STAGE_B;
        uint32_t bSt = aSt + 10240;

        #pragma unroll
        for (int ks = 0; ks < 2; ks++) {
            uint32_t a[4][4], b[4][2];
            #pragma unroll
            for (int mf = 0; mf < 4; mf++) {
                int row = wr * 64 + mf * 16 + arow_j;
                ldsm_x4(a[mf], aSt + row * 80 + akb + ks * 32);
            }
            {
                uint32_t bv[4];
                int row0 = wc * 32 + bn_off;
                ldsm_x4(bv, bSt + row0 * 80 + bkb + ks * 32);
                b[0][0] = bv[0]; b[0][1] = bv[1]; b[1][0] = bv[2]; b[1][1] = bv[3];
                int row1 = row0 + 16;
                ldsm_x4(bv, bSt + row1 * 80 + bkb + ks * 32);
                b[2][0] = bv[0]; b[2][1] = bv[1]; b[3][0] = bv[2]; b[3][1] = bv[3];
            }
            #pragma unroll
            for (int mf = 0; mf < 4; mf++)
                #pragma unroll
                for (int nf = 0; nf < 4; nf++)
                    mma_bf16(d[mf][nf], a[mf], b[nf]);
        }
        __syncthreads();
        if (c + 3 < 24) load_chunk(c + 3, (c + 3) % 3);
        CP_COMMIT();
    }

    // ---- epilogue: stage 64-row halves in smem, per-row top-6 over 128 cols ----
    const int g = lane >> 2, tq = lane & 3;
    #pragma unroll
    for (int ph = 0; ph < 2; ph++) {
        __syncthreads();
        if (wr == ph) {
            #pragma unroll
            for (int mf = 0; mf < 4; mf++) {
                int lr = mf * 16 + g;
                #pragma unroll
                for (int nf = 0; nf < 4; nf++) {
                    int col = wc * 32 + nf * 8 + tq * 2;
                    sEpi[lr][col]         = d[mf][nf][0];
                    sEpi[lr][col + 1]     = d[mf][nf][1];
                    sEpi[lr + 8][col]     = d[mf][nf][2];
                    sEpi[lr + 8][col + 1] = d[mf][nf][3];
                }
            }
        }
        __syncthreads();
        if (tid < 64) {
            float v[6]; int ix[6];
            #pragma unroll
            for (int k = 0; k < 6; k++) { v[k] = NEG_INF; ix[k] = 0; }
            int cb = bx * 128;
            for (int j = 0; j < 128; j++) {
                float val = sEpi[tid][j] * 0.0625f;
                if (val > v[5]) {
                    v[5] = val; ix[5] = cb + j;
                    #pragma unroll
                    for (int k = 5; k > 0; k--) {
                        if (v[k] > v[k - 1]) {
                            float tv = v[k]; v[k] = v[k - 1]; v[k - 1] = tv;
                            int   ti = ix[k]; ix[k] = ix[k - 1]; ix[k - 1] = ti;
                        }
                    }
                }
            }
            size_t row = (size_t)by * 128 + ph * 64 + tid;
            size_t o = row * CANDS + bx * 6;
            #pragma unroll
            for (int k = 0; k < 6; k++) { g_candv[o + k] = v[k]; g_candi[o + k] = ix[k]; }
        }
    }
}

// ---------------- top-k candidate reduce + softmax + message construction ----------------
__global__ __launch_bounds__(128)
void topk_msg_kernel() {
    int i = blockIdx.x;
    int t = threadIdx.x;
    const float* cv = g_candv + (size_t)i * CANDS;
    const int*   ci = g_candi + (size_t)i * CANDS;

    float lv[6]; int li[6];
    #pragma unroll
    for (int k = 0; k < 6; k++) { lv[k] = NEG_INF; li[k] = 0; }
    for (int c = t; c < CANDS; c += 128) {
        float v = cv[c];
        if (v > lv[5]) {
            lv[5] = v; li[5] = ci[c];
            #pragma unroll
            for (int k = 5; k > 0; k--) {
                if (lv[k] > lv[k - 1]) {
                    float tv = lv[k]; lv[k] = lv[k - 1]; lv[k - 1] = tv;
                    int   tx = li[k]; li[k] = li[k - 1]; li[k - 1] = tx;
                }
            }
        }
    }

    __shared__ float sv[128]; __shared__ int si[128];
    __shared__ float topv[6]; __shared__ int topi[6];
    for (int r = 0; r < 6; r++) {
        sv[t] = lv[0]; si[t] = t;
        __syncthreads();
        #pragma unroll
        for (int o = 64; o > 0; o >>= 1) {
            if (t < o && sv[t + o] > sv[t]) { sv[t] = sv[t + o]; si[t] = si[t + o]; }
            __syncthreads();
        }
        if (t == si[0]) {
            topv[r] = lv[0]; topi[r] = li[0];
            #pragma unroll
            for (int k = 0; k < 5; k++) { lv[k] = lv[k + 1]; li[k] = li[k + 1]; }
            lv[5] = NEG_INF;
        }
        __syncthreads();
    }

    float tv[6]; int ti[6];
    #pragma unroll
    for (int k = 0; k < 6; k++) { tv[k] = topv[k]; ti[k] = topi[k]; }
    float pm = tv[0];
    #pragma unroll
    for (int k = 1; k < 6; k++) pm = fmaxf(pm, tv[k]);
    float pk[6], ps = 0.f;
    #pragma unroll
    for (int k = 0; k < 6; k++) { pk[k] = expf(tv[k] - pm); ps += pk[k]; }
    float pinv = 1.f / ps;
    #pragma unroll
    for (int k = 0; k < 6; k++) pk[k] *= pinv;

    float ehv[2]; float nb[6][2];
    #pragma unroll
    for (int u = 0; u < 2; u++) ehv[u] = g_eh[(size_t)i * DH_ + t + u * 128];
    #pragma unroll
    for (int k = 0; k < 6; k++)
        #pragma unroll
        for (int u = 0; u < 2; u++)
            nb[k][u] = g_et[(size_t)ti[k] * DH_ + t + u * 128];

    float sN[6], sG[6];
    #pragma unroll
    for (int k = 0; k < 6; k++) { sN[k] = 0.f; sG[k] = 0.f; }
    #pragma unroll
    for (int k = 0; k < 6; k++) {
        #pragma unroll
        for (int u = 0; u < 2; u++) {
            float ehr = pk[k] * nb[k][u] + (1.f - pk[k]) * ehv[u];
            float gt  = tanhf(ehv[u] + ehr);
            sN[k] += nb[k][u];
            sG[k] += gt;
        }
    }

    __shared__ float part[4][12];
    __shared__ float tot[12];
    int lane = t & 31, wp = t >> 5;
    #pragma unroll
    for (int q = 0; q < 6; q++) {
        float v = warp_sum(sN[q]); if (lane == 0) part[wp][q]     = v;
        float w = warp_sum(sG[q]); if (lane == 0) part[wp][6 + q] = w;
    }
    __syncthreads();
    if (t < 12) tot[t] = part[0][t] + part[1][t] + part[2][t] + part[3][t];
    __syncthreads();

    float kw[6], km = NEG_INF;
    #pragma unroll
    for (int k = 0; k < 6; k++) { kw[k] = tot[k] * tot[6 + k]; km = fmaxf(km, kw[k]); }
    float kp[6], ks = 0.f;
    #pragma unroll
    for (int k = 0; k < 6; k++) { kp[k] = expf(kw[k] - km); ks += kp[k]; }
    float kinv = 1.f / ks;

    #pragma unroll
    for (int u = 0; u < 2; u++) {
        float eN = 0.f;
        #pragma unroll
        for (int k = 0; k < 6; k++) eN += kp[k] * kinv * nb[k][u];
        int d = t + u * 128;
        float e = ehv[u];
        g_a[(size_t)i * DH_ + d] = e + eN;
        g_m[(size_t)i * DH_ + d] = e * eN;
    }
}

// ---------------- readout ----------------
__global__ __launch_bounds__(128)
void score_kernel(const float* __restrict__ Ag2, const float* __restrict__ bg2) {
    int i = blockIdx.x, t = threadIdx.x;
    float v = g_h[(size_t)i * 128 + t] * Ag2[t];
    v = warp_sum(v);
    __shared__ float p[4];
    if ((t & 31) == 0) p[t >> 5] = v;
    __syncthreads();
    if (t == 0) g_s[i] = p[0] + p[1] + p[2] + p[3] + bg2[0];
}

__global__ __launch_bounds__(1024)
void stat_kernel() {
    int t = threadIdx.x;
    __shared__ float sm[1024];
    float m = NEG_INF;
    for (int i = t; i < NP; i += 1024) m = fmaxf(m, g_s[i]);
    sm[t] = m; __syncthreads();
    for (int o = 512; o > 0; o >>= 1) { if (t < o) sm[t] = fmaxf(sm[t], sm[t + o]); __syncthreads(); }
    float mx = sm[0];
    __syncthreads();
    float e = 0.f;
    for (int i = t; i < NP; i += 1024) e += expf(g_s[i] - mx);
    sm[t] = e; __syncthreads();
    for (int o = 512; o > 0; o >>= 1) { if (t < o) sm[t] += sm[t + o]; __syncthreads(); }
    if (t == 0) { g_stat[0] = mx; g_stat[1] = sm[0]; }
}

__global__ __launch_bounds__(256)
void accum_kernel(const float* __restrict__ emsg, float* __restrict__ eg) {
    int t = threadIdx.x;
    int r0 = blockIdx.x * 256;
    __shared__ float w[256];
    float mx = g_stat[0], inv = 1.f / g_stat[1];
    w[t] = expf(g_s[r0 + t] - mx) * inv;
    __syncthreads();
    float acc = 0.f;
    for (int r = 0; r < 256; r++) acc += w[r] * emsg[(size_t)(r0 + r) * DH_ + t];
    atomicAdd(&eg[t], acc);
}

// ---------------- launcher ----------------
extern "C" void kernel_launch(void* const* d_in, const int* in_sizes, int n_in,
                              void* d_out, int out_size) {
    const float* x_path = (const float*)d_in[0];
    const float* fc1_W  = (const float*)d_in[1];
    const float* fc1_b  = (const float*)d_in[2];
    const float* Wh     = (const float*)d_in[3];
    const float* bh     = (const float*)d_in[4];
    const float* Wt     = (const float*)d_in[5];
    const float* bt     = (const float*)d_in[6];
    const float* W1     = (const float*)d_in[7];
    const float* b1     = (const float*)d_in[8];
    const float* W2     = (const float*)d_in[9];
    const float* b2     = (const float*)d_in[10];
    const float* Ag1    = (const float*)d_in[11];
    const float* bg1    = (const float*)d_in[12];
    const float* Ag2    = (const float*)d_in[13];
    const float* bg2    = (const float*)d_in[14];

    float* out    = (float*)d_out;               // e_msg: 8192 x 256
    float* out_eg = out + (size_t)NP * DH_;      // e_g: 256

    void *px, *peh, *pet, *pa, *pm, *ph;
    cudaGetSymbolAddress(&px,  g_x);
    cudaGetSymbolAddress(&peh, g_eh);
    cudaGetSymbolAddress(&pet, g_et);
    cudaGetSymbolAddress(&pa,  g_a);
    cudaGetSymbolAddress(&pm,  g_m);
    cudaGetSymbolAddress(&ph,  g_h);

    cudaFuncSetAttribute(gemm_nt_mma, cudaFuncAttributeMaxDynamicSharedMemorySize, SMEM_DYN);

    zero_kernel<<<1, 256>>>(out_eg);

    // fc1 + leaky
    gemm_nn<true, false><<<dim3(4, 64), 256>>>(x_path, fc1_W, fc1_b, nullptr,
                                               (float*)px, NP, DH_, DIN_);
    // mean-mix
    colsum_kernel<<<32, 256>>>();
    mix_kernel<<<2048, 1024>>>();

    // e_h, e_t
    gemm_nn<false, false><<<dim3(4, 64), 256>>>((const float*)px, Wh, bh, nullptr,
                                                (float*)peh, NP, DH_, DH_);
    gemm_nn<false, false><<<dim3(4, 64), 256>>>((const float*)px, Wt, bt, nullptr,
                                                (float*)pet, NP, DH_, DH_);

    // bf16 hi/lo split
    convert_kernel<<<NP, 256>>>();

    // tensor-core (mma.sync) attention logits + fused per-block top-6
    gemm_nt_mma<<<dim3(64, 64), 256, SMEM_DYN>>>();

    // candidate reduce + message construction
    topk_msg_kernel<<<NP, 128>>>();

    // e_msg = leaky(a@W1+b1) + leaky(m@W2+b2), written into d_out
    gemm_nn<true, false><<<dim3(4, 64), 256>>>((const float*)pa, W1, b1, nullptr,
                                               out, NP, DH_, DH_);
    gemm_nn<true, true><<<dim3(4, 64), 256>>>((const float*)pm, W2, b2, out,
                                              out, NP, DH_, DH_);

    // readout
    gemm_nn<true, false><<<dim3(2, 64), 256>>>(out, Ag1, bg1, nullptr,
                                               (float*)ph, NP, DH_ / 2, DH_);
    score_kernel<<<NP, 128>>>(Ag2, bg2);
    stat_kernel<<<1, 1024>>>();
    accum_kernel<<<32, 256>>>(out, out_eg);
}

// round 5
// speedup vs baseline: 1.5043x; 1.1060x over previous
#include <cuda_runtime.h>
#include <cuda_bf16.h>
#include <math.h>
#include <stdint.h>

#define NP   8192
#define DIN_ 1024
#define DH_  256
#define KSP  768                 // 3*DH split width
#define KSP_FC 3072              // 3*DIN split width
#define CANDS 384
#define NEG_INF (-3.402823466e38f)

// ---------------- scratch (allocation-free: __device__ globals) ----------------
__device__ float g_x [NP*DH_];
__device__ float g_eh[NP*DH_];
__device__ float g_et[NP*DH_];
__device__ __nv_bfloat16 g_Ps [(size_t)NP*KSP_FC];  // x_path split
__device__ __nv_bfloat16 g_Xs [(size_t)NP*KSP];     // mixed x split (A-side)
__device__ __nv_bfloat16 g_Ahl[(size_t)NP*KSP];     // e_h split (A-side)
__device__ __nv_bfloat16 g_Bhl[(size_t)NP*KSP];     // e_t split (B-side)
__device__ __nv_bfloat16 g_As [(size_t)NP*KSP];     // a split
__device__ __nv_bfloat16 g_Ms [(size_t)NP*KSP];     // m split
__device__ __nv_bfloat16 g_Es [(size_t)NP*KSP];     // e_msg split
__device__ __nv_bfloat16 g_Wfc1s[(size_t)DH_*KSP_FC];
__device__ __nv_bfloat16 g_Whs [DH_*KSP];
__device__ __nv_bfloat16 g_Wts [DH_*KSP];
__device__ __nv_bfloat16 g_W1s [DH_*KSP];
__device__ __nv_bfloat16 g_W2s [DH_*KSP];
__device__ __nv_bfloat16 g_Ag1s[(DH_/2)*KSP];
__device__ float g_candv[(size_t)NP*CANDS];
__device__ int   g_candi[(size_t)NP*CANDS];
__device__ float g_h [NP*(DH_/2)];
__device__ float g_mean[DH_];
__device__ float g_s[NP];
__device__ float g_stat[2];

__device__ __forceinline__ float leaky_f(float v) { return v > 0.f ? v : 0.01f * v; }

__device__ __forceinline__ float warp_sum(float v) {
    #pragma unroll
    for (int o = 16; o > 0; o >>= 1) v += __shfl_down_sync(0xffffffffu, v, o);
    return v;
}

// ---------------- PTX helpers ----------------
__device__ __forceinline__ uint32_t smem_u32(const void* p) {
    uint32_t a;
    asm("{ .reg .u64 t; cvta.to.shared.u64 t, %1; cvt.u32.u64 %0, t; }" : "=r"(a) : "l"(p));
    return a;
}
__device__ __forceinline__ void cp16(uint32_t dst, const void* src) {
    asm volatile("cp.async.cg.shared.global [%0], [%1], 16;" :: "r"(dst), "l"(src));
}
#define CP_COMMIT()  asm volatile("cp.async.commit_group;" ::: "memory")
#define CP_WAIT2()   asm volatile("cp.async.wait_group 2;" ::: "memory")

__device__ __forceinline__ void ldsm_x4(uint32_t (&r)[4], uint32_t addr) {
    asm volatile("ldmatrix.sync.aligned.m8n8.x4.shared.b16 {%0,%1,%2,%3}, [%4];"
                 : "=r"(r[0]), "=r"(r[1]), "=r"(r[2]), "=r"(r[3]) : "r"(addr));
}
__device__ __forceinline__ void mma_bf16(float (&d)[4], const uint32_t (&a)[4],
                                         const uint32_t* b) {
    asm volatile("mma.sync.aligned.m16n8k16.row.col.f32.bf16.bf16.f32 "
                 "{%0,%1,%2,%3}, {%4,%5,%6,%7}, {%8,%9}, {%0,%1,%2,%3};"
                 : "+f"(d[0]), "+f"(d[1]), "+f"(d[2]), "+f"(d[3])
                 : "r"(a[0]), "r"(a[1]), "r"(a[2]), "r"(a[3]), "r"(b[0]), "r"(b[1]));
}

// ---------------- zero init ----------------
__global__ void zero_kernel(float* eg) {
    int t = threadIdx.x;
    g_mean[t] = 0.f;
    eg[t] = 0.f;
}

// ---------------- weight split+transpose: W (K x N) -> Ws (N x 3K) [h|l|h] ----------------
__global__ void splitw_kernel(const float* __restrict__ W, __nv_bfloat16* __restrict__ out,
                              int K, int N) {
    int idx = blockIdx.x * 256 + threadIdx.x;
    if (idx >= K * N) return;
    int k = idx / N, n = idx - k * N;
    float v = W[idx];
    __nv_bfloat16 h = __float2bfloat16(v);
    __nv_bfloat16 l = __float2bfloat16(v - __bfloat162float(h));
    size_t o = (size_t)n * (3 * K);
    out[o + k]         = h;
    out[o + K + k]     = l;
    out[o + 2 * K + k] = h;
}

// ---------------- A split: A (M x K fp32) -> out (M x 3K bf16) [h|h|l] ----------------
__global__ __launch_bounds__(256)
void splita_kernel(const float* __restrict__ A, __nv_bfloat16* __restrict__ out, int K) {
    int idx = blockIdx.x * 256 + threadIdx.x;    // over M*K/2 pairs
    int half = K >> 1;
    int row = idx / half, c2 = idx - row * half;
    int col = c2 * 2;
    float2 v = *(const float2*)(A + (size_t)row * K + col);
    __nv_bfloat16 h0 = __float2bfloat16(v.x), h1 = __float2bfloat16(v.y);
    __nv_bfloat16 l0 = __float2bfloat16(v.x - __bfloat162float(h0));
    __nv_bfloat16 l1 = __float2bfloat16(v.y - __bfloat162float(h1));
    __nv_bfloat162 hh; hh.x = h0; hh.y = h1;
    __nv_bfloat162 ll; ll.x = l0; ll.y = l1;
    size_t o = (size_t)row * (3 * K) + col;
    *(__nv_bfloat162*)&out[o]         = hh;
    *(__nv_bfloat162*)&out[o + K]     = hh;
    *(__nv_bfloat162*)&out[o + 2 * K] = ll;
}

// ---------------- column sums / mean mix (+fused split of x) ----------------
__global__ void colsum_kernel() {
    int t = threadIdx.x;
    int r0 = blockIdx.x * 256;
    float s = 0.f;
    for (int r = 0; r < 256; r++) s += g_x[(size_t)(r0 + r) * DH_ + t];
    atomicAdd(&g_mean[t], s);
}

__global__ __launch_bounds__(256)
void mix_split_kernel() {
    int idx = blockIdx.x * 256 + threadIdx.x;   // over NP*128 pairs
    int row = idx >> 7, c2 = idx & 127;
    int col = c2 * 2;
    float2 v = *(const float2*)(g_x + (size_t)row * DH_ + col);
    float m0 = g_mean[col]     * (1.f / (float)NP);
    float m1 = g_mean[col + 1] * (1.f / (float)NP);
    float x0 = (v.x + m0) * 0.5f;
    float x1 = (v.y + m1) * 0.5f;
    __nv_bfloat16 h0 = __float2bfloat16(x0), h1 = __float2bfloat16(x1);
    __nv_bfloat16 l0 = __float2bfloat16(x0 - __bfloat162float(h0));
    __nv_bfloat16 l1 = __float2bfloat16(x1 - __bfloat162float(h1));
    __nv_bfloat162 hh; hh.x = h0; hh.y = h1;
    __nv_bfloat162 ll; ll.x = l0; ll.y = l1;
    size_t o = (size_t)row * KSP + col;
    *(__nv_bfloat162*)&g_Xs[o]       = hh;
    *(__nv_bfloat162*)&g_Xs[o + 256] = hh;
    *(__nv_bfloat162*)&g_Xs[o + 512] = ll;
}

// ---------------- generic mma.sync linear: C = [ADD? Cin +] act(A' @ W'^T + b) ----------------
// A': M x Kp bf16 (K-major, [h|h|l]); W': N x Kp bf16 (K-major, [h|l|h]).
// BM=64, BN=128, BK=32, 3-stage cp.async. SPLIT: 0 none, 1 A-side out, 2 B-side out.
#define LSTAGE_B 15360                 // A 64x80 + B 128x80
#define LSMEM_DYN (3 * LSTAGE_B)

template<bool LEAKY, bool ADD, int SPLIT>
__global__ __launch_bounds__(256, 2)
void lin_mma(const __nv_bfloat16* __restrict__ A, const __nv_bfloat16* __restrict__ Bw,
             const float* __restrict__ bias, const float* __restrict__ Cin,
             float* __restrict__ C, __nv_bfloat16* __restrict__ S,
             int Kp, int N)
{
    extern __shared__ char smem[];
    const int tid = threadIdx.x;
    const int lane = tid & 31, wid = tid >> 5;
    const int wr = wid >> 2, wc = wid & 3;
    const int bx = blockIdx.x, by = blockIdx.y;
    uint32_t sb = smem_u32(smem);
    const int Kb = Kp * 2;
    const char* Abase = ((const char*)A)  + (size_t)(by * 64)  * Kb;
    const char* Bbase = ((const char*)Bw) + (size_t)(bx * 128) * Kb;
    const int nch = Kp / 32;

    auto load_chunk = [&](int c, int s) {
        uint32_t aSt = sb + s * LSTAGE_B;
        uint32_t bSt = aSt + 5120;
        int coff = c * 64;
        {
            int r = tid >> 2, cc = tid & 3;
            cp16(aSt + r * 80 + cc * 16, Abase + (size_t)r * Kb + coff + cc * 16);
        }
        #pragma unroll
        for (int j = 0; j < 2; j++) {
            int q = tid + j * 256;
            int r = q >> 2, cc = q & 3;
            cp16(bSt + r * 80 + cc * 16, Bbase + (size_t)r * Kb + coff + cc * 16);
        }
    };

    float d[2][4][4];
    #pragma unroll
    for (int mf = 0; mf < 2; mf++)
        #pragma unroll
        for (int nf = 0; nf < 4; nf++)
            #pragma unroll
            for (int q = 0; q < 4; q++) d[mf][nf][q] = 0.f;

    load_chunk(0, 0); CP_COMMIT();
    load_chunk(1, 1); CP_COMMIT();
    load_chunk(2, 2); CP_COMMIT();

    const int arow_j = ((lane >> 3) & 1) * 8 + (lane & 7);
    const int akb    = (lane >> 4) * 16;
    const int bj     = lane >> 3;
    const int bn_off = (bj >> 1) * 8 + (lane & 7);
    const int bkb    = (bj & 1) * 16;

    for (int c = 0; c < nch; c++) {
        CP_WAIT2();
        __syncthreads();
        int s = c % 3;
        uint32_t aSt = sb + s * LSTAGE_B;
        uint32_t bSt = aSt + 5120;

        #pragma unroll
        for (int ks = 0; ks < 2; ks++) {
            uint32_t a[2][4], b[4][2];
            #pragma unroll
            for (int mf = 0; mf < 2; mf++) {
                int row = wr * 32 + mf * 16 + arow_j;
                ldsm_x4(a[mf], aSt + row * 80 + akb + ks * 32);
            }
            {
                uint32_t bv[4];
                int row0 = wc * 32 + bn_off;
                ldsm_x4(bv, bSt + row0 * 80 + bkb + ks * 32);
                b[0][0] = bv[0]; b[0][1] = bv[1]; b[1][0] = bv[2]; b[1][1] = bv[3];
                int row1 = row0 + 16;
                ldsm_x4(bv, bSt + row1 * 80 + bkb + ks * 32);
                b[2][0] = bv[0]; b[2][1] = bv[1]; b[3][0] = bv[2]; b[3][1] = bv[3];
            }
            #pragma unroll
            for (int mf = 0; mf < 2; mf++)
                #pragma unroll
                for (int nf = 0; nf < 4; nf++)
                    mma_bf16(d[mf][nf], a[mf], b[nf]);
        }
        __syncthreads();
        if (c + 3 < nch) load_chunk(c + 3, (c + 3) % 3);
        CP_COMMIT();
    }

    // ---- epilogue ----
    const int g = lane >> 2, tq = lane & 3;
    auto emit = [&](int r, int c, float v0, float v1) {
        v0 += bias[c]; v1 += bias[c + 1];
        if (LEAKY) { v0 = leaky_f(v0); v1 = leaky_f(v1); }
        if (ADD)   { v0 += Cin[(size_t)r * N + c]; v1 += Cin[(size_t)r * N + c + 1]; }
        C[(size_t)r * N + c]     = v0;
        C[(size_t)r * N + c + 1] = v1;
        if (SPLIT) {
            __nv_bfloat16 h0 = __float2bfloat16(v0), h1 = __float2bfloat16(v1);
            __nv_bfloat16 l0 = __float2bfloat16(v0 - __bfloat162float(h0));
            __nv_bfloat16 l1 = __float2bfloat16(v1 - __bfloat162float(h1));
            __nv_bfloat162 hh; hh.x = h0; hh.y = h1;
            __nv_bfloat162 ll; ll.x = l0; ll.y = l1;
            size_t o = (size_t)r * KSP + c;
            *(__nv_bfloat162*)&S[o] = hh;
            if (SPLIT == 1) {
                *(__nv_bfloat162*)&S[o + 256] = hh;
                *(__nv_bfloat162*)&S[o + 512] = ll;
            } else {
                *(__nv_bfloat162*)&S[o + 256] = ll;
                *(__nv_bfloat162*)&S[o + 512] = hh;
            }
        }
    };
    #pragma unroll
    for (int mf = 0; mf < 2; mf++) {
        #pragma unroll
        for (int nf = 0; nf < 4; nf++) {
            int row = by * 64 + wr * 32 + mf * 16 + g;
            int col = bx * 128 + wc * 32 + nf * 8 + tq * 2;
            emit(row,     col, d[mf][nf][0], d[mf][nf][1]);
            emit(row + 8, col, d[mf][nf][2], d[mf][nf][3]);
        }
    }
}

// ---------------- mma.sync NT GEMM + fused per-block top-6 ----------------
#define STAGE_B 20480
#define SMEM_DYN (3 * STAGE_B)

__global__ __launch_bounds__(256, 2)
void gemm_nt_mma() {
    extern __shared__ char smem[];
    float (*sEpi)[129] = (float(*)[129])smem;
    const int tid = threadIdx.x;
    const int wid = tid >> 5, lane = tid & 31;
    const int wr = wid >> 2, wc = wid & 3;
    const int bx = blockIdx.x, by = blockIdx.y;

    uint32_t sb = smem_u32(smem);
    const char* Abase = ((const char*)g_Ahl) + (size_t)(by * 128) * (KSP * 2);
    const char* Bbase = ((const char*)g_Bhl) + (size_t)(bx * 128) * (KSP * 2);

    auto load_chunk = [&](int c, int s) {
        uint32_t aSt = sb + s * STAGE_B;
        uint32_t bSt = aSt + 10240;
        int coff = c * 64;
        #pragma unroll
        for (int j = 0; j < 2; j++) {
            int q = tid + j * 256;
            int r = q >> 2, cc = q & 3;
            cp16(aSt + r * 80 + cc * 16, Abase + (size_t)r * (KSP*2) + coff + cc * 16);
            cp16(bSt + r * 80 + cc * 16, Bbase + (size_t)r * (KSP*2) + coff + cc * 16);
        }
    };

    float d[4][4][4];
    #pragma unroll
    for (int mf = 0; mf < 4; mf++)
        #pragma unroll
        for (int nf = 0; nf < 4; nf++)
            #pragma unroll
            for (int q = 0; q < 4; q++) d[mf][nf][q] = 0.f;

    load_chunk(0, 0); CP_COMMIT();
    load_chunk(1, 1); CP_COMMIT();
    load_chunk(2, 2); CP_COMMIT();

    const int arow_j = ((lane >> 3) & 1) * 8 + (lane & 7);
    const int akb    = (lane >> 4) * 16;
    const int bj     = lane >> 3;
    const int bn_off = (bj >> 1) * 8 + (lane & 7);
    const int bkb    = (bj & 1) * 16;

    for (int c = 0; c < 24; c++) {
        CP_WAIT2();
        __syncthreads();
        int s = c % 3;
        uint32_t aSt = sb + s * STAGE_B;
        uint32_t bSt = aSt + 10240;

        #pragma unroll
        for (int ks = 0; ks < 2; ks++) {
            uint32_t a[4][4], b[4][2];
            #pragma unroll
            for (int mf = 0; mf < 4; mf++) {
                int row = wr * 64 + mf * 16 + arow_j;
                ldsm_x4(a[mf], aSt + row * 80 + akb + ks * 32);
            }
            {
                uint32_t bv[4];
                int row0 = wc * 32 + bn_off;
                ldsm_x4(bv, bSt + row0 * 80 + bkb + ks * 32);
                b[0][0] = bv[0]; b[0][1] = bv[1]; b[1][0] = bv[2]; b[1][1] = bv[3];
                int row1 = row0 + 16;
                ldsm_x4(bv, bSt + row1 * 80 + bkb + ks * 32);
                b[2][0] = bv[0]; b[2][1] = bv[1]; b[3][0] = bv[2]; b[3][1] = bv[3];
            }
            #pragma unroll
            for (int mf = 0; mf < 4; mf++)
                #pragma unroll
                for (int nf = 0; nf < 4; nf++)
                    mma_bf16(d[mf][nf], a[mf], b[nf]);
        }
        __syncthreads();
        if (c + 3 < 24) load_chunk(c + 3, (c + 3) % 3);
        CP_COMMIT();
    }

    const int g = lane >> 2, tq = lane & 3;
    #pragma unroll
    for (int ph = 0; ph < 2; ph++) {
        __syncthreads();
        if (wr == ph) {
            #pragma unroll
            for (int mf = 0; mf < 4; mf++) {
                int lr = mf * 16 + g;
                #pragma unroll
                for (int nf = 0; nf < 4; nf++) {
                    int col = wc * 32 + nf * 8 + tq * 2;
                    sEpi[lr][col]         = d[mf][nf][0];
                    sEpi[lr][col + 1]     = d[mf][nf][1];
                    sEpi[lr + 8][col]     = d[mf][nf][2];
                    sEpi[lr + 8][col + 1] = d[mf][nf][3];
                }
            }
        }
        __syncthreads();
        if (tid < 64) {
            float v[6]; int ix[6];
            #pragma unroll
            for (int k = 0; k < 6; k++) { v[k] = NEG_INF; ix[k] = 0; }
            int cb = bx * 128;
            for (int j = 0; j < 128; j++) {
                float val = sEpi[tid][j] * 0.0625f;
                if (val > v[5]) {
                    v[5] = val; ix[5] = cb + j;
                    #pragma unroll
                    for (int k = 5; k > 0; k--) {
                        if (v[k] > v[k - 1]) {
                            float tv = v[k]; v[k] = v[k - 1]; v[k - 1] = tv;
                            int   ti = ix[k]; ix[k] = ix[k - 1]; ix[k - 1] = ti;
                        }
                    }
                }
            }
            size_t row = (size_t)by * 128 + ph * 64 + tid;
            size_t o = row * CANDS + bx * 6;
            #pragma unroll
            for (int k = 0; k < 6; k++) { g_candv[o + k] = v[k]; g_candi[o + k] = ix[k]; }
        }
    }
}

// ---------------- top-k candidate reduce + message construction (+fused split out) ----------------
__global__ __launch_bounds__(128)
void topk_msg_kernel() {
    int i = blockIdx.x;
    int t = threadIdx.x;
    const float* cv = g_candv + (size_t)i * CANDS;
    const int*   ci = g_candi + (size_t)i * CANDS;

    float lv[6]; int li[6];
    #pragma unroll
    for (int k = 0; k < 6; k++) { lv[k] = NEG_INF; li[k] = 0; }
    for (int c = t; c < CANDS; c += 128) {
        float v = cv[c];
        if (v > lv[5]) {
            lv[5] = v; li[5] = ci[c];
            #pragma unroll
            for (int k = 5; k > 0; k--) {
                if (lv[k] > lv[k - 1]) {
                    float tv = lv[k]; lv[k] = lv[k - 1]; lv[k - 1] = tv;
                    int   tx = li[k]; li[k] = li[k - 1]; li[k - 1] = tx;
                }
            }
        }
    }

    __shared__ float sv[128]; __shared__ int si[128];
    __shared__ float topv[6]; __shared__ int topi[6];
    for (int r = 0; r < 6; r++) {
        sv[t] = lv[0]; si[t] = t;
        __syncthreads();
        #pragma unroll
        for (int o = 64; o > 0; o >>= 1) {
            if (t < o && sv[t + o] > sv[t]) { sv[t] = sv[t + o]; si[t] = si[t + o]; }
            __syncthreads();
        }
        if (t == si[0]) {
            topv[r] = lv[0]; topi[r] = li[0];
            #pragma unroll
            for (int k = 0; k < 5; k++) { lv[k] = lv[k + 1]; li[k] = li[k + 1]; }
            lv[5] = NEG_INF;
        }
        __syncthreads();
    }

    float tv[6]; int ti[6];
    #pragma unroll
    for (int k = 0; k < 6; k++) { tv[k] = topv[k]; ti[k] = topi[k]; }
    float pm = tv[0];
    #pragma unroll
    for (int k = 1; k < 6; k++) pm = fmaxf(pm, tv[k]);
    float pk[6], ps = 0.f;
    #pragma unroll
    for (int k = 0; k < 6; k++) { pk[k] = expf(tv[k] - pm); ps += pk[k]; }
    float pinv = 1.f / ps;
    #pragma unroll
    for (int k = 0; k < 6; k++) pk[k] *= pinv;

    float ehv[2]; float nb[6][2];
    #pragma unroll
    for (int u = 0; u < 2; u++) ehv[u] = g_eh[(size_t)i * DH_ + t + u * 128];
    #pragma unroll
    for (int k = 0; k < 6; k++)
        #pragma unroll
        for (int u = 0; u < 2; u++)
            nb[k][u] = g_et[(size_t)ti[k] * DH_ + t + u * 128];

    float sN[6], sG[6];
    #pragma unroll
    for (int k = 0; k < 6; k++) { sN[k] = 0.f; sG[k] = 0.f; }
    #pragma unroll
    for (int k = 0; k < 6; k++) {
        #pragma unroll
        for (int u = 0; u < 2; u++) {
            float ehr = pk[k] * nb[k][u] + (1.f - pk[k]) * ehv[u];
            float gt  = tanhf(ehv[u] + ehr);
            sN[k] += nb[k][u];
            sG[k] += gt;
        }
    }

    __shared__ float part[4][12];
    __shared__ float tot[12];
    int lane = t & 31, wp = t >> 5;
    #pragma unroll
    for (int q = 0; q < 6; q++) {
        float v = warp_sum(sN[q]); if (lane == 0) part[wp][q]     = v;
        float w = warp_sum(sG[q]); if (lane == 0) part[wp][6 + q] = w;
    }
    __syncthreads();
    if (t < 12) tot[t] = part[0][t] + part[1][t] + part[2][t] + part[3][t];
    __syncthreads();

    float kw[6], km = NEG_INF;
    #pragma unroll
    for (int k = 0; k < 6; k++) { kw[k] = tot[k] * tot[6 + k]; km = fmaxf(km, kw[k]); }
    float kp[6], ks = 0.f;
    #pragma unroll
    for (int k = 0; k < 6; k++) { kp[k] = expf(kw[k] - km); ks += kp[k]; }
    float kinv = 1.f / ks;

    #pragma unroll
    for (int u = 0; u < 2; u++) {
        float eN = 0.f;
        #pragma unroll
        for (int k = 0; k < 6; k++) eN += kp[k] * kinv * nb[k][u];
        int dcol = t + u * 128;
        float e = ehv[u];
        float av = e + eN;
        float mv = e * eN;
        __nv_bfloat16 ah = __float2bfloat16(av);
        __nv_bfloat16 al = __float2bfloat16(av - __bfloat162float(ah));
        __nv_bfloat16 mh = __float2bfloat16(mv);
        __nv_bfloat16 ml = __float2bfloat16(mv - __bfloat162float(mh));
        size_t o = (size_t)i * KSP + dcol;
        g_As[o] = ah; g_As[o + 256] = ah; g_As[o + 512] = al;
        g_Ms[o] = mh; g_Ms[o + 256] = mh; g_Ms[o + 512] = ml;
    }
}

// ---------------- readout ----------------
__global__ __launch_bounds__(128)
void score_kernel(const float* __restrict__ Ag2, const float* __restrict__ bg2) {
    int i = blockIdx.x, t = threadIdx.x;
    float v = g_h[(size_t)i * 128 + t] * Ag2[t];
    v = warp_sum(v);
    __shared__ float p[4];
    if ((t & 31) == 0) p[t >> 5] = v;
    __syncthreads();
    if (t == 0) g_s[i] = p[0] + p[1] + p[2] + p[3] + bg2[0];
}

__global__ __launch_bounds__(1024)
void stat_kernel() {
    int t = threadIdx.x;
    __shared__ float sm[1024];
    float m = NEG_INF;
    for (int i = t; i < NP; i += 1024) m = fmaxf(m, g_s[i]);
    sm[t] = m; __syncthreads();
    for (int o = 512; o > 0; o >>= 1) { if (t < o) sm[t] = fmaxf(sm[t], sm[t + o]); __syncthreads(); }
    float mx = sm[0];
    __syncthreads();
    float e = 0.f;
    for (int i = t; i < NP; i += 1024) e += expf(g_s[i] - mx);
    sm[t] = e; __syncthreads();
    for (int o = 512; o > 0; o >>= 1) { if (t < o) sm[t] += sm[t + o]; __syncthreads(); }
    if (t == 0) { g_stat[0] = mx; g_stat[1] = sm[0]; }
}

__global__ __launch_bounds__(256)
void accum_kernel(const float* __restrict__ emsg, float* __restrict__ eg) {
    int t = threadIdx.x;
    int r0 = blockIdx.x * 256;
    __shared__ float w[256];
    float mx = g_stat[0], inv = 1.f / g_stat[1];
    w[t] = expf(g_s[r0 + t] - mx) * inv;
    __syncthreads();
    float acc = 0.f;
    for (int r = 0; r < 256; r++) acc += w[r] * emsg[(size_t)(r0 + r) * DH_ + t];
    atomicAdd(&eg[t], acc);
}

// ---------------- launcher ----------------
extern "C" void kernel_launch(void* const* d_in, const int* in_sizes, int n_in,
                              void* d_out, int out_size) {
    const float* x_path = (const float*)d_in[0];
    const float* fc1_W  = (const float*)d_in[1];
    const float* fc1_b  = (const float*)d_in[2];
    const float* Wh     = (const float*)d_in[3];
    const float* bh     = (const float*)d_in[4];
    const float* Wt     = (const float*)d_in[5];
    const float* bt     = (const float*)d_in[6];
    const float* W1     = (const float*)d_in[7];
    const float* b1     = (const float*)d_in[8];
    const float* W2     = (const float*)d_in[9];
    const float* b2     = (const float*)d_in[10];
    const float* Ag1    = (const float*)d_in[11];
    const float* bg1    = (const float*)d_in[12];
    const float* Ag2    = (const float*)d_in[13];
    const float* bg2    = (const float*)d_in[14];

    float* out    = (float*)d_out;               // e_msg: 8192 x 256
    float* out_eg = out + (size_t)NP * DH_;      // e_g: 256

    void *px, *peh, *pet, *ph;
    void *pPs, *pXs, *pAhl, *pBhl, *pAs, *pMs, *pEs;
    void *pWfc1, *pWhs, *pWts, *pW1s, *pW2s, *pAg1s;
    cudaGetSymbolAddress(&px,  g_x);
    cudaGetSymbolAddress(&peh, g_eh);
    cudaGetSymbolAddress(&pet, g_et);
    cudaGetSymbolAddress(&ph,  g_h);
    cudaGetSymbolAddress(&pPs,  g_Ps);
    cudaGetSymbolAddress(&pXs,  g_Xs);
    cudaGetSymbolAddress(&pAhl, g_Ahl);
    cudaGetSymbolAddress(&pBhl, g_Bhl);
    cudaGetSymbolAddress(&pAs,  g_As);
    cudaGetSymbolAddress(&pMs,  g_Ms);
    cudaGetSymbolAddress(&pEs,  g_Es);
    cudaGetSymbolAddress(&pWfc1, g_Wfc1s);
    cudaGetSymbolAddress(&pWhs, g_Whs);
    cudaGetSymbolAddress(&pWts, g_Wts);
    cudaGetSymbolAddress(&pW1s, g_W1s);
    cudaGetSymbolAddress(&pW2s, g_W2s);
    cudaGetSymbolAddress(&pAg1s, g_Ag1s);

    cudaFuncSetAttribute(gemm_nt_mma, cudaFuncAttributeMaxDynamicSharedMemorySize, SMEM_DYN);
    cudaFuncSetAttribute(lin_mma<true, false, 0>, cudaFuncAttributeMaxDynamicSharedMemorySize, LSMEM_DYN);
    cudaFuncSetAttribute(lin_mma<false, false, 1>, cudaFuncAttributeMaxDynamicSharedMemorySize, LSMEM_DYN);
    cudaFuncSetAttribute(lin_mma<false, false, 2>, cudaFuncAttributeMaxDynamicSharedMemorySize, LSMEM_DYN);
    cudaFuncSetAttribute(lin_mma<true, true, 1>, cudaFuncAttributeMaxDynamicSharedMemorySize, LSMEM_DYN);

    zero_kernel<<<1, 256>>>(out_eg);

    // weight splits (tiny)
    splitw_kernel<<<(DIN_*DH_ + 255)/256, 256>>>(fc1_W, (__nv_bfloat16*)pWfc1, DIN_, DH_);
    splitw_kernel<<<(DH_*DH_ + 255)/256, 256>>>(Wh, (__nv_bfloat16*)pWhs, DH_, DH_);
    splitw_kernel<<<(DH_*DH_ + 255)/256, 256>>>(Wt, (__nv_bfloat16*)pWts, DH_, DH_);
    splitw_kernel<<<(DH_*DH_ + 255)/256, 256>>>(W1, (__nv_bfloat16*)pW1s, DH_, DH_);
    splitw_kernel<<<(DH_*DH_ + 255)/256, 256>>>(W2, (__nv_bfloat16*)pW2s, DH_, DH_);
    splitw_kernel<<<(DH_*(DH_/2) + 255)/256, 256>>>(Ag1, (__nv_bfloat16*)pAg1s, DH_, DH_/2);

    // x_path split
    splita_kernel<<<NP * (DIN_/2) / 256, 256>>>(x_path, (__nv_bfloat16*)pPs, DIN_);

    // fc1 + leaky -> g_x    (grid.y = 8192/64 = 128)
    lin_mma<true, false, 0><<<dim3(2, 128), 256, LSMEM_DYN>>>(
        (const __nv_bfloat16*)pPs, (const __nv_bfloat16*)pWfc1, fc1_b, nullptr,
        (float*)px, nullptr, KSP_FC, DH_);

    // mean-mix (+split of x)
    colsum_kernel<<<32, 256>>>();
    mix_split_kernel<<<NP * 128 / 256, 256>>>();

    // e_h (fp32 + A-side split), e_t (fp32 + B-side split)
    lin_mma<false, false, 1><<<dim3(2, 128), 256, LSMEM_DYN>>>(
        (const __nv_bfloat16*)pXs, (const __nv_bfloat16*)pWhs, bh, nullptr,
        (float*)peh, (__nv_bfloat16*)pAhl, KSP, DH_);
    lin_mma<false, false, 2><<<dim3(2, 128), 256, LSMEM_DYN>>>(
        (const __nv_bfloat16*)pXs, (const __nv_bfloat16*)pWts, bt, nullptr,
        (float*)pet, (__nv_bfloat16*)pBhl, KSP, DH_);

    // tensor-core attention logits + fused per-block top-6
    gemm_nt_mma<<<dim3(64, 64), 256, SMEM_DYN>>>();

    // candidate reduce + message construction (emits a/m splits)
    topk_msg_kernel<<<NP, 128>>>();

    // e_msg = leaky(a@W1+b1) + leaky(m@W2+b2) -> out (+split for Ag1)
    lin_mma<true, false, 0><<<dim3(2, 128), 256, LSMEM_DYN>>>(
        (const __nv_bfloat16*)pAs, (const __nv_bfloat16*)pW1s, b1, nullptr,
        out, nullptr, KSP, DH_);
    lin_mma<true, true, 1><<<dim3(2, 128), 256, LSMEM_DYN>>>(
        (const __nv_bfloat16*)pMs, (const __nv_bfloat16*)pW2s, b2, out,
        out, (__nv_bfloat16*)pEs, KSP, DH_);

    // readout: g_h = leaky(e_msg @ Ag1 + bg1)
    lin_mma<true, false, 0><<<dim3(1, 128), 256, LSMEM_DYN>>>(
        (const __nv_bfloat16*)pEs, (const __nv_bfloat16*)pAg1s, bg1, nullptr,
        (float*)ph, nullptr, KSP, DH_/2);

    score_kernel<<<NP, 128>>>(Ag2, bg2);
    stat_kernel<<<1, 1024>>>();
    accum_kernel<<<32, 256>>>(out, out_eg);
}

// round 6
// speedup vs baseline: 1.5560x; 1.0344x over previous
#include <cuda_runtime.h>
#include <cuda_bf16.h>
#include <math.h>
#include <stdint.h>

#define NP   8192
#define DIN_ 1024
#define DH_  256
#define KSP  768                 // 3*DH split width
#define KSP_FC 3072              // 3*DIN split width
#define CANDS 384
#define NEG_INF (-3.402823466e38f)

// ---------------- scratch (allocation-free: __device__ globals) ----------------
__device__ float g_x [NP*DH_];
__device__ float g_eh[NP*DH_];
__device__ float g_et[NP*DH_];
__device__ __nv_bfloat16 g_Ps [(size_t)NP*KSP_FC];  // x_path split
__device__ __nv_bfloat16 g_Xs [(size_t)NP*KSP];     // mixed x split (A-side)
__device__ __nv_bfloat16 g_Ahl[(size_t)NP*KSP];     // e_h split (A-side)
__device__ __nv_bfloat16 g_Bhl[(size_t)NP*KSP];     // e_t split (B-side)
__device__ __nv_bfloat16 g_As [(size_t)NP*KSP];     // a split
__device__ __nv_bfloat16 g_Ms [(size_t)NP*KSP];     // m split
__device__ __nv_bfloat16 g_Es [(size_t)NP*KSP];     // e_msg split
__device__ __nv_bfloat16 g_Wfc1s[(size_t)DH_*KSP_FC];
__device__ __nv_bfloat16 g_Wcat [512*KSP];          // [Wh;Wt] split
__device__ __nv_bfloat16 g_W1s [DH_*KSP];
__device__ __nv_bfloat16 g_W2s [DH_*KSP];
__device__ __nv_bfloat16 g_Ag1s[(DH_/2)*KSP];
__device__ float g_bcat[512];
__device__ float g_candv[(size_t)NP*CANDS];
__device__ int   g_candi[(size_t)NP*CANDS];
__device__ float g_h [NP*(DH_/2)];
__device__ float g_mean[DH_];
__device__ float g_s[NP];
__device__ float g_stat[2];

__device__ __forceinline__ float leaky_f(float v) { return v > 0.f ? v : 0.01f * v; }

__device__ __forceinline__ float warp_sum(float v) {
    #pragma unroll
    for (int o = 16; o > 0; o >>= 1) v += __shfl_down_sync(0xffffffffu, v, o);
    return v;
}

// ---------------- PTX helpers ----------------
__device__ __forceinline__ uint32_t smem_u32(const void* p) {
    uint32_t a;
    asm("{ .reg .u64 t; cvta.to.shared.u64 t, %1; cvt.u32.u64 %0, t; }" : "=r"(a) : "l"(p));
    return a;
}
__device__ __forceinline__ void cp16(uint32_t dst, const void* src) {
    asm volatile("cp.async.cg.shared.global [%0], [%1], 16;" :: "r"(dst), "l"(src));
}
#define CP_COMMIT()  asm volatile("cp.async.commit_group;" ::: "memory")
#define CP_WAIT2()   asm volatile("cp.async.wait_group 2;" ::: "memory")

__device__ __forceinline__ void ldsm_x4(uint32_t (&r)[4], uint32_t addr) {
    asm volatile("ldmatrix.sync.aligned.m8n8.x4.shared.b16 {%0,%1,%2,%3}, [%4];"
                 : "=r"(r[0]), "=r"(r[1]), "=r"(r[2]), "=r"(r[3]) : "r"(addr));
}
__device__ __forceinline__ void mma_bf16(float (&d)[4], const uint32_t (&a)[4],
                                         const uint32_t* b) {
    asm volatile("mma.sync.aligned.m16n8k16.row.col.f32.bf16.bf16.f32 "
                 "{%0,%1,%2,%3}, {%4,%5,%6,%7}, {%8,%9}, {%0,%1,%2,%3};"
                 : "+f"(d[0]), "+f"(d[1]), "+f"(d[2]), "+f"(d[3])
                 : "r"(a[0]), "r"(a[1]), "r"(a[2]), "r"(a[3]), "r"(b[0]), "r"(b[1]));
}

__device__ __forceinline__ void split_pair(float v0, float v1,
                                           __nv_bfloat162& hh, __nv_bfloat162& ll) {
    __nv_bfloat16 h0 = __float2bfloat16(v0), h1 = __float2bfloat16(v1);
    hh.x = h0; hh.y = h1;
    ll.x = __float2bfloat16(v0 - __bfloat162float(h0));
    ll.y = __float2bfloat16(v1 - __bfloat162float(h1));
}

// ---------------- merged prep: weight splits + bcat + zeroing ----------------
__device__ __forceinline__ void splitw_body(const float* __restrict__ W,
                                            __nv_bfloat16* __restrict__ out,
                                            int K, int N, int baseRow, int idx) {
    int k = idx / N, n = idx - k * N;
    float v = W[idx];
    __nv_bfloat16 h = __float2bfloat16(v);
    __nv_bfloat16 l = __float2bfloat16(v - __bfloat162float(h));
    size_t o = (size_t)(n + baseRow) * (3 * K);
    out[o + k]         = h;
    out[o + K + k]     = l;
    out[o + 2 * K + k] = h;
}

__global__ void prep_kernel(const float* __restrict__ fc1W,
                            const float* __restrict__ Wh, const float* __restrict__ Wt,
                            const float* __restrict__ W1, const float* __restrict__ W2,
                            const float* __restrict__ Ag1,
                            const float* __restrict__ bh, const float* __restrict__ bt,
                            float* __restrict__ eg) {
    int b = blockIdx.x, t = threadIdx.x;
    if (b < 1024)       splitw_body(fc1W, g_Wfc1s, DIN_, DH_, 0,   b * 256 + t);
    else if (b < 1280)  splitw_body(Wh,   g_Wcat,  DH_, DH_, 0,   (b - 1024) * 256 + t);
    else if (b < 1536)  splitw_body(Wt,   g_Wcat,  DH_, DH_, 256, (b - 1280) * 256 + t);
    else if (b < 1792)  splitw_body(W1,   g_W1s,   DH_, DH_, 0,   (b - 1536) * 256 + t);
    else if (b < 2048)  splitw_body(W2,   g_W2s,   DH_, DH_, 0,   (b - 1792) * 256 + t);
    else if (b < 2176)  splitw_body(Ag1,  g_Ag1s,  DH_, DH_/2, 0, (b - 2048) * 256 + t);
    else {
        g_mean[t] = 0.f;
        eg[t] = 0.f;
        g_bcat[t] = bh[t];
        g_bcat[256 + t] = bt[t];
    }
}

// ---------------- A split: x_path (M x 1024 fp32) -> (M x 3072 bf16) [h|h|l] ----------------
__global__ __launch_bounds__(256)
void splita_kernel(const float* __restrict__ A, __nv_bfloat16* __restrict__ out, int K) {
    int idx = blockIdx.x * 256 + threadIdx.x;
    int half = K >> 1;
    int row = idx / half, c2 = idx - row * half;
    int col = c2 * 2;
    float2 v = *(const float2*)(A + (size_t)row * K + col);
    __nv_bfloat162 hh, ll;
    split_pair(v.x, v.y, hh, ll);
    size_t o = (size_t)row * (3 * K) + col;
    *(__nv_bfloat162*)&out[o]         = hh;
    *(__nv_bfloat162*)&out[o + K]     = hh;
    *(__nv_bfloat162*)&out[o + 2 * K] = ll;
}

// ---------------- mean mix (+fused split of x) ----------------
__global__ __launch_bounds__(256)
void mix_split_kernel() {
    int idx = blockIdx.x * 256 + threadIdx.x;
    int row = idx >> 7, c2 = idx & 127;
    int col = c2 * 2;
    float2 v = *(const float2*)(g_x + (size_t)row * DH_ + col);
    float x0 = (v.x + g_mean[col]     * (1.f / (float)NP)) * 0.5f;
    float x1 = (v.y + g_mean[col + 1] * (1.f / (float)NP)) * 0.5f;
    __nv_bfloat162 hh, ll;
    split_pair(x0, x1, hh, ll);
    size_t o = (size_t)row * KSP + col;
    *(__nv_bfloat162*)&g_Xs[o]       = hh;
    *(__nv_bfloat162*)&g_Xs[o + 256] = hh;
    *(__nv_bfloat162*)&g_Xs[o + 512] = ll;
}

// ---------------- generic mma.sync linear ----------------
// SPLIT: 0 none, 1 A-side out, 2 B-side out, 3 ehet routing (cols<256 -> e_h/Ahl, else e_t/Bhl).
// COLSUM: accumulate column sums of output into g_mean (fc1 path).
#define LSTAGE_B 15360                 // A 64x80 + B 128x80
#define LSMEM_DYN (3 * LSTAGE_B + 512)

template<bool LEAKY, bool ADD, int SPLIT, bool COLSUM>
__global__ __launch_bounds__(256, 2)
void lin_mma(const __nv_bfloat16* __restrict__ A, const __nv_bfloat16* __restrict__ Bw,
             const float* __restrict__ bias, const float* __restrict__ Cin,
             float* __restrict__ C, __nv_bfloat16* __restrict__ S,
             int Kp, int N)
{
    extern __shared__ char smem[];
    const int tid = threadIdx.x;
    const int lane = tid & 31, wid = tid >> 5;
    const int wr = wid >> 2, wc = wid & 3;
    const int bx = blockIdx.x, by = blockIdx.y;
    uint32_t sb = smem_u32(smem);
    float* colacc = (float*)(smem + 3 * LSTAGE_B);
    if (COLSUM && tid < 128) colacc[tid] = 0.f;
    const int Kb = Kp * 2;
    const char* Abase = ((const char*)A)  + (size_t)(by * 64)  * Kb;
    const char* Bbase = ((const char*)Bw) + (size_t)(bx * 128) * Kb;
    const int nch = Kp / 32;

    auto load_chunk = [&](int c, int s) {
        uint32_t aSt = sb + s * LSTAGE_B;
        uint32_t bSt = aSt + 5120;
        int coff = c * 64;
        {
            int r = tid >> 2, cc = tid & 3;
            cp16(aSt + r * 80 + cc * 16, Abase + (size_t)r * Kb + coff + cc * 16);
        }
        #pragma unroll
        for (int j = 0; j < 2; j++) {
            int q = tid + j * 256;
            int r = q >> 2, cc = q & 3;
            cp16(bSt + r * 80 + cc * 16, Bbase + (size_t)r * Kb + coff + cc * 16);
        }
    };

    float d[2][4][4];
    #pragma unroll
    for (int mf = 0; mf < 2; mf++)
        #pragma unroll
        for (int nf = 0; nf < 4; nf++)
            #pragma unroll
            for (int q = 0; q < 4; q++) d[mf][nf][q] = 0.f;

    load_chunk(0, 0); CP_COMMIT();
    load_chunk(1, 1); CP_COMMIT();
    load_chunk(2, 2); CP_COMMIT();

    const int arow_j = ((lane >> 3) & 1) * 8 + (lane & 7);
    const int akb    = (lane >> 4) * 16;
    const int bj     = lane >> 3;
    const int bn_off = (bj >> 1) * 8 + (lane & 7);
    const int bkb    = (bj & 1) * 16;

    for (int c = 0; c < nch; c++) {
        CP_WAIT2();
        __syncthreads();
        uint32_t aSt = sb + (c % 3) * LSTAGE_B;
        uint32_t bSt = aSt + 5120;

        #pragma unroll
        for (int ks = 0; ks < 2; ks++) {
            uint32_t a[2][4], b[4][2];
            #pragma unroll
            for (int mf = 0; mf < 2; mf++) {
                int row = wr * 32 + mf * 16 + arow_j;
                ldsm_x4(a[mf], aSt + row * 80 + akb + ks * 32);
            }
            {
                uint32_t bv[4];
                int row0 = wc * 32 + bn_off;
                ldsm_x4(bv, bSt + row0 * 80 + bkb + ks * 32);
                b[0][0] = bv[0]; b[0][1] = bv[1]; b[1][0] = bv[2]; b[1][1] = bv[3];
                int row1 = row0 + 16;
                ldsm_x4(bv, bSt + row1 * 80 + bkb + ks * 32);
                b[2][0] = bv[0]; b[2][1] = bv[1]; b[3][0] = bv[2]; b[3][1] = bv[3];
            }
            #pragma unroll
            for (int mf = 0; mf < 2; mf++)
                #pragma unroll
                for (int nf = 0; nf < 4; nf++)
                    mma_bf16(d[mf][nf], a[mf], b[nf]);
        }
        __syncthreads();
        if (c + 3 < nch) load_chunk(c + 3, (c + 3) % 3);
        CP_COMMIT();
    }

    // ---- epilogue ----
    const int g = lane >> 2, tq = lane & 3;
    auto emit = [&](int r, int c, float v0, float v1) {
        v0 += bias[c]; v1 += bias[c + 1];
        if (SPLIT == 3) {
            __nv_bfloat162 hh, ll;
            split_pair(v0, v1, hh, ll);
            if (c < 256) {
                g_eh[(size_t)r * DH_ + c]     = v0;
                g_eh[(size_t)r * DH_ + c + 1] = v1;
                size_t o = (size_t)r * KSP + c;
                *(__nv_bfloat162*)&g_Ahl[o]       = hh;
                *(__nv_bfloat162*)&g_Ahl[o + 256] = hh;
                *(__nv_bfloat162*)&g_Ahl[o + 512] = ll;
            } else {
                int c2 = c - 256;
                g_et[(size_t)r * DH_ + c2]     = v0;
                g_et[(size_t)r * DH_ + c2 + 1] = v1;
                size_t o = (size_t)r * KSP + c2;
                *(__nv_bfloat162*)&g_Bhl[o]       = hh;
                *(__nv_bfloat162*)&g_Bhl[o + 256] = ll;
                *(__nv_bfloat162*)&g_Bhl[o + 512] = hh;
            }
            return;
        }
        if (LEAKY) { v0 = leaky_f(v0); v1 = leaky_f(v1); }
        if (ADD)   { v0 += Cin[(size_t)r * N + c]; v1 += Cin[(size_t)r * N + c + 1]; }
        C[(size_t)r * N + c]     = v0;
        C[(size_t)r * N + c + 1] = v1;
        if (COLSUM) {
            int cl = c - bx * 128;
            atomicAdd(&colacc[cl], v0);
            atomicAdd(&colacc[cl + 1], v1);
        }
        if (SPLIT == 1 || SPLIT == 2) {
            __nv_bfloat162 hh, ll;
            split_pair(v0, v1, hh, ll);
            size_t o = (size_t)r * KSP + c;
            *(__nv_bfloat162*)&S[o] = hh;
            if (SPLIT == 1) {
                *(__nv_bfloat162*)&S[o + 256] = hh;
                *(__nv_bfloat162*)&S[o + 512] = ll;
            } else {
                *(__nv_bfloat162*)&S[o + 256] = ll;
                *(__nv_bfloat162*)&S[o + 512] = hh;
            }
        }
    };
    #pragma unroll
    for (int mf = 0; mf < 2; mf++) {
        #pragma unroll
        for (int nf = 0; nf < 4; nf++) {
            int row = by * 64 + wr * 32 + mf * 16 + g;
            int col = bx * 128 + wc * 32 + nf * 8 + tq * 2;
            emit(row,     col, d[mf][nf][0], d[mf][nf][1]);
            emit(row + 8, col, d[mf][nf][2], d[mf][nf][3]);
        }
    }
    if (COLSUM) {
        __syncthreads();
        if (tid < 128) atomicAdd(&g_mean[bx * 128 + tid], colacc[tid]);
    }
}

// ---------------- NT GEMM v2: 128x256 tile, warp 64x64, occ 1, fused top-6 ----------------
#define STAGE2_B 30720                 // A 128x80 + B 256x80
#define SMEM_NT  132608                // max(3*STAGE2_B, 128*259*4)

__global__ __launch_bounds__(256, 1)
void gemm_nt_mma() {
    extern __shared__ char smem[];
    const int tid = threadIdx.x;
    const int wid = tid >> 5, lane = tid & 31;
    const int wr = wid >> 2, wc = wid & 3;     // 2 x 4 warps, 64x64 each
    const int bx = blockIdx.x, by = blockIdx.y;
    uint32_t sb = smem_u32(smem);
    const char* Abase = ((const char*)g_Ahl) + (size_t)(by * 128) * (KSP * 2);
    const char* Bbase = ((const char*)g_Bhl) + (size_t)(bx * 256) * (KSP * 2);

    auto load_chunk = [&](int c, int s) {
        uint32_t aSt = sb + s * STAGE2_B;
        uint32_t bSt = aSt + 10240;
        int coff = c * 64;
        #pragma unroll
        for (int j = 0; j < 2; j++) {
            int q = tid + j * 256;
            int r = q >> 2, cc = q & 3;
            cp16(aSt + r * 80 + cc * 16, Abase + (size_t)r * (KSP*2) + coff + cc * 16);
        }
        #pragma unroll
        for (int j = 0; j < 4; j++) {
            int q = tid + j * 256;
            int r = q >> 2, cc = q & 3;
            cp16(bSt + r * 80 + cc * 16, Bbase + (size_t)r * (KSP*2) + coff + cc * 16);
        }
    };

    float d[4][8][4];
    #pragma unroll
    for (int mf = 0; mf < 4; mf++)
        #pragma unroll
        for (int nf = 0; nf < 8; nf++)
            #pragma unroll
            for (int q = 0; q < 4; q++) d[mf][nf][q] = 0.f;

    load_chunk(0, 0); CP_COMMIT();
    load_chunk(1, 1); CP_COMMIT();
    load_chunk(2, 2); CP_COMMIT();

    const int arow_j = ((lane >> 3) & 1) * 8 + (lane & 7);
    const int akb    = (lane >> 4) * 16;
    const int bj     = lane >> 3;
    const int bn_off = (bj >> 1) * 8 + (lane & 7);
    const int bkb    = (bj & 1) * 16;

    for (int c = 0; c < 24; c++) {
        CP_WAIT2();
        __syncthreads();
        uint32_t aSt = sb + (c % 3) * STAGE2_B;
        uint32_t bSt = aSt + 10240;

        #pragma unroll
        for (int ks = 0; ks < 2; ks++) {
            uint32_t a[4][4], b[8][2];
            #pragma unroll
            for (int mf = 0; mf < 4; mf++) {
                int row = wr * 64 + mf * 16 + arow_j;
                ldsm_x4(a[mf], aSt + row * 80 + akb + ks * 32);
            }
            #pragma unroll
            for (int nb = 0; nb < 4; nb++) {
                uint32_t bv[4];
                int row = wc * 64 + nb * 16 + bn_off;
                ldsm_x4(bv, bSt + row * 80 + bkb + ks * 32);
                b[nb*2][0]   = bv[0]; b[nb*2][1]   = bv[1];
                b[nb*2+1][0] = bv[2]; b[nb*2+1][1] = bv[3];
            }
            #pragma unroll
            for (int mf = 0; mf < 4; mf++)
                #pragma unroll
                for (int nf = 0; nf < 8; nf++)
                    mma_bf16(d[mf][nf], a[mf], b[nf]);
        }
        __syncthreads();
        if (c + 3 < 24) load_chunk(c + 3, (c + 3) % 3);
        CP_COMMIT();
    }

    // ---- epilogue: all accums -> smem [128][259], then per-row top-6 ----
    float* sE = (float*)smem;
    __syncthreads();
    const int g = lane >> 2, tq = lane & 3;
    #pragma unroll
    for (int mf = 0; mf < 4; mf++) {
        int r0 = wr * 64 + mf * 16 + g;
        #pragma unroll
        for (int nf = 0; nf < 8; nf++) {
            int cc = wc * 64 + nf * 8 + tq * 2;
            sE[r0 * 259 + cc]           = d[mf][nf][0];
            sE[r0 * 259 + cc + 1]       = d[mf][nf][1];
            sE[(r0 + 8) * 259 + cc]     = d[mf][nf][2];
            sE[(r0 + 8) * 259 + cc + 1] = d[mf][nf][3];
        }
    }
    __syncthreads();
    {
        int row = tid & 127, ch = tid >> 7;
        float v[6]; int ix[6];
        #pragma unroll
        for (int k = 0; k < 6; k++) { v[k] = NEG_INF; ix[k] = 0; }
        int cb = bx * 256 + ch * 128;
        const float* rp = sE + row * 259 + ch * 128;
        for (int j = 0; j < 128; j++) {
            float val = rp[j] * 0.0625f;
            if (val > v[5]) {
                v[5] = val; ix[5] = cb + j;
                #pragma unroll
                for (int k = 5; k > 0; k--) {
                    if (v[k] > v[k - 1]) {
                        float tv = v[k]; v[k] = v[k - 1]; v[k - 1] = tv;
                        int   ti = ix[k]; ix[k] = ix[k - 1]; ix[k - 1] = ti;
                    }
                }
            }
        }
        size_t rg = (size_t)by * 128 + row;
        size_t o = rg * CANDS + bx * 12 + ch * 6;
        #pragma unroll
        for (int k = 0; k < 6; k++) { g_candv[o + k] = v[k]; g_candi[o + k] = ix[k]; }
    }
}

// ---------------- top-k candidate reduce + message construction (+fused split out) ----------------
__global__ __launch_bounds__(128)
void topk_msg_kernel() {
    int i = blockIdx.x;
    int t = threadIdx.x;
    const float* cv = g_candv + (size_t)i * CANDS;
    const int*   ci = g_candi + (size_t)i * CANDS;

    float lv[6]; int li[6];
    #pragma unroll
    for (int k = 0; k < 6; k++) { lv[k] = NEG_INF; li[k] = 0; }
    for (int c = t; c < CANDS; c += 128) {
        float v = cv[c];
        if (v > lv[5]) {
            lv[5] = v; li[5] = ci[c];
            #pragma unroll
            for (int k = 5; k > 0; k--) {
                if (lv[k] > lv[k - 1]) {
                    float tv = lv[k]; lv[k] = lv[k - 1]; lv[k - 1] = tv;
                    int   tx = li[k]; li[k] = li[k - 1]; li[k - 1] = tx;
                }
            }
        }
    }

    __shared__ float sv[128]; __shared__ int si[128];
    __shared__ float topv[6]; __shared__ int topi[6];
    for (int r = 0; r < 6; r++) {
        sv[t] = lv[0]; si[t] = t;
        __syncthreads();
        #pragma unroll
        for (int o = 64; o > 0; o >>= 1) {
            if (t < o && sv[t + o] > sv[t]) { sv[t] = sv[t + o]; si[t] = si[t + o]; }
            __syncthreads();
        }
        if (t == si[0]) {
            topv[r] = lv[0]; topi[r] = li[0];
            #pragma unroll
            for (int k = 0; k < 5; k++) { lv[k] = lv[k + 1]; li[k] = li[k + 1]; }
            lv[5] = NEG_INF;
        }
        __syncthreads();
    }

    float tv[6]; int ti[6];
    #pragma unroll
    for (int k = 0; k < 6; k++) { tv[k] = topv[k]; ti[k] = topi[k]; }
    float pm = tv[0];
    #pragma unroll
    for (int k = 1; k < 6; k++) pm = fmaxf(pm, tv[k]);
    float pk[6], ps = 0.f;
    #pragma unroll
    for (int k = 0; k < 6; k++) { pk[k] = expf(tv[k] - pm); ps += pk[k]; }
    float pinv = 1.f / ps;
    #pragma unroll
    for (int k = 0; k < 6; k++) pk[k] *= pinv;

    float ehv[2]; float nb[6][2];
    #pragma unroll
    for (int u = 0; u < 2; u++) ehv[u] = g_eh[(size_t)i * DH_ + t + u * 128];
    #pragma unroll
    for (int k = 0; k < 6; k++)
        #pragma unroll
        for (int u = 0; u < 2; u++)
            nb[k][u] = g_et[(size_t)ti[k] * DH_ + t + u * 128];

    float sN[6], sG[6];
    #pragma unroll
    for (int k = 0; k < 6; k++) { sN[k] = 0.f; sG[k] = 0.f; }
    #pragma unroll
    for (int k = 0; k < 6; k++) {
        #pragma unroll
        for (int u = 0; u < 2; u++) {
            float ehr = pk[k] * nb[k][u] + (1.f - pk[k]) * ehv[u];
            float gt  = tanhf(ehv[u] + ehr);
            sN[k] += nb[k][u];
            sG[k] += gt;
        }
    }

    __shared__ float part[4][12];
    __shared__ float tot[12];
    int lane = t & 31, wp = t >> 5;
    #pragma unroll
    for (int q = 0; q < 6; q++) {
        float v = warp_sum(sN[q]); if (lane == 0) part[wp][q]     = v;
        float w = warp_sum(sG[q]); if (lane == 0) part[wp][6 + q] = w;
    }
    __syncthreads();
    if (t < 12) tot[t] = part[0][t] + part[1][t] + part[2][t] + part[3][t];
    __syncthreads();

    float kw[6], km = NEG_INF;
    #pragma unroll
    for (int k = 0; k < 6; k++) { kw[k] = tot[k] * tot[6 + k]; km = fmaxf(km, kw[k]); }
    float kp[6], ks = 0.f;
    #pragma unroll
    for (int k = 0; k < 6; k++) { kp[k] = expf(kw[k] - km); ks += kp[k]; }
    float kinv = 1.f / ks;

    #pragma unroll
    for (int u = 0; u < 2; u++) {
        float eN = 0.f;
        #pragma unroll
        for (int k = 0; k < 6; k++) eN += kp[k] * kinv * nb[k][u];
        int dcol = t + u * 128;
        float e = ehv[u];
        float av = e + eN;
        float mv = e * eN;
        __nv_bfloat16 ah = __float2bfloat16(av);
        __nv_bfloat16 al = __float2bfloat16(av - __bfloat162float(ah));
        __nv_bfloat16 mh = __float2bfloat16(mv);
        __nv_bfloat16 ml = __float2bfloat16(mv - __bfloat162float(mh));
        size_t o = (size_t)i * KSP + dcol;
        g_As[o] = ah; g_As[o + 256] = ah; g_As[o + 512] = al;
        g_Ms[o] = mh; g_Ms[o + 256] = mh; g_Ms[o + 512] = ml;
    }
}

// ---------------- readout ----------------
__global__ __launch_bounds__(128)
void score_kernel(const float* __restrict__ Ag2, const float* __restrict__ bg2) {
    int i = blockIdx.x, t = threadIdx.x;
    float v = g_h[(size_t)i * 128 + t] * Ag2[t];
    v = warp_sum(v);
    __shared__ float p[4];
    if ((t & 31) == 0) p[t >> 5] = v;
    __syncthreads();
    if (t == 0) g_s[i] = p[0] + p[1] + p[2] + p[3] + bg2[0];
}

__global__ __launch_bounds__(1024)
void stat_kernel() {
    int t = threadIdx.x;
    __shared__ float sm[1024];
    float m = NEG_INF;
    for (int i = t; i < NP; i += 1024) m = fmaxf(m, g_s[i]);
    sm[t] = m; __syncthreads();
    for (int o = 512; o > 0; o >>= 1) { if (t < o) sm[t] = fmaxf(sm[t], sm[t + o]); __syncthreads(); }
    float mx = sm[0];
    __syncthreads();
    float e = 0.f;
    for (int i = t; i < NP; i += 1024) e += expf(g_s[i] - mx);
    sm[t] = e; __syncthreads();
    for (int o = 512; o > 0; o >>= 1) { if (t < o) sm[t] += sm[t + o]; __syncthreads(); }
    if (t == 0) { g_stat[0] = mx; g_stat[1] = sm[0]; }
}

__global__ __launch_bounds__(256)
void accum_kernel(const float* __restrict__ emsg, float* __restrict__ eg) {
    int t = threadIdx.x;
    int r0 = blockIdx.x * 256;
    __shared__ float w[256];
    float mx = g_stat[0], inv = 1.f / g_stat[1];
    w[t] = expf(g_s[r0 + t] - mx) * inv;
    __syncthreads();
    float acc = 0.f;
    for (int r = 0; r < 256; r++) acc += w[r] * emsg[(size_t)(r0 + r) * DH_ + t];
    atomicAdd(&eg[t], acc);
}

// ---------------- launcher ----------------
extern "C" void kernel_launch(void* const* d_in, const int* in_sizes, int n_in,
                              void* d_out, int out_size) {
    const float* x_path = (const float*)d_in[0];
    const float* fc1_W  = (const float*)d_in[1];
    const float* fc1_b  = (const float*)d_in[2];
    const float* Wh     = (const float*)d_in[3];
    const float* bh     = (const float*)d_in[4];
    const float* Wt     = (const float*)d_in[5];
    const float* bt     = (const float*)d_in[6];
    const float* W1     = (const float*)d_in[7];
    const float* b1     = (const float*)d_in[8];
    const float* W2     = (const float*)d_in[9];
    const float* b2     = (const float*)d_in[10];
    const float* Ag1    = (const float*)d_in[11];
    const float* bg1    = (const float*)d_in[12];
    const float* Ag2    = (const float*)d_in[13];
    const float* bg2    = (const float*)d_in[14];

    float* out    = (float*)d_out;               // e_msg: 8192 x 256
    float* out_eg = out + (size_t)NP * DH_;      // e_g: 256

    void *px, *ph, *pPs, *pXs, *pAs, *pMs, *pEs;
    void *pWfc1, *pWcat, *pW1s, *pW2s, *pAg1s, *pbcat;
    cudaGetSymbolAddress(&px,  g_x);
    cudaGetSymbolAddress(&ph,  g_h);
    cudaGetSymbolAddress(&pPs,  g_Ps);
    cudaGetSymbolAddress(&pXs,  g_Xs);
    cudaGetSymbolAddress(&pAs,  g_As);
    cudaGetSymbolAddress(&pMs,  g_Ms);
    cudaGetSymbolAddress(&pEs,  g_Es);
    cudaGetSymbolAddress(&pWfc1, g_Wfc1s);
    cudaGetSymbolAddress(&pWcat, g_Wcat);
    cudaGetSymbolAddress(&pW1s, g_W1s);
    cudaGetSymbolAddress(&pW2s, g_W2s);
    cudaGetSymbolAddress(&pAg1s, g_Ag1s);
    cudaGetSymbolAddress(&pbcat, g_bcat);

    cudaFuncSetAttribute(gemm_nt_mma, cudaFuncAttributeMaxDynamicSharedMemorySize, SMEM_NT);
    cudaFuncSetAttribute(lin_mma<true, false, 0, true>,  cudaFuncAttributeMaxDynamicSharedMemorySize, LSMEM_DYN);
    cudaFuncSetAttribute(lin_mma<true, false, 0, false>, cudaFuncAttributeMaxDynamicSharedMemorySize, LSMEM_DYN);
    cudaFuncSetAttribute(lin_mma<false, false, 3, false>,cudaFuncAttributeMaxDynamicSharedMemorySize, LSMEM_DYN);
    cudaFuncSetAttribute(lin_mma<true, true, 1, false>,  cudaFuncAttributeMaxDynamicSharedMemorySize, LSMEM_DYN);

    // 0: merged prep (weight splits + bcat + zero)
    prep_kernel<<<2177, 256>>>(fc1_W, Wh, Wt, W1, W2, Ag1, bh, bt, out_eg);
    // 1: x_path split
    splita_kernel<<<NP * (DIN_/2) / 256, 256>>>(x_path, (__nv_bfloat16*)pPs, DIN_);
    // 2: fc1 + leaky -> g_x (+fused colsum into g_mean)
    lin_mma<true, false, 0, true><<<dim3(2, 128), 256, LSMEM_DYN>>>(
        (const __nv_bfloat16*)pPs, (const __nv_bfloat16*)pWfc1, fc1_b, nullptr,
        (float*)px, nullptr, KSP_FC, DH_);
    // 3: mean-mix (+split of x)
    mix_split_kernel<<<NP * 128 / 256, 256>>>();
    // 4: merged e_h|e_t (N=512) with routed epilogue
    lin_mma<false, false, 3, false><<<dim3(4, 128), 256, LSMEM_DYN>>>(
        (const __nv_bfloat16*)pXs, (const __nv_bfloat16*)pWcat, (const float*)pbcat,
        nullptr, nullptr, nullptr, KSP, 512);
    // 5: NT GEMM v2 + fused top-6  (launch index 5 -> profiled by ncu -s 5 -c 1)
    gemm_nt_mma<<<dim3(32, 64), 256, SMEM_NT>>>();
    // 6: candidate reduce + message construction
    topk_msg_kernel<<<NP, 128>>>();
    // 7-8: e_msg = leaky(a@W1+b1) + leaky(m@W2+b2) -> out (+split for Ag1)
    lin_mma<true, false, 0, false><<<dim3(2, 128), 256, LSMEM_DYN>>>(
        (const __nv_bfloat16*)pAs, (const __nv_bfloat16*)pW1s, b1, nullptr,
        out, nullptr, KSP, DH_);
    lin_mma<true, true, 1, false><<<dim3(2, 128), 256, LSMEM_DYN>>>(
        (const __nv_bfloat16*)pMs, (const __nv_bfloat16*)pW2s, b2, out,
        out, (__nv_bfloat16*)pEs, KSP, DH_);
    // 9: readout hidden
    lin_mma<true, false, 0, false><<<dim3(1, 128), 256, LSMEM_DYN>>>(
        (const __nv_bfloat16*)pEs, (const __nv_bfloat16*)pAg1s, bg1, nullptr,
        (float*)ph, nullptr, KSP, DH_/2);
    // 10-12: gated readout
    score_kernel<<<NP, 128>>>(Ag2, bg2);
    stat_kernel<<<1, 1024>>>();
    accum_kernel<<<32, 256>>>(out, out_eg);
}

// round 7
// speedup vs baseline: 2.1586x; 1.3873x over previous
#include <cuda_runtime.h>
#include <cuda_bf16.h>
#include <math.h>
#include <stdint.h>

#define NP   8192
#define DIN_ 1024
#define DH_  256
#define KSP  768                 // 3*DH split width (linears)
#define KSP_FC 3072              // 3*DIN split width
#define CANDS 384
#define NEG_INF (-3.402823466e38f)

// ---------------- scratch (allocation-free: __device__ globals) ----------------
__device__ float g_x [NP*DH_];
__device__ float g_eh[NP*DH_];
__device__ float g_et[NP*DH_];
__device__ __nv_bfloat16 g_Ps [(size_t)NP*KSP_FC];  // x_path split
__device__ __nv_bfloat16 g_Xs [(size_t)NP*KSP];     // mixed x split (A-side)
__device__ __nv_bfloat16 g_Ah [(size_t)NP*DH_];     // e_h hi (NT A operand)
__device__ __nv_bfloat16 g_Bh [(size_t)NP*DH_];     // e_t hi (NT B operand)
__device__ __nv_bfloat16 g_As [(size_t)NP*KSP];     // a split
__device__ __nv_bfloat16 g_Ms [(size_t)NP*KSP];     // m split
__device__ __nv_bfloat16 g_Es [(size_t)NP*KSP];     // e_msg split
__device__ __nv_bfloat16 g_Wfc1s[(size_t)DH_*KSP_FC];
__device__ __nv_bfloat16 g_Wcat [512*KSP];          // [Wh;Wt] split
__device__ __nv_bfloat16 g_W1s [DH_*KSP];
__device__ __nv_bfloat16 g_W2s [DH_*KSP];
__device__ __nv_bfloat16 g_Ag1s[(DH_/2)*KSP];
__device__ float g_bcat[512];
__device__ float g_candv[(size_t)NP*CANDS];
__device__ int   g_candi[(size_t)NP*CANDS];
__device__ float g_h [NP*(DH_/2)];
__device__ float g_mean[DH_];
__device__ float g_s[NP];
__device__ float g_stat[2];

__device__ __forceinline__ float leaky_f(float v) { return v > 0.f ? v : 0.01f * v; }

__device__ __forceinline__ float warp_sum(float v) {
    #pragma unroll
    for (int o = 16; o > 0; o >>= 1) v += __shfl_down_sync(0xffffffffu, v, o);
    return v;
}

// ---------------- PTX helpers ----------------
__device__ __forceinline__ uint32_t smem_u32(const void* p) {
    uint32_t a;
    asm("{ .reg .u64 t; cvta.to.shared.u64 t, %1; cvt.u32.u64 %0, t; }" : "=r"(a) : "l"(p));
    return a;
}
__device__ __forceinline__ void cp16(uint32_t dst, const void* src) {
    asm volatile("cp.async.cg.shared.global [%0], [%1], 16;" :: "r"(dst), "l"(src));
}
#define CP_COMMIT()  asm volatile("cp.async.commit_group;" ::: "memory")
#define CP_WAIT2()   asm volatile("cp.async.wait_group 2;" ::: "memory")

__device__ __forceinline__ void ldsm_x4(uint32_t (&r)[4], uint32_t addr) {
    asm volatile("ldmatrix.sync.aligned.m8n8.x4.shared.b16 {%0,%1,%2,%3}, [%4];"
                 : "=r"(r[0]), "=r"(r[1]), "=r"(r[2]), "=r"(r[3]) : "r"(addr));
}
__device__ __forceinline__ void mma_bf16(float (&d)[4], const uint32_t (&a)[4],
                                         const uint32_t* b) {
    asm volatile("mma.sync.aligned.m16n8k16.row.col.f32.bf16.bf16.f32 "
                 "{%0,%1,%2,%3}, {%4,%5,%6,%7}, {%8,%9}, {%0,%1,%2,%3};"
                 : "+f"(d[0]), "+f"(d[1]), "+f"(d[2]), "+f"(d[3])
                 : "r"(a[0]), "r"(a[1]), "r"(a[2]), "r"(a[3]), "r"(b[0]), "r"(b[1]));
}

__device__ __forceinline__ void split_pair(float v0, float v1,
                                           __nv_bfloat162& hh, __nv_bfloat162& ll) {
    __nv_bfloat16 h0 = __float2bfloat16(v0), h1 = __float2bfloat16(v1);
    hh.x = h0; hh.y = h1;
    ll.x = __float2bfloat16(v0 - __bfloat162float(h0));
    ll.y = __float2bfloat16(v1 - __bfloat162float(h1));
}

// ---------------- merged prep: weight splits + bcat + zeroing ----------------
__device__ __forceinline__ void splitw_body(const float* __restrict__ W,
                                            __nv_bfloat16* __restrict__ out,
                                            int K, int N, int baseRow, int idx) {
    int k = idx / N, n = idx - k * N;
    float v = W[idx];
    __nv_bfloat16 h = __float2bfloat16(v);
    __nv_bfloat16 l = __float2bfloat16(v - __bfloat162float(h));
    size_t o = (size_t)(n + baseRow) * (3 * K);
    out[o + k]         = h;
    out[o + K + k]     = l;
    out[o + 2 * K + k] = h;
}

__global__ void prep_kernel(const float* __restrict__ fc1W,
                            const float* __restrict__ Wh, const float* __restrict__ Wt,
                            const float* __restrict__ W1, const float* __restrict__ W2,
                            const float* __restrict__ Ag1,
                            const float* __restrict__ bh, const float* __restrict__ bt,
                            float* __restrict__ eg) {
    int b = blockIdx.x, t = threadIdx.x;
    if (b < 1024)       splitw_body(fc1W, g_Wfc1s, DIN_, DH_, 0,   b * 256 + t);
    else if (b < 1280)  splitw_body(Wh,   g_Wcat,  DH_, DH_, 0,   (b - 1024) * 256 + t);
    else if (b < 1536)  splitw_body(Wt,   g_Wcat,  DH_, DH_, 256, (b - 1280) * 256 + t);
    else if (b < 1792)  splitw_body(W1,   g_W1s,   DH_, DH_, 0,   (b - 1536) * 256 + t);
    else if (b < 2048)  splitw_body(W2,   g_W2s,   DH_, DH_, 0,   (b - 1792) * 256 + t);
    else if (b < 2176)  splitw_body(Ag1,  g_Ag1s,  DH_, DH_/2, 0, (b - 2048) * 256 + t);
    else {
        g_mean[t] = 0.f;
        eg[t] = 0.f;
        g_bcat[t] = bh[t];
        g_bcat[256 + t] = bt[t];
    }
}

// ---------------- A split: x_path (M x 1024 fp32) -> (M x 3072 bf16) [h|h|l] ----------------
__global__ __launch_bounds__(256)
void splita_kernel(const float* __restrict__ A, __nv_bfloat16* __restrict__ out, int K) {
    int idx = blockIdx.x * 256 + threadIdx.x;
    int half = K >> 1;
    int row = idx / half, c2 = idx - row * half;
    int col = c2 * 2;
    float2 v = *(const float2*)(A + (size_t)row * K + col);
    __nv_bfloat162 hh, ll;
    split_pair(v.x, v.y, hh, ll);
    size_t o = (size_t)row * (3 * K) + col;
    *(__nv_bfloat162*)&out[o]         = hh;
    *(__nv_bfloat162*)&out[o + K]     = hh;
    *(__nv_bfloat162*)&out[o + 2 * K] = ll;
}

// ---------------- mean mix (+fused split of x) ----------------
__global__ __launch_bounds__(256)
void mix_split_kernel() {
    int idx = blockIdx.x * 256 + threadIdx.x;
    int row = idx >> 7, c2 = idx & 127;
    int col = c2 * 2;
    float2 v = *(const float2*)(g_x + (size_t)row * DH_ + col);
    float x0 = (v.x + g_mean[col]     * (1.f / (float)NP)) * 0.5f;
    float x1 = (v.y + g_mean[col + 1] * (1.f / (float)NP)) * 0.5f;
    __nv_bfloat162 hh, ll;
    split_pair(x0, x1, hh, ll);
    size_t o = (size_t)row * KSP + col;
    *(__nv_bfloat162*)&g_Xs[o]       = hh;
    *(__nv_bfloat162*)&g_Xs[o + 256] = hh;
    *(__nv_bfloat162*)&g_Xs[o + 512] = ll;
}

// ---------------- generic mma.sync linear ----------------
// SPLIT: 0 none, 1 A-side split out, 3 ehet routing (cols<256 -> e_h + hi(Ah), else e_t + hi(Bh)).
// COLSUM: accumulate column sums of output into g_mean (fc1 path).
#define LSTAGE_B 15360                 // A 64x80 + B 128x80
#define LSMEM_DYN (3 * LSTAGE_B + 512)

template<bool LEAKY, bool ADD, int SPLIT, bool COLSUM>
__global__ __launch_bounds__(256, 2)
void lin_mma(const __nv_bfloat16* __restrict__ A, const __nv_bfloat16* __restrict__ Bw,
             const float* __restrict__ bias, const float* __restrict__ Cin,
             float* __restrict__ C, __nv_bfloat16* __restrict__ S,
             int Kp, int N)
{
    extern __shared__ char smem[];
    const int tid = threadIdx.x;
    const int lane = tid & 31, wid = tid >> 5;
    const int wr = wid >> 2, wc = wid & 3;
    const int bx = blockIdx.x, by = blockIdx.y;
    uint32_t sb = smem_u32(smem);
    float* colacc = (float*)(smem + 3 * LSTAGE_B);
    if (COLSUM && tid < 128) colacc[tid] = 0.f;
    const int Kb = Kp * 2;
    const char* Abase = ((const char*)A)  + (size_t)(by * 64)  * Kb;
    const char* Bbase = ((const char*)Bw) + (size_t)(bx * 128) * Kb;
    const int nch = Kp / 32;

    auto load_chunk = [&](int c, int s) {
        uint32_t aSt = sb + s * LSTAGE_B;
        uint32_t bSt = aSt + 5120;
        int coff = c * 64;
        {
            int r = tid >> 2, cc = tid & 3;
            cp16(aSt + r * 80 + cc * 16, Abase + (size_t)r * Kb + coff + cc * 16);
        }
        #pragma unroll
        for (int j = 0; j < 2; j++) {
            int q = tid + j * 256;
            int r = q >> 2, cc = q & 3;
            cp16(bSt + r * 80 + cc * 16, Bbase + (size_t)r * Kb + coff + cc * 16);
        }
    };

    float d[2][4][4];
    #pragma unroll
    for (int mf = 0; mf < 2; mf++)
        #pragma unroll
        for (int nf = 0; nf < 4; nf++)
            #pragma unroll
            for (int q = 0; q < 4; q++) d[mf][nf][q] = 0.f;

    load_chunk(0, 0); CP_COMMIT();
    load_chunk(1, 1); CP_COMMIT();
    load_chunk(2, 2); CP_COMMIT();

    const int arow_j = ((lane >> 3) & 1) * 8 + (lane & 7);
    const int akb    = (lane >> 4) * 16;
    const int bj     = lane >> 3;
    const int bn_off = (bj >> 1) * 8 + (lane & 7);
    const int bkb    = (bj & 1) * 16;

    for (int c = 0; c < nch; c++) {
        CP_WAIT2();
        __syncthreads();
        uint32_t aSt = sb + (c % 3) * LSTAGE_B;
        uint32_t bSt = aSt + 5120;

        #pragma unroll
        for (int ks = 0; ks < 2; ks++) {
            uint32_t a[2][4], b[4][2];
            #pragma unroll
            for (int mf = 0; mf < 2; mf++) {
                int row = wr * 32 + mf * 16 + arow_j;
                ldsm_x4(a[mf], aSt + row * 80 + akb + ks * 32);
            }
            {
                uint32_t bv[4];
                int row0 = wc * 32 + bn_off;
                ldsm_x4(bv, bSt + row0 * 80 + bkb + ks * 32);
                b[0][0] = bv[0]; b[0][1] = bv[1]; b[1][0] = bv[2]; b[1][1] = bv[3];
                int row1 = row0 + 16;
                ldsm_x4(bv, bSt + row1 * 80 + bkb + ks * 32);
                b[2][0] = bv[0]; b[2][1] = bv[1]; b[3][0] = bv[2]; b[3][1] = bv[3];
            }
            #pragma unroll
            for (int mf = 0; mf < 2; mf++)
                #pragma unroll
                for (int nf = 0; nf < 4; nf++)
                    mma_bf16(d[mf][nf], a[mf], b[nf]);
        }
        __syncthreads();
        if (c + 3 < nch) load_chunk(c + 3, (c + 3) % 3);
        CP_COMMIT();
    }

    // ---- epilogue ----
    const int g = lane >> 2, tq = lane & 3;
    auto emit = [&](int r, int c, float v0, float v1) {
        v0 += bias[c]; v1 += bias[c + 1];
        if (SPLIT == 3) {
            __nv_bfloat162 hh;
            hh.x = __float2bfloat16(v0); hh.y = __float2bfloat16(v1);
            if (c < 256) {
                g_eh[(size_t)r * DH_ + c]     = v0;
                g_eh[(size_t)r * DH_ + c + 1] = v1;
                *(__nv_bfloat162*)&g_Ah[(size_t)r * DH_ + c] = hh;
            } else {
                int c2 = c - 256;
                g_et[(size_t)r * DH_ + c2]     = v0;
                g_et[(size_t)r * DH_ + c2 + 1] = v1;
                *(__nv_bfloat162*)&g_Bh[(size_t)r * DH_ + c2] = hh;
            }
            return;
        }
        if (LEAKY) { v0 = leaky_f(v0); v1 = leaky_f(v1); }
        if (ADD)   { v0 += Cin[(size_t)r * N + c]; v1 += Cin[(size_t)r * N + c + 1]; }
        C[(size_t)r * N + c]     = v0;
        C[(size_t)r * N + c + 1] = v1;
        if (COLSUM) {
            int cl = c - bx * 128;
            atomicAdd(&colacc[cl], v0);
            atomicAdd(&colacc[cl + 1], v1);
        }
        if (SPLIT == 1) {
            __nv_bfloat162 hh, ll;
            split_pair(v0, v1, hh, ll);
            size_t o = (size_t)r * KSP + c;
            *(__nv_bfloat162*)&S[o]       = hh;
            *(__nv_bfloat162*)&S[o + 256] = hh;
            *(__nv_bfloat162*)&S[o + 512] = ll;
        }
    };
    #pragma unroll
    for (int mf = 0; mf < 2; mf++) {
        #pragma unroll
        for (int nf = 0; nf < 4; nf++) {
            int row = by * 64 + wr * 32 + mf * 16 + g;
            int col = bx * 128 + wc * 32 + nf * 8 + tq * 2;
            emit(row,     col, d[mf][nf][0], d[mf][nf][1]);
            emit(row + 8, col, d[mf][nf][2], d[mf][nf][3]);
        }
    }
    if (COLSUM) {
        __syncthreads();
        if (tid < 128) atomicAdd(&g_mean[bx * 128 + tid], colacc[tid]);
    }
}

// ---------------- NT GEMM (hi-only, K=256): approx logits + fused top-6/chunk ----------------
#define STAGE2_B 30720                 // A 128x80 + B 256x80
#define SMEM_NT  132608                // max(3*STAGE2_B, 128*259*4)

__global__ __launch_bounds__(256, 1)
void gemm_nt_mma() {
    extern __shared__ char smem[];
    const int tid = threadIdx.x;
    const int wid = tid >> 5, lane = tid & 31;
    const int wr = wid >> 2, wc = wid & 3;     // 2 x 4 warps, 64x64 each
    const int bx = blockIdx.x, by = blockIdx.y;
    uint32_t sb = smem_u32(smem);
    const int Kb = DH_ * 2;                    // 512 bytes per row
    const char* Abase = ((const char*)g_Ah) + (size_t)(by * 128) * Kb;
    const char* Bbase = ((const char*)g_Bh) + (size_t)(bx * 256) * Kb;

    auto load_chunk = [&](int c, int s) {
        uint32_t aSt = sb + s * STAGE2_B;
        uint32_t bSt = aSt + 10240;
        int coff = c * 64;
        #pragma unroll
        for (int j = 0; j < 2; j++) {
            int q = tid + j * 256;
            int r = q >> 2, cc = q & 3;
            cp16(aSt + r * 80 + cc * 16, Abase + (size_t)r * Kb + coff + cc * 16);
        }
        #pragma unroll
        for (int j = 0; j < 4; j++) {
            int q = tid + j * 256;
            int r = q >> 2, cc = q & 3;
            cp16(bSt + r * 80 + cc * 16, Bbase + (size_t)r * Kb + coff + cc * 16);
        }
    };

    float d[4][8][4];
    #pragma unroll
    for (int mf = 0; mf < 4; mf++)
        #pragma unroll
        for (int nf = 0; nf < 8; nf++)
            #pragma unroll
            for (int q = 0; q < 4; q++) d[mf][nf][q] = 0.f;

    load_chunk(0, 0); CP_COMMIT();
    load_chunk(1, 1); CP_COMMIT();
    load_chunk(2, 2); CP_COMMIT();

    const int arow_j = ((lane >> 3) & 1) * 8 + (lane & 7);
    const int akb    = (lane >> 4) * 16;
    const int bj     = lane >> 3;
    const int bn_off = (bj >> 1) * 8 + (lane & 7);
    const int bkb    = (bj & 1) * 16;

    for (int c = 0; c < 8; c++) {              // K=256 -> 8 chunks of 32
        CP_WAIT2();
        __syncthreads();
        uint32_t aSt = sb + (c % 3) * STAGE2_B;
        uint32_t bSt = aSt + 10240;

        #pragma unroll
        for (int ks = 0; ks < 2; ks++) {
            uint32_t a[4][4], b[8][2];
            #pragma unroll
            for (int mf = 0; mf < 4; mf++) {
                int row = wr * 64 + mf * 16 + arow_j;
                ldsm_x4(a[mf], aSt + row * 80 + akb + ks * 32);
            }
            #pragma unroll
            for (int nb = 0; nb < 4; nb++) {
                uint32_t bv[4];
                int row = wc * 64 + nb * 16 + bn_off;
                ldsm_x4(bv, bSt + row * 80 + bkb + ks * 32);
                b[nb*2][0]   = bv[0]; b[nb*2][1]   = bv[1];
                b[nb*2+1][0] = bv[2]; b[nb*2+1][1] = bv[3];
            }
            #pragma unroll
            for (int mf = 0; mf < 4; mf++)
                #pragma unroll
                for (int nf = 0; nf < 8; nf++)
                    mma_bf16(d[mf][nf], a[mf], b[nf]);
        }
        __syncthreads();
        if (c + 3 < 8) load_chunk(c + 3, (c + 3) % 3);
        CP_COMMIT();
    }

    // ---- epilogue: accums -> smem [128][259], per-(row, 128-col chunk) top-6 ----
    float* sE = (float*)smem;
    __syncthreads();
    const int g = lane >> 2, tq = lane & 3;
    #pragma unroll
    for (int mf = 0; mf < 4; mf++) {
        int r0 = wr * 64 + mf * 16 + g;
        #pragma unroll
        for (int nf = 0; nf < 8; nf++) {
            int cc = wc * 64 + nf * 8 + tq * 2;
            sE[r0 * 259 + cc]           = d[mf][nf][0];
            sE[r0 * 259 + cc + 1]       = d[mf][nf][1];
            sE[(r0 + 8) * 259 + cc]     = d[mf][nf][2];
            sE[(r0 + 8) * 259 + cc + 1] = d[mf][nf][3];
        }
    }
    __syncthreads();
    {
        int row = tid & 127, ch = tid >> 7;
        float v[6]; int ix[6];
        #pragma unroll
        for (int k = 0; k < 6; k++) { v[k] = NEG_INF; ix[k] = 0; }
        int cb = bx * 256 + ch * 128;
        const float* rp = sE + row * 259 + ch * 128;
        for (int j = 0; j < 128; j++) {
            float val = rp[j] * 0.0625f;
            if (val > v[5]) {
                v[5] = val; ix[5] = cb + j;
                #pragma unroll
                for (int k = 5; k > 0; k--) {
                    if (v[k] > v[k - 1]) {
                        float tv = v[k]; v[k] = v[k - 1]; v[k - 1] = tv;
                        int   ti = ix[k]; ix[k] = ix[k - 1]; ix[k - 1] = ti;
                    }
                }
            }
        }
        size_t rg = (size_t)by * 128 + row;
        size_t o = rg * CANDS + bx * 12 + ch * 6;
        #pragma unroll
        for (int k = 0; k < 6; k++) { g_candv[o + k] = v[k]; g_candi[o + k] = ix[k]; }
    }
}

// ---------------- topk: approx top-12 -> exact rescore -> exact top-6 -> messages ----------------
__global__ __launch_bounds__(128)
void topk_msg_kernel() {
    int i = blockIdx.x;
    int t = threadIdx.x;
    const float* cv = g_candv + (size_t)i * CANDS;
    const int*   ci = g_candi + (size_t)i * CANDS;

    // per-thread top-3 over its 3 candidates (384/128)
    float lv[3]; int li[3];
    #pragma unroll
    for (int k = 0; k < 3; k++) { lv[k] = NEG_INF; li[k] = 0; }
    #pragma unroll
    for (int j = 0; j < 3; j++) {
        int c = t + j * 128;
        float v = cv[c];
        if (v > lv[2]) {
            lv[2] = v; li[2] = ci[c];
            #pragma unroll
            for (int k = 2; k > 0; k--) {
                if (lv[k] > lv[k - 1]) {
                    float tv = lv[k]; lv[k] = lv[k - 1]; lv[k - 1] = tv;
                    int   tx = li[k]; li[k] = li[k - 1]; li[k - 1] = tx;
                }
            }
        }
    }

    // 12 rounds of block argmax -> approx top-12 indices
    __shared__ float sv[128]; __shared__ int si[128];
    __shared__ int topi[12];
    for (int r = 0; r < 12; r++) {
        sv[t] = lv[0]; si[t] = t;
        __syncthreads();
        #pragma unroll
        for (int o = 64; o > 0; o >>= 1) {
            if (t < o && sv[t + o] > sv[t]) { sv[t] = sv[t + o]; si[t] = si[t + o]; }
            __syncthreads();
        }
        if (t == si[0]) {
            topi[r] = li[0];
            lv[0] = lv[1]; li[0] = li[1];
            lv[1] = lv[2]; li[1] = li[2];
            lv[2] = NEG_INF;
        }
        __syncthreads();
    }

    // exact fp32 rescore of the 12 candidates: logit_j = (e_h[i] . e_t[cand_j]) / 16
    int ti12[12];
    #pragma unroll
    for (int k = 0; k < 12; k++) ti12[k] = topi[k];

    float ehv[2];
    #pragma unroll
    for (int u = 0; u < 2; u++) ehv[u] = g_eh[(size_t)i * DH_ + t + u * 128];

    float nb12[12][2];
    #pragma unroll
    for (int k = 0; k < 12; k++)
        #pragma unroll
        for (int u = 0; u < 2; u++)
            nb12[k][u] = g_et[(size_t)ti12[k] * DH_ + t + u * 128];

    __shared__ float part[4][12];
    __shared__ float tot[12];
    int lane = t & 31, wp = t >> 5;
    #pragma unroll
    for (int k = 0; k < 12; k++) {
        float s = ehv[0] * nb12[k][0] + ehv[1] * nb12[k][1];
        s = warp_sum(s);
        if (lane == 0) part[wp][k] = s;
    }
    __syncthreads();
    if (t < 12) tot[t] = (part[0][t] + part[1][t] + part[2][t] + part[3][t]) * 0.0625f;
    __syncthreads();

    // exact top-6 of the 12 (all threads redundantly; deterministic)
    float val12[12];
    #pragma unroll
    for (int k = 0; k < 12; k++) val12[k] = tot[k];
    int sel[6];
    unsigned used = 0;
    #pragma unroll
    for (int r = 0; r < 6; r++) {
        int best = -1; float bv = NEG_INF;
        #pragma unroll
        for (int k = 0; k < 12; k++) {
            if (!(used >> k & 1) && val12[k] > bv) { bv = val12[k]; best = k; }
        }
        used |= 1u << best;
        sel[r] = best;
    }

    // softmax p over the 6 exact logits
    float tv[6];
    float nb[6][2];
    #pragma unroll
    for (int k = 0; k < 6; k++) {
        tv[k] = val12[sel[k]];
        nb[k][0] = nb12[sel[k]][0];
        nb[k][1] = nb12[sel[k]][1];
    }
    float pm = tv[0];
    #pragma unroll
    for (int k = 1; k < 6; k++) pm = fmaxf(pm, tv[k]);
    float pk[6], ps = 0.f;
    #pragma unroll
    for (int k = 0; k < 6; k++) { pk[k] = expf(tv[k] - pm); ps += pk[k]; }
    float pinv = 1.f / ps;
    #pragma unroll
    for (int k = 0; k < 6; k++) pk[k] *= pinv;

    // message phase
    float sN[6], sG[6];
    #pragma unroll
    for (int k = 0; k < 6; k++) { sN[k] = 0.f; sG[k] = 0.f; }
    #pragma unroll
    for (int k = 0; k < 6; k++) {
        #pragma unroll
        for (int u = 0; u < 2; u++) {
            float ehr = pk[k] * nb[k][u] + (1.f - pk[k]) * ehv[u];
            float gt  = tanhf(ehv[u] + ehr);
            sN[k] += nb[k][u];
            sG[k] += gt;
        }
    }

    __syncthreads();
    #pragma unroll
    for (int q = 0; q < 6; q++) {
        float v = warp_sum(sN[q]); if (lane == 0) part[wp][q]     = v;
        float w = warp_sum(sG[q]); if (lane == 0) part[wp][6 + q] = w;
    }
    __syncthreads();
    if (t < 12) tot[t] = part[0][t] + part[1][t] + part[2][t] + part[3][t];
    __syncthreads();

    float kw[6], km = NEG_INF;
    #pragma unroll
    for (int k = 0; k < 6; k++) { kw[k] = tot[k] * tot[6 + k]; km = fmaxf(km, kw[k]); }
    float kp[6], ks = 0.f;
    #pragma unroll
    for (int k = 0; k < 6; k++) { kp[k] = expf(kw[k] - km); ks += kp[k]; }
    float kinv = 1.f / ks;

    #pragma unroll
    for (int u = 0; u < 2; u++) {
        float eN = 0.f;
        #pragma unroll
        for (int k = 0; k < 6; k++) eN += kp[k] * kinv * nb[k][u];
        int dcol = t + u * 128;
        float e = ehv[u];
        float av = e + eN;
        float mv = e * eN;
        __nv_bfloat16 ah = __float2bfloat16(av);
        __nv_bfloat16 al = __float2bfloat16(av - __bfloat162float(ah));
        __nv_bfloat16 mh = __float2bfloat16(mv);
        __nv_bfloat16 ml = __float2bfloat16(mv - __bfloat162float(mh));
        size_t o = (size_t)i * KSP + dcol;
        g_As[o] = ah; g_As[o + 256] = ah; g_As[o + 512] = al;
        g_Ms[o] = mh; g_Ms[o + 256] = mh; g_Ms[o + 512] = ml;
    }
}

// ---------------- readout ----------------
__global__ __launch_bounds__(128)
void score_kernel(const float* __restrict__ Ag2, const float* __restrict__ bg2) {
    int i = blockIdx.x, t = threadIdx.x;
    float v = g_h[(size_t)i * 128 + t] * Ag2[t];
    v = warp_sum(v);
    __shared__ float p[4];
    if ((t & 31) == 0) p[t >> 5] = v;
    __syncthreads();
    if (t == 0) g_s[i] = p[0] + p[1] + p[2] + p[3] + bg2[0];
}

__global__ __launch_bounds__(1024)
void stat_kernel() {
    int t = threadIdx.x;
    __shared__ float sm[1024];
    float m = NEG_INF;
    for (int i = t; i < NP; i += 1024) m = fmaxf(m, g_s[i]);
    sm[t] = m; __syncthreads();
    for (int o = 512; o > 0; o >>= 1) { if (t < o) sm[t] = fmaxf(sm[t], sm[t + o]); __syncthreads(); }
    float mx = sm[0];
    __syncthreads();
    float e = 0.f;
    for (int i = t; i < NP; i += 1024) e += expf(g_s[i] - mx);
    sm[t] = e; __syncthreads();
    for (int o = 512; o > 0; o >>= 1) { if (t < o) sm[t] += sm[t + o]; __syncthreads(); }
    if (t == 0) { g_stat[0] = mx; g_stat[1] = sm[0]; }
}

__global__ __launch_bounds__(256)
void accum_kernel(const float* __restrict__ emsg, float* __restrict__ eg) {
    int t = threadIdx.x;
    int r0 = blockIdx.x * 256;
    __shared__ float w[256];
    float mx = g_stat[0], inv = 1.f / g_stat[1];
    w[t] = expf(g_s[r0 + t] - mx) * inv;
    __syncthreads();
    float acc = 0.f;
    for (int r = 0; r < 256; r++) acc += w[r] * emsg[(size_t)(r0 + r) * DH_ + t];
    atomicAdd(&eg[t], acc);
}

// ---------------- launcher ----------------
extern "C" void kernel_launch(void* const* d_in, const int* in_sizes, int n_in,
                              void* d_out, int out_size) {
    const float* x_path = (const float*)d_in[0];
    const float* fc1_W  = (const float*)d_in[1];
    const float* fc1_b  = (const float*)d_in[2];
    const float* Wh     = (const float*)d_in[3];
    const float* bh     = (const float*)d_in[4];
    const float* Wt     = (const float*)d_in[5];
    const float* bt     = (const float*)d_in[6];
    const float* W1     = (const float*)d_in[7];
    const float* b1     = (const float*)d_in[8];
    const float* W2     = (const float*)d_in[9];
    const float* b2     = (const float*)d_in[10];
    const float* Ag1    = (const float*)d_in[11];
    const float* bg1    = (const float*)d_in[12];
    const float* Ag2    = (const float*)d_in[13];
    const float* bg2    = (const float*)d_in[14];

    float* out    = (float*)d_out;               // e_msg: 8192 x 256
    float* out_eg = out + (size_t)NP * DH_;      // e_g: 256

    void *px, *ph, *pPs, *pXs, *pAs, *pMs, *pEs;
    void *pWfc1, *pWcat, *pW1s, *pW2s, *pAg1s, *pbcat;
    cudaGetSymbolAddress(&px,  g_x);
    cudaGetSymbolAddress(&ph,  g_h);
    cudaGetSymbolAddress(&pPs,  g_Ps);
    cudaGetSymbolAddress(&pXs,  g_Xs);
    cudaGetSymbolAddress(&pAs,  g_As);
    cudaGetSymbolAddress(&pMs,  g_Ms);
    cudaGetSymbolAddress(&pEs,  g_Es);
    cudaGetSymbolAddress(&pWfc1, g_Wfc1s);
    cudaGetSymbolAddress(&pWcat, g_Wcat);
    cudaGetSymbolAddress(&pW1s, g_W1s);
    cudaGetSymbolAddress(&pW2s, g_W2s);
    cudaGetSymbolAddress(&pAg1s, g_Ag1s);
    cudaGetSymbolAddress(&pbcat, g_bcat);

    cudaFuncSetAttribute(gemm_nt_mma, cudaFuncAttributeMaxDynamicSharedMemorySize, SMEM_NT);
    cudaFuncSetAttribute(lin_mma<true, false, 0, true>,  cudaFuncAttributeMaxDynamicSharedMemorySize, LSMEM_DYN);
    cudaFuncSetAttribute(lin_mma<true, false, 0, false>, cudaFuncAttributeMaxDynamicSharedMemorySize, LSMEM_DYN);
    cudaFuncSetAttribute(lin_mma<false, false, 3, false>,cudaFuncAttributeMaxDynamicSharedMemorySize, LSMEM_DYN);
    cudaFuncSetAttribute(lin_mma<true, true, 1, false>,  cudaFuncAttributeMaxDynamicSharedMemorySize, LSMEM_DYN);

    // 0: merged prep (weight splits + bcat + zero)
    prep_kernel<<<2177, 256>>>(fc1_W, Wh, Wt, W1, W2, Ag1, bh, bt, out_eg);
    // 1: x_path split
    splita_kernel<<<NP * (DIN_/2) / 256, 256>>>(x_path, (__nv_bfloat16*)pPs, DIN_);
    // 2: fc1 + leaky -> g_x (+fused colsum into g_mean)
    lin_mma<true, false, 0, true><<<dim3(2, 128), 256, LSMEM_DYN>>>(
        (const __nv_bfloat16*)pPs, (const __nv_bfloat16*)pWfc1, fc1_b, nullptr,
        (float*)px, nullptr, KSP_FC, DH_);
    // 3: mean-mix (+split of x)
    mix_split_kernel<<<NP * 128 / 256, 256>>>();
    // 4: merged e_h|e_t (N=512) with routed epilogue (fp32 + hi bf16)
    lin_mma<false, false, 3, false><<<dim3(4, 128), 256, LSMEM_DYN>>>(
        (const __nv_bfloat16*)pXs, (const __nv_bfloat16*)pWcat, (const float*)pbcat,
        nullptr, nullptr, nullptr, KSP, 512);
    // 5: hi-only NT GEMM (K=256) + fused approx top-6 per chunk
    gemm_nt_mma<<<dim3(32, 64), 256, SMEM_NT>>>();
    // 6: approx top-12 -> exact rescore -> exact top-6 -> messages
    topk_msg_kernel<<<NP, 128>>>();
    // 7-8: e_msg = leaky(a@W1+b1) + leaky(m@W2+b2) -> out (+split for Ag1)
    lin_mma<true, false, 0, false><<<dim3(2, 128), 256, LSMEM_DYN>>>(
        (const __nv_bfloat16*)pAs, (const __nv_bfloat16*)pW1s, b1, nullptr,
        out, nullptr, KSP, DH_);
    lin_mma<true, true, 1, false><<<dim3(2, 128), 256, LSMEM_DYN>>>(
        (const __nv_bfloat16*)pMs, (const __nv_bfloat16*)pW2s, b2, out,
        out, (__nv_bfloat16*)pEs, KSP, DH_);
    // 9: readout hidden
    lin_mma<true, false, 0, false><<<dim3(1, 128), 256, LSMEM_DYN>>>(
        (const __nv_bfloat16*)pEs, (const __nv_bfloat16*)pAg1s, bg1, nullptr,
        (float*)ph, nullptr, KSP, DH_/2);
    // 10-12: gated readout
    score_kernel<<<NP, 128>>>(Ag2, bg2);
    stat_kernel<<<1, 1024>>>();
    accum_kernel<<<32, 256>>>(out, out_eg);
}

// round 8
// speedup vs baseline: 2.2293x; 1.0327x over previous
#include <cuda_runtime.h>
#include <cuda_bf16.h>
#include <math.h>
#include <stdint.h>

#define NP   8192
#define DIN_ 1024
#define DH_  256
#define KSP  768                 // 3*DH split width (linears)
#define KSP_FC 3072              // 3*DIN split width
#define CANDS 384
#define NEG_INF (-3.402823466e38f)

// ---------------- scratch (allocation-free: __device__ globals) ----------------
__device__ float g_x [NP*DH_];
__device__ float g_eh[NP*DH_];
__device__ float g_et[NP*DH_];
__device__ __nv_bfloat16 g_Ps [(size_t)NP*KSP_FC];  // x_path split
__device__ __nv_bfloat16 g_Xs [(size_t)NP*KSP];     // mixed x split (A-side)
__device__ __nv_bfloat16 g_Ah [(size_t)NP*DH_];     // e_h hi (NT A operand)
__device__ __nv_bfloat16 g_Bh [(size_t)NP*DH_];     // e_t hi (NT B operand)
__device__ __nv_bfloat16 g_As [(size_t)NP*KSP];     // a split
__device__ __nv_bfloat16 g_Ms [(size_t)NP*KSP];     // m split
__device__ __nv_bfloat16 g_Es [(size_t)NP*KSP];     // e_msg split
__device__ __nv_bfloat16 g_Wfc1s[(size_t)DH_*KSP_FC];
__device__ __nv_bfloat16 g_Wcat [512*KSP];          // [Wh;Wt] split
__device__ __nv_bfloat16 g_W1s [DH_*KSP];
__device__ __nv_bfloat16 g_W2s [DH_*KSP];
__device__ __nv_bfloat16 g_Ag1s[(DH_/2)*KSP];
__device__ float g_bcat[512];
__device__ float g_candv[(size_t)NP*CANDS];
__device__ int   g_candi[(size_t)NP*CANDS];
__device__ float g_h [NP*(DH_/2)];
__device__ float g_mean[DH_];
__device__ float g_s[NP];
__device__ float g_stat[2];

__device__ __forceinline__ float leaky_f(float v) { return v > 0.f ? v : 0.01f * v; }

__device__ __forceinline__ float warp_sum(float v) {
    #pragma unroll
    for (int o = 16; o > 0; o >>= 1) v += __shfl_down_sync(0xffffffffu, v, o);
    return v;
}

// ---------------- PTX helpers ----------------
__device__ __forceinline__ uint32_t smem_u32(const void* p) {
    uint32_t a;
    asm("{ .reg .u64 t; cvta.to.shared.u64 t, %1; cvt.u32.u64 %0, t; }" : "=r"(a) : "l"(p));
    return a;
}
__device__ __forceinline__ void cp16(uint32_t dst, const void* src) {
    asm volatile("cp.async.cg.shared.global [%0], [%1], 16;" :: "r"(dst), "l"(src));
}
#define CP_COMMIT()  asm volatile("cp.async.commit_group;" ::: "memory")
#define CP_WAIT1()   asm volatile("cp.async.wait_group 1;" ::: "memory")
#define CP_WAIT0()   asm volatile("cp.async.wait_group 0;" ::: "memory")

__device__ __forceinline__ void ldsm_x4(uint32_t (&r)[4], uint32_t addr) {
    asm volatile("ldmatrix.sync.aligned.m8n8.x4.shared.b16 {%0,%1,%2,%3}, [%4];"
                 : "=r"(r[0]), "=r"(r[1]), "=r"(r[2]), "=r"(r[3]) : "r"(addr));
}
__device__ __forceinline__ void mma_bf16(float (&d)[4], const uint32_t (&a)[4],
                                         const uint32_t* b) {
    asm volatile("mma.sync.aligned.m16n8k16.row.col.f32.bf16.bf16.f32 "
                 "{%0,%1,%2,%3}, {%4,%5,%6,%7}, {%8,%9}, {%0,%1,%2,%3};"
                 : "+f"(d[0]), "+f"(d[1]), "+f"(d[2]), "+f"(d[3])
                 : "r"(a[0]), "r"(a[1]), "r"(a[2]), "r"(a[3]), "r"(b[0]), "r"(b[1]));
}

__device__ __forceinline__ void split_pair(float v0, float v1,
                                           __nv_bfloat162& hh, __nv_bfloat162& ll) {
    __nv_bfloat16 h0 = __float2bfloat16(v0), h1 = __float2bfloat16(v1);
    hh.x = h0; hh.y = h1;
    ll.x = __float2bfloat16(v0 - __bfloat162float(h0));
    ll.y = __float2bfloat16(v1 - __bfloat162float(h1));
}

// ---------------- merged prep: weight splits + bcat + zeroing ----------------
__device__ __forceinline__ void splitw_body(const float* __restrict__ W,
                                            __nv_bfloat16* __restrict__ out,
                                            int K, int N, int baseRow, int idx) {
    int k = idx / N, n = idx - k * N;
    float v = W[idx];
    __nv_bfloat16 h = __float2bfloat16(v);
    __nv_bfloat16 l = __float2bfloat16(v - __bfloat162float(h));
    size_t o = (size_t)(n + baseRow) * (3 * K);
    out[o + k]         = h;
    out[o + K + k]     = l;
    out[o + 2 * K + k] = h;
}

__global__ void prep_kernel(const float* __restrict__ fc1W,
                            const float* __restrict__ Wh, const float* __restrict__ Wt,
                            const float* __restrict__ W1, const float* __restrict__ W2,
                            const float* __restrict__ Ag1,
                            const float* __restrict__ bh, const float* __restrict__ bt,
                            float* __restrict__ eg) {
    int b = blockIdx.x, t = threadIdx.x;
    if (b < 1024)       splitw_body(fc1W, g_Wfc1s, DIN_, DH_, 0,   b * 256 + t);
    else if (b < 1280)  splitw_body(Wh,   g_Wcat,  DH_, DH_, 0,   (b - 1024) * 256 + t);
    else if (b < 1536)  splitw_body(Wt,   g_Wcat,  DH_, DH_, 256, (b - 1280) * 256 + t);
    else if (b < 1792)  splitw_body(W1,   g_W1s,   DH_, DH_, 0,   (b - 1536) * 256 + t);
    else if (b < 2048)  splitw_body(W2,   g_W2s,   DH_, DH_, 0,   (b - 1792) * 256 + t);
    else if (b < 2176)  splitw_body(Ag1,  g_Ag1s,  DH_, DH_/2, 0, (b - 2048) * 256 + t);
    else {
        g_mean[t] = 0.f;
        eg[t] = 0.f;
        g_bcat[t] = bh[t];
        g_bcat[256 + t] = bt[t];
    }
}

// ---------------- A split: x_path (M x 1024 fp32) -> (M x 3072 bf16) [h|h|l] ----------------
__global__ __launch_bounds__(256)
void splita_kernel(const float* __restrict__ A, __nv_bfloat16* __restrict__ out, int K) {
    int idx = blockIdx.x * 256 + threadIdx.x;
    int half = K >> 1;
    int row = idx / half, c2 = idx - row * half;
    int col = c2 * 2;
    float2 v = *(const float2*)(A + (size_t)row * K + col);
    __nv_bfloat162 hh, ll;
    split_pair(v.x, v.y, hh, ll);
    size_t o = (size_t)row * (3 * K) + col;
    *(__nv_bfloat162*)&out[o]         = hh;
    *(__nv_bfloat162*)&out[o + K]     = hh;
    *(__nv_bfloat162*)&out[o + 2 * K] = ll;
}

// ---------------- mean mix (+fused split of x) ----------------
__global__ __launch_bounds__(256)
void mix_split_kernel() {
    int idx = blockIdx.x * 256 + threadIdx.x;
    int row = idx >> 7, c2 = idx & 127;
    int col = c2 * 2;
    float2 v = *(const float2*)(g_x + (size_t)row * DH_ + col);
    float x0 = (v.x + g_mean[col]     * (1.f / (float)NP)) * 0.5f;
    float x1 = (v.y + g_mean[col + 1] * (1.f / (float)NP)) * 0.5f;
    __nv_bfloat162 hh, ll;
    split_pair(x0, x1, hh, ll);
    size_t o = (size_t)row * KSP + col;
    *(__nv_bfloat162*)&g_Xs[o]       = hh;
    *(__nv_bfloat162*)&g_Xs[o + 256] = hh;
    *(__nv_bfloat162*)&g_Xs[o + 512] = ll;
}

// ---------------- generic mma.sync linear (BK=128 elems, 2-stage, occ 2) ----------------
// SPLIT: 0 none, 1 A-side split out, 3 ehet routing.
// COLSUM: accumulate column sums of output into g_mean (fc1 path).
// Stage: A 64 rows x 272B + B 128 rows x 272B.
#define L_AST   17408                    // 64*272
#define L_STAGE 52224                    // + 128*272
#define LSMEM_DYN (2 * L_STAGE + 512)

template<bool LEAKY, bool ADD, int SPLIT, bool COLSUM>
__global__ __launch_bounds__(256, 2)
void lin_mma(const __nv_bfloat16* __restrict__ A, const __nv_bfloat16* __restrict__ Bw,
             const float* __restrict__ bias, const float* __restrict__ Cin,
             float* __restrict__ C, __nv_bfloat16* __restrict__ S,
             int Kp, int N)
{
    extern __shared__ char smem[];
    const int tid = threadIdx.x;
    const int lane = tid & 31, wid = tid >> 5;
    const int wr = wid >> 2, wc = wid & 3;
    const int bx = blockIdx.x, by = blockIdx.y;
    uint32_t sb = smem_u32(smem);
    float* colacc = (float*)(smem + 2 * L_STAGE);
    if (COLSUM && tid < 128) colacc[tid] = 0.f;
    const int Kb = Kp * 2;
    const char* Abase = ((const char*)A)  + (size_t)(by * 64)  * Kb;
    const char* Bbase = ((const char*)Bw) + (size_t)(bx * 128) * Kb;
    const int nch = Kp / 128;            // 128-elem (256 B) chunks

    auto load_chunk = [&](int c, int s) {
        uint32_t aSt = sb + s * L_STAGE;
        uint32_t bSt = aSt + L_AST;
        int coff = c * 256;
        int r = tid >> 4, cc = tid & 15;
        #pragma unroll
        for (int j = 0; j < 4; j++) {    // A: 64 rows x 16 units
            int rr = r + j * 16;
            cp16(aSt + rr * 272 + cc * 16, Abase + (size_t)rr * Kb + coff + cc * 16);
        }
        #pragma unroll
        for (int j = 0; j < 8; j++) {    // B: 128 rows x 16 units
            int rr = r + j * 16;
            cp16(bSt + rr * 272 + cc * 16, Bbase + (size_t)rr * Kb + coff + cc * 16);
        }
    };

    float d[2][4][4];
    #pragma unroll
    for (int mf = 0; mf < 2; mf++)
        #pragma unroll
        for (int nf = 0; nf < 4; nf++)
            #pragma unroll
            for (int q = 0; q < 4; q++) d[mf][nf][q] = 0.f;

    load_chunk(0, 0); CP_COMMIT();
    if (nch > 1) load_chunk(1, 1);
    CP_COMMIT();

    const int arow_j = ((lane >> 3) & 1) * 8 + (lane & 7);
    const int akb    = (lane >> 4) * 16;
    const int bj     = lane >> 3;
    const int bn_off = (bj >> 1) * 8 + (lane & 7);
    const int bkb    = (bj & 1) * 16;

    for (int c = 0; c < nch; c++) {
        CP_WAIT1();
        __syncthreads();
        uint32_t aSt = sb + (c & 1) * L_STAGE;
        uint32_t bSt = aSt + L_AST;

        #pragma unroll
        for (int ks = 0; ks < 8; ks++) {
            uint32_t a[2][4], b[4][2];
            #pragma unroll
            for (int mf = 0; mf < 2; mf++) {
                int row = wr * 32 + mf * 16 + arow_j;
                ldsm_x4(a[mf], aSt + row * 272 + ks * 32 + akb);
            }
            {
                uint32_t bv[4];
                int row0 = wc * 32 + bn_off;
                ldsm_x4(bv, bSt + row0 * 272 + ks * 32 + bkb);
                b[0][0] = bv[0]; b[0][1] = bv[1]; b[1][0] = bv[2]; b[1][1] = bv[3];
                int row1 = row0 + 16;
                ldsm_x4(bv, bSt + row1 * 272 + ks * 32 + bkb);
                b[2][0] = bv[0]; b[2][1] = bv[1]; b[3][0] = bv[2]; b[3][1] = bv[3];
            }
            #pragma unroll
            for (int mf = 0; mf < 2; mf++)
                #pragma unroll
                for (int nf = 0; nf < 4; nf++)
                    mma_bf16(d[mf][nf], a[mf], b[nf]);
        }
        __syncthreads();
        if (c + 2 < nch) load_chunk(c + 2, c & 1);
        CP_COMMIT();
    }

    // ---- epilogue ----
    const int g = lane >> 2, tq = lane & 3;
    auto emit = [&](int r, int c, float v0, float v1) {
        v0 += bias[c]; v1 += bias[c + 1];
        if (SPLIT == 3) {
            __nv_bfloat162 hh;
            hh.x = __float2bfloat16(v0); hh.y = __float2bfloat16(v1);
            if (c < 256) {
                g_eh[(size_t)r * DH_ + c]     = v0;
                g_eh[(size_t)r * DH_ + c + 1] = v1;
                *(__nv_bfloat162*)&g_Ah[(size_t)r * DH_ + c] = hh;
            } else {
                int c2 = c - 256;
                g_et[(size_t)r * DH_ + c2]     = v0;
                g_et[(size_t)r * DH_ + c2 + 1] = v1;
                *(__nv_bfloat162*)&g_Bh[(size_t)r * DH_ + c2] = hh;
            }
            return;
        }
        if (LEAKY) { v0 = leaky_f(v0); v1 = leaky_f(v1); }
        if (ADD)   { v0 += Cin[(size_t)r * N + c]; v1 += Cin[(size_t)r * N + c + 1]; }
        C[(size_t)r * N + c]     = v0;
        C[(size_t)r * N + c + 1] = v1;
        if (COLSUM) {
            int cl = c - bx * 128;
            atomicAdd(&colacc[cl], v0);
            atomicAdd(&colacc[cl + 1], v1);
        }
        if (SPLIT == 1) {
            __nv_bfloat162 hh, ll;
            split_pair(v0, v1, hh, ll);
            size_t o = (size_t)r * KSP + c;
            *(__nv_bfloat162*)&S[o]       = hh;
            *(__nv_bfloat162*)&S[o + 256] = hh;
            *(__nv_bfloat162*)&S[o + 512] = ll;
        }
    };
    #pragma unroll
    for (int mf = 0; mf < 2; mf++) {
        #pragma unroll
        for (int nf = 0; nf < 4; nf++) {
            int row = by * 64 + wr * 32 + mf * 16 + g;
            int col = bx * 128 + wc * 32 + nf * 8 + tq * 2;
            emit(row,     col, d[mf][nf][0], d[mf][nf][1]);
            emit(row + 8, col, d[mf][nf][2], d[mf][nf][3]);
        }
    }
    if (COLSUM) {
        __syncthreads();
        if (tid < 128) atomicAdd(&g_mean[bx * 128 + tid], colacc[tid]);
    }
}

// ---------------- NT GEMM (hi-only, K=256, 2 mega-chunks): logits + fused top-6 ----------------
// Stage: A 128 rows x 272B + B 256 rows x 272B = 104448 B; 2 stages resident.
#define NT_AST   34816                   // 128*272
#define NT_STAGE 104448                  // + 256*272
#define SMEM_NT  208896                  // 2 stages (epilogue 128*259*4 = 132608 fits)

__global__ __launch_bounds__(256, 1)
void gemm_nt_mma() {
    extern __shared__ char smem[];
    const int tid = threadIdx.x;
    const int wid = tid >> 5, lane = tid & 31;
    const int wr = wid >> 2, wc = wid & 3;     // 2 x 4 warps, 64x64 each
    const int bx = blockIdx.x, by = blockIdx.y;
    uint32_t sb = smem_u32(smem);
    const int Kb = DH_ * 2;                    // 512 bytes per row
    const char* Abase = ((const char*)g_Ah) + (size_t)(by * 128) * Kb;
    const char* Bbase = ((const char*)g_Bh) + (size_t)(bx * 256) * Kb;

    auto load_chunk = [&](int c, int s) {
        uint32_t aSt = sb + s * NT_STAGE;
        uint32_t bSt = aSt + NT_AST;
        int coff = c * 256;
        int r = tid >> 4, cc = tid & 15;
        #pragma unroll
        for (int j = 0; j < 8; j++) {          // A: 128 rows
            int rr = r + j * 16;
            cp16(aSt + rr * 272 + cc * 16, Abase + (size_t)rr * Kb + coff + cc * 16);
        }
        #pragma unroll
        for (int j = 0; j < 16; j++) {         // B: 256 rows
            int rr = r + j * 16;
            cp16(bSt + rr * 272 + cc * 16, Bbase + (size_t)rr * Kb + coff + cc * 16);
        }
    };

    float d[4][8][4];
    #pragma unroll
    for (int mf = 0; mf < 4; mf++)
        #pragma unroll
        for (int nf = 0; nf < 8; nf++)
            #pragma unroll
            for (int q = 0; q < 4; q++) d[mf][nf][q] = 0.f;

    load_chunk(0, 0); CP_COMMIT();
    load_chunk(1, 1); CP_COMMIT();

    const int arow_j = ((lane >> 3) & 1) * 8 + (lane & 7);
    const int akb    = (lane >> 4) * 16;
    const int bj     = lane >> 3;
    const int bn_off = (bj >> 1) * 8 + (lane & 7);
    const int bkb    = (bj & 1) * 16;

    #pragma unroll
    for (int c = 0; c < 2; c++) {
        if (c == 0) CP_WAIT1(); else CP_WAIT0();
        __syncthreads();
        uint32_t aSt = sb + c * NT_STAGE;
        uint32_t bSt = aSt + NT_AST;

        #pragma unroll
        for (int ks = 0; ks < 8; ks++) {
            uint32_t a[4][4], b[8][2];
            #pragma unroll
            for (int mf = 0; mf < 4; mf++) {
                int row = wr * 64 + mf * 16 + arow_j;
                ldsm_x4(a[mf], aSt + row * 272 + ks * 32 + akb);
            }
            #pragma unroll
            for (int nb = 0; nb < 4; nb++) {
                uint32_t bv[4];
                int row = wc * 64 + nb * 16 + bn_off;
                ldsm_x4(bv, bSt + row * 272 + ks * 32 + bkb);
                b[nb*2][0]   = bv[0]; b[nb*2][1]   = bv[1];
                b[nb*2+1][0] = bv[2]; b[nb*2+1][1] = bv[3];
            }
            #pragma unroll
            for (int mf = 0; mf < 4; mf++)
                #pragma unroll
                for (int nf = 0; nf < 8; nf++)
                    mma_bf16(d[mf][nf], a[mf], b[nf]);
        }
    }

    // ---- epilogue: accums -> smem [128][259], per-(row, 128-col chunk) top-6 ----
    float* sE = (float*)smem;
    __syncthreads();
    const int g = lane >> 2, tq = lane & 3;
    #pragma unroll
    for (int mf = 0; mf < 4; mf++) {
        int r0 = wr * 64 + mf * 16 + g;
        #pragma unroll
        for (int nf = 0; nf < 8; nf++) {
            int cc = wc * 64 + nf * 8 + tq * 2;
            sE[r0 * 259 + cc]           = d[mf][nf][0];
            sE[r0 * 259 + cc + 1]       = d[mf][nf][1];
            sE[(r0 + 8) * 259 + cc]     = d[mf][nf][2];
            sE[(r0 + 8) * 259 + cc + 1] = d[mf][nf][3];
        }
    }
    __syncthreads();
    {
        int row = tid & 127, ch = tid >> 7;
        float v[6]; int ix[6];
        #pragma unroll
        for (int k = 0; k < 6; k++) { v[k] = NEG_INF; ix[k] = 0; }
        int cb = bx * 256 + ch * 128;
        const float* rp = sE + row * 259 + ch * 128;
        for (int j = 0; j < 128; j++) {
            float val = rp[j] * 0.0625f;
            if (val > v[5]) {
                v[5] = val; ix[5] = cb + j;
                #pragma unroll
                for (int k = 5; k > 0; k--) {
                    if (v[k] > v[k - 1]) {
                        float tv = v[k]; v[k] = v[k - 1]; v[k - 1] = tv;
                        int   ti = ix[k]; ix[k] = ix[k - 1]; ix[k - 1] = ti;
                    }
                }
            }
        }
        size_t rg = (size_t)by * 128 + row;
        size_t o = rg * CANDS + bx * 12 + ch * 6;
        #pragma unroll
        for (int k = 0; k < 6; k++) { g_candv[o + k] = v[k]; g_candi[o + k] = ix[k]; }
    }
}

// ---------------- topk: approx top-12 -> exact rescore -> exact top-6 -> messages ----------------
__global__ __launch_bounds__(128)
void topk_msg_kernel() {
    int i = blockIdx.x;
    int t = threadIdx.x;
    const float* cv = g_candv + (size_t)i * CANDS;
    const int*   ci = g_candi + (size_t)i * CANDS;

    float lv[3]; int li[3];
    #pragma unroll
    for (int k = 0; k < 3; k++) { lv[k] = NEG_INF; li[k] = 0; }
    #pragma unroll
    for (int j = 0; j < 3; j++) {
        int c = t + j * 128;
        float v = cv[c];
        if (v > lv[2]) {
            lv[2] = v; li[2] = ci[c];
            #pragma unroll
            for (int k = 2; k > 0; k--) {
                if (lv[k] > lv[k - 1]) {
                    float tv = lv[k]; lv[k] = lv[k - 1]; lv[k - 1] = tv;
                    int   tx = li[k]; li[k] = li[k - 1]; li[k - 1] = tx;
                }
            }
        }
    }

    __shared__ float sv[128]; __shared__ int si[128];
    __shared__ int topi[12];
    for (int r = 0; r < 12; r++) {
        sv[t] = lv[0]; si[t] = t;
        __syncthreads();
        #pragma unroll
        for (int o = 64; o > 0; o >>= 1) {
            if (t < o && sv[t + o] > sv[t]) { sv[t] = sv[t + o]; si[t] = si[t + o]; }
            __syncthreads();
        }
        if (t == si[0]) {
            topi[r] = li[0];
            lv[0] = lv[1]; li[0] = li[1];
            lv[1] = lv[2]; li[1] = li[2];
            lv[2] = NEG_INF;
        }
        __syncthreads();
    }

    int ti12[12];
    #pragma unroll
    for (int k = 0; k < 12; k++) ti12[k] = topi[k];

    float ehv[2];
    #pragma unroll
    for (int u = 0; u < 2; u++) ehv[u] = g_eh[(size_t)i * DH_ + t + u * 128];

    float nb12[12][2];
    #pragma unroll
    for (int k = 0; k < 12; k++)
        #pragma unroll
        for (int u = 0; u < 2; u++)
            nb12[k][u] = g_et[(size_t)ti12[k] * DH_ + t + u * 128];

    __shared__ float part[4][12];
    __shared__ float tot[12];
    int lane = t & 31, wp = t >> 5;
    #pragma unroll
    for (int k = 0; k < 12; k++) {
        float s = ehv[0] * nb12[k][0] + ehv[1] * nb12[k][1];
        s = warp_sum(s);
        if (lane == 0) part[wp][k] = s;
    }
    __syncthreads();
    if (t < 12) tot[t] = (part[0][t] + part[1][t] + part[2][t] + part[3][t]) * 0.0625f;
    __syncthreads();

    float val12[12];
    #pragma unroll
    for (int k = 0; k < 12; k++) val12[k] = tot[k];
    int sel[6];
    unsigned used = 0;
    #pragma unroll
    for (int r = 0; r < 6; r++) {
        int best = -1; float bv = NEG_INF;
        #pragma unroll
        for (int k = 0; k < 12; k++) {
            if (!(used >> k & 1) && val12[k] > bv) { bv = val12[k]; best = k; }
        }
        used |= 1u << best;
        sel[r] = best;
    }

    float tv[6];
    float nb[6][2];
    #pragma unroll
    for (int k = 0; k < 6; k++) {
        tv[k] = val12[sel[k]];
        nb[k][0] = nb12[sel[k]][0];
        nb[k][1] = nb12[sel[k]][1];
    }
    float pm = tv[0];
    #pragma unroll
    for (int k = 1; k < 6; k++) pm = fmaxf(pm, tv[k]);
    float pk[6], ps = 0.f;
    #pragma unroll
    for (int k = 0; k < 6; k++) { pk[k] = expf(tv[k] - pm); ps += pk[k]; }
    float pinv = 1.f / ps;
    #pragma unroll
    for (int k = 0; k < 6; k++) pk[k] *= pinv;

    float sN[6], sG[6];
    #pragma unroll
    for (int k = 0; k < 6; k++) { sN[k] = 0.f; sG[k] = 0.f; }
    #pragma unroll
    for (int k = 0; k < 6; k++) {
        #pragma unroll
        for (int u = 0; u < 2; u++) {
            float ehr = pk[k] * nb[k][u] + (1.f - pk[k]) * ehv[u];
            float gt  = tanhf(ehv[u] + ehr);
            sN[k] += nb[k][u];
            sG[k] += gt;
        }
    }

    __syncthreads();
    #pragma unroll
    for (int q = 0; q < 6; q++) {
        float v = warp_sum(sN[q]); if (lane == 0) part[wp][q]     = v;
        float w = warp_sum(sG[q]); if (lane == 0) part[wp][6 + q] = w;
    }
    __syncthreads();
    if (t < 12) tot[t] = part[0][t] + part[1][t] + part[2][t] + part[3][t];
    __syncthreads();

    float kw[6], km = NEG_INF;
    #pragma unroll
    for (int k = 0; k < 6; k++) { kw[k] = tot[k] * tot[6 + k]; km = fmaxf(km, kw[k]); }
    float kp[6], ks = 0.f;
    #pragma unroll
    for (int k = 0; k < 6; k++) { kp[k] = expf(kw[k] - km); ks += kp[k]; }
    float kinv = 1.f / ks;

    #pragma unroll
    for (int u = 0; u < 2; u++) {
        float eN = 0.f;
        #pragma unroll
        for (int k = 0; k < 6; k++) eN += kp[k] * kinv * nb[k][u];
        int dcol = t + u * 128;
        float e = ehv[u];
        float av = e + eN;
        float mv = e * eN;
        __nv_bfloat16 ah = __float2bfloat16(av);
        __nv_bfloat16 al = __float2bfloat16(av - __bfloat162float(ah));
        __nv_bfloat16 mh = __float2bfloat16(mv);
        __nv_bfloat16 ml = __float2bfloat16(mv - __bfloat162float(mh));
        size_t o = (size_t)i * KSP + dcol;
        g_As[o] = ah; g_As[o + 256] = ah; g_As[o + 512] = al;
        g_Ms[o] = mh; g_Ms[o + 256] = mh; g_Ms[o + 512] = ml;
    }
}

// ---------------- readout ----------------
__global__ __launch_bounds__(128)
void score_kernel(const float* __restrict__ Ag2, const float* __restrict__ bg2) {
    int i = blockIdx.x, t = threadIdx.x;
    float v = g_h[(size_t)i * 128 + t] * Ag2[t];
    v = warp_sum(v);
    __shared__ float p[4];
    if ((t & 31) == 0) p[t >> 5] = v;
    __syncthreads();
    if (t == 0) g_s[i] = p[0] + p[1] + p[2] + p[3] + bg2[0];
}

__global__ __launch_bounds__(1024)
void stat_kernel() {
    int t = threadIdx.x;
    __shared__ float sm[1024];
    float m = NEG_INF;
    for (int i = t; i < NP; i += 1024) m = fmaxf(m, g_s[i]);
    sm[t] = m; __syncthreads();
    for (int o = 512; o > 0; o >>= 1) { if (t < o) sm[t] = fmaxf(sm[t], sm[t + o]); __syncthreads(); }
    float mx = sm[0];
    __syncthreads();
    float e = 0.f;
    for (int i = t; i < NP; i += 1024) e += expf(g_s[i] - mx);
    sm[t] = e; __syncthreads();
    for (int o = 512; o > 0; o >>= 1) { if (t < o) sm[t] += sm[t + o]; __syncthreads(); }
    if (t == 0) { g_stat[0] = mx; g_stat[1] = sm[0]; }
}

__global__ __launch_bounds__(256)
void accum_kernel(const float* __restrict__ emsg, float* __restrict__ eg) {
    int t = threadIdx.x;
    int r0 = blockIdx.x * 256;
    __shared__ float w[256];
    float mx = g_stat[0], inv = 1.f / g_stat[1];
    w[t] = expf(g_s[r0 + t] - mx) * inv;
    __syncthreads();
    float acc = 0.f;
    for (int r = 0; r < 256; r++) acc += w[r] * emsg[(size_t)(r0 + r) * DH_ + t];
    atomicAdd(&eg[t], acc);
}

// ---------------- launcher ----------------
extern "C" void kernel_launch(void* const* d_in, const int* in_sizes, int n_in,
                              void* d_out, int out_size) {
    const float* x_path = (const float*)d_in[0];
    const float* fc1_W  = (const float*)d_in[1];
    const float* fc1_b  = (const float*)d_in[2];
    const float* Wh     = (const float*)d_in[3];
    const float* bh     = (const float*)d_in[4];
    const float* Wt     = (const float*)d_in[5];
    const float* bt     = (const float*)d_in[6];
    const float* W1     = (const float*)d_in[7];
    const float* b1     = (const float*)d_in[8];
    const float* W2     = (const float*)d_in[9];
    const float* b2     = (const float*)d_in[10];
    const float* Ag1    = (const float*)d_in[11];
    const float* bg1    = (const float*)d_in[12];
    const float* Ag2    = (const float*)d_in[13];
    const float* bg2    = (const float*)d_in[14];

    float* out    = (float*)d_out;               // e_msg: 8192 x 256
    float* out_eg = out + (size_t)NP * DH_;      // e_g: 256

    void *px, *ph, *pPs, *pXs, *pAs, *pMs, *pEs;
    void *pWfc1, *pWcat, *pW1s, *pW2s, *pAg1s, *pbcat;
    cudaGetSymbolAddress(&px,  g_x);
    cudaGetSymbolAddress(&ph,  g_h);
    cudaGetSymbolAddress(&pPs,  g_Ps);
    cudaGetSymbolAddress(&pXs,  g_Xs);
    cudaGetSymbolAddress(&pAs,  g_As);
    cudaGetSymbolAddress(&pMs,  g_Ms);
    cudaGetSymbolAddress(&pEs,  g_Es);
    cudaGetSymbolAddress(&pWfc1, g_Wfc1s);
    cudaGetSymbolAddress(&pWcat, g_Wcat);
    cudaGetSymbolAddress(&pW1s, g_W1s);
    cudaGetSymbolAddress(&pW2s, g_W2s);
    cudaGetSymbolAddress(&pAg1s, g_Ag1s);
    cudaGetSymbolAddress(&pbcat, g_bcat);

    cudaFuncSetAttribute(gemm_nt_mma, cudaFuncAttributeMaxDynamicSharedMemorySize, SMEM_NT);
    cudaFuncSetAttribute(lin_mma<true, false, 0, true>,  cudaFuncAttributeMaxDynamicSharedMemorySize, LSMEM_DYN);
    cudaFuncSetAttribute(lin_mma<true, false, 0, false>, cudaFuncAttributeMaxDynamicSharedMemorySize, LSMEM_DYN);
    cudaFuncSetAttribute(lin_mma<false, false, 3, false>,cudaFuncAttributeMaxDynamicSharedMemorySize, LSMEM_DYN);
    cudaFuncSetAttribute(lin_mma<true, true, 1, false>,  cudaFuncAttributeMaxDynamicSharedMemorySize, LSMEM_DYN);

    // 0: merged prep (weight splits + bcat + zero)
    prep_kernel<<<2177, 256>>>(fc1_W, Wh, Wt, W1, W2, Ag1, bh, bt, out_eg);
    // 1: x_path split
    splita_kernel<<<NP * (DIN_/2) / 256, 256>>>(x_path, (__nv_bfloat16*)pPs, DIN_);
    // 2: fc1 + leaky -> g_x (+fused colsum into g_mean)
    lin_mma<true, false, 0, true><<<dim3(2, 128), 256, LSMEM_DYN>>>(
        (const __nv_bfloat16*)pPs, (const __nv_bfloat16*)pWfc1, fc1_b, nullptr,
        (float*)px, nullptr, KSP_FC, DH_);
    // 3: mean-mix (+split of x)
    mix_split_kernel<<<NP * 128 / 256, 256>>>();
    // 4: merged e_h|e_t (N=512) with routed epilogue (fp32 + hi bf16)
    lin_mma<false, false, 3, false><<<dim3(4, 128), 256, LSMEM_DYN>>>(
        (const __nv_bfloat16*)pXs, (const __nv_bfloat16*)pWcat, (const float*)pbcat,
        nullptr, nullptr, nullptr, KSP, 512);
    // 5: hi-only NT GEMM (K=256, 2 mega-chunks) + fused approx top-6 per chunk
    gemm_nt_mma<<<dim3(32, 64), 256, SMEM_NT>>>();
    // 6: approx top-12 -> exact rescore -> exact top-6 -> messages
    topk_msg_kernel<<<NP, 128>>>();
    // 7-8: e_msg = leaky(a@W1+b1) + leaky(m@W2+b2) -> out (+split for Ag1)
    lin_mma<true, false, 0, false><<<dim3(2, 128), 256, LSMEM_DYN>>>(
        (const __nv_bfloat16*)pAs, (const __nv_bfloat16*)pW1s, b1, nullptr,
        out, nullptr, KSP, DH_);
    lin_mma<true, true, 1, false><<<dim3(2, 128), 256, LSMEM_DYN>>>(
        (const __nv_bfloat16*)pMs, (const __nv_bfloat16*)pW2s, b2, out,
        out, (__nv_bfloat16*)pEs, KSP, DH_);
    // 9: readout hidden
    lin_mma<true, false, 0, false><<<dim3(1, 128), 256, LSMEM_DYN>>>(
        (const __nv_bfloat16*)pEs, (const __nv_bfloat16*)pAg1s, bg1, nullptr,
        (float*)ph, nullptr, KSP, DH_/2);
    // 10-12: gated readout
    score_kernel<<<NP, 128>>>(Ag2, bg2);
    stat_kernel<<<1, 1024>>>();
    accum_kernel<<<32, 256>>>(out, out_eg);
}

// round 9
// speedup vs baseline: 2.2554x; 1.0117x over previous
#include <cuda_runtime.h>
#include <cuda_bf16.h>
#include <cuda_fp16.h>
#include <math.h>
#include <stdint.h>

#define NP   8192
#define DIN_ 1024
#define DH_  256
#define KSP  768                 // 3*DH split width (linears)
#define KSP_FC 3072              // 3*DIN split width
#define CANDS 384
#define NEG_INF (-3.402823466e38f)

// ---------------- scratch (allocation-free: __device__ globals) ----------------
__device__ float g_x [NP*DH_];
__device__ float g_eh[NP*DH_];
__device__ float g_et[NP*DH_];
__device__ __nv_bfloat16 g_Ps [(size_t)NP*KSP_FC];  // x_path split
__device__ __nv_bfloat16 g_Xs [(size_t)NP*KSP];     // mixed x split (A-side)
__device__ __half g_Ah [(size_t)NP*DH_];            // e_h fp16 (NT A operand)
__device__ __half g_Bh [(size_t)NP*DH_];            // e_t fp16 (NT B operand)
__device__ __nv_bfloat16 g_As [(size_t)NP*KSP];     // a split
__device__ __nv_bfloat16 g_Ms [(size_t)NP*KSP];     // m split
__device__ __nv_bfloat16 g_Es [(size_t)NP*KSP];     // e_msg split
__device__ __nv_bfloat16 g_Wfc1s[(size_t)DH_*KSP_FC];
__device__ __nv_bfloat16 g_Wcat [512*KSP];          // [Wh;Wt] split
__device__ __nv_bfloat16 g_W1s [DH_*KSP];
__device__ __nv_bfloat16 g_W2s [DH_*KSP];
__device__ __nv_bfloat16 g_Ag1s[(DH_/2)*KSP];
__device__ float g_bcat[512];
__device__ float g_candv[(size_t)NP*CANDS];
__device__ int   g_candi[(size_t)NP*CANDS];
__device__ float g_h [NP*(DH_/2)];
__device__ float g_mean[DH_];
__device__ float g_s[NP];
__device__ float g_stat[2];

__device__ __forceinline__ float leaky_f(float v) { return v > 0.f ? v : 0.01f * v; }

__device__ __forceinline__ float warp_sum(float v) {
    #pragma unroll
    for (int o = 16; o > 0; o >>= 1) v += __shfl_down_sync(0xffffffffu, v, o);
    return v;
}

// ---------------- PTX helpers ----------------
__device__ __forceinline__ uint32_t smem_u32(const void* p) {
    uint32_t a;
    asm("{ .reg .u64 t; cvta.to.shared.u64 t, %1; cvt.u32.u64 %0, t; }" : "=r"(a) : "l"(p));
    return a;
}
__device__ __forceinline__ void cp16(uint32_t dst, const void* src) {
    asm volatile("cp.async.cg.shared.global [%0], [%1], 16;" :: "r"(dst), "l"(src));
}
#define CP_COMMIT()  asm volatile("cp.async.commit_group;" ::: "memory")
#define CP_WAIT1()   asm volatile("cp.async.wait_group 1;" ::: "memory")
#define CP_WAIT0()   asm volatile("cp.async.wait_group 0;" ::: "memory")

__device__ __forceinline__ void ldsm_x4(uint32_t (&r)[4], uint32_t addr) {
    asm volatile("ldmatrix.sync.aligned.m8n8.x4.shared.b16 {%0,%1,%2,%3}, [%4];"
                 : "=r"(r[0]), "=r"(r[1]), "=r"(r[2]), "=r"(r[3]) : "r"(addr));
}
// bf16 inputs, fp32 accum (linears)
__device__ __forceinline__ void mma_bf16(float (&d)[4], const uint32_t (&a)[4],
                                         const uint32_t* b) {
    asm volatile("mma.sync.aligned.m16n8k16.row.col.f32.bf16.bf16.f32 "
                 "{%0,%1,%2,%3}, {%4,%5,%6,%7}, {%8,%9}, {%0,%1,%2,%3};"
                 : "+f"(d[0]), "+f"(d[1]), "+f"(d[2]), "+f"(d[3])
                 : "r"(a[0]), "r"(a[1]), "r"(a[2]), "r"(a[3]), "r"(b[0]), "r"(b[1]));
}
// fp16 inputs, fp16 accum (NT ranking GEMM — 2x issue rate)
__device__ __forceinline__ void mma_f16acc(uint32_t (&d)[2], const uint32_t (&a)[4],
                                           const uint32_t* b) {
    asm volatile("mma.sync.aligned.m16n8k16.row.col.f16.f16.f16.f16 "
                 "{%0,%1}, {%2,%3,%4,%5}, {%6,%7}, {%0,%1};"
                 : "+r"(d[0]), "+r"(d[1])
                 : "r"(a[0]), "r"(a[1]), "r"(a[2]), "r"(a[3]), "r"(b[0]), "r"(b[1]));
}

__device__ __forceinline__ void split_pair(float v0, float v1,
                                           __nv_bfloat162& hh, __nv_bfloat162& ll) {
    __nv_bfloat16 h0 = __float2bfloat16(v0), h1 = __float2bfloat16(v1);
    hh.x = h0; hh.y = h1;
    ll.x = __float2bfloat16(v0 - __bfloat162float(h0));
    ll.y = __float2bfloat16(v1 - __bfloat162float(h1));
}

// ---------------- merged prep: weight splits + bcat + zeroing ----------------
__device__ __forceinline__ void splitw_body(const float* __restrict__ W,
                                            __nv_bfloat16* __restrict__ out,
                                            int K, int N, int baseRow, int idx) {
    int k = idx / N, n = idx - k * N;
    float v = W[idx];
    __nv_bfloat16 h = __float2bfloat16(v);
    __nv_bfloat16 l = __float2bfloat16(v - __bfloat162float(h));
    size_t o = (size_t)(n + baseRow) * (3 * K);
    out[o + k]         = h;
    out[o + K + k]     = l;
    out[o + 2 * K + k] = h;
}

__global__ void prep_kernel(const float* __restrict__ fc1W,
                            const float* __restrict__ Wh, const float* __restrict__ Wt,
                            const float* __restrict__ W1, const float* __restrict__ W2,
                            const float* __restrict__ Ag1,
                            const float* __restrict__ bh, const float* __restrict__ bt,
                            float* __restrict__ eg) {
    int b = blockIdx.x, t = threadIdx.x;
    if (b < 1024)       splitw_body(fc1W, g_Wfc1s, DIN_, DH_, 0,   b * 256 + t);
    else if (b < 1280)  splitw_body(Wh,   g_Wcat,  DH_, DH_, 0,   (b - 1024) * 256 + t);
    else if (b < 1536)  splitw_body(Wt,   g_Wcat,  DH_, DH_, 256, (b - 1280) * 256 + t);
    else if (b < 1792)  splitw_body(W1,   g_W1s,   DH_, DH_, 0,   (b - 1536) * 256 + t);
    else if (b < 2048)  splitw_body(W2,   g_W2s,   DH_, DH_, 0,   (b - 1792) * 256 + t);
    else if (b < 2176)  splitw_body(Ag1,  g_Ag1s,  DH_, DH_/2, 0, (b - 2048) * 256 + t);
    else if (b < 2208)  g_s[(b - 2176) * 256 + t] = 0.f;
    else {
        g_mean[t] = 0.f;
        eg[t] = 0.f;
        g_bcat[t] = bh[t];
        g_bcat[256 + t] = bt[t];
    }
}

// ---------------- A split: x_path (M x 1024 fp32) -> (M x 3072 bf16) [h|h|l] ----------------
__global__ __launch_bounds__(256)
void splita_kernel(const float* __restrict__ A, __nv_bfloat16* __restrict__ out, int K) {
    int idx = blockIdx.x * 256 + threadIdx.x;
    int half = K >> 1;
    int row = idx / half, c2 = idx - row * half;
    int col = c2 * 2;
    float2 v = *(const float2*)(A + (size_t)row * K + col);
    __nv_bfloat162 hh, ll;
    split_pair(v.x, v.y, hh, ll);
    size_t o = (size_t)row * (3 * K) + col;
    *(__nv_bfloat162*)&out[o]         = hh;
    *(__nv_bfloat162*)&out[o + K]     = hh;
    *(__nv_bfloat162*)&out[o + 2 * K] = ll;
}

// ---------------- mean mix (+fused split of x) ----------------
__global__ __launch_bounds__(256)
void mix_split_kernel() {
    int idx = blockIdx.x * 256 + threadIdx.x;
    int row = idx >> 7, c2 = idx & 127;
    int col = c2 * 2;
    float2 v = *(const float2*)(g_x + (size_t)row * DH_ + col);
    float x0 = (v.x + g_mean[col]     * (1.f / (float)NP)) * 0.5f;
    float x1 = (v.y + g_mean[col + 1] * (1.f / (float)NP)) * 0.5f;
    __nv_bfloat162 hh, ll;
    split_pair(x0, x1, hh, ll);
    size_t o = (size_t)row * KSP + col;
    *(__nv_bfloat162*)&g_Xs[o]       = hh;
    *(__nv_bfloat162*)&g_Xs[o + 256] = hh;
    *(__nv_bfloat162*)&g_Xs[o + 512] = ll;
}

// ---------------- generic mma.sync linear (BK=128 elems, 2-stage, occ 2) ----------------
// SPLIT: 0 none, 1 A-side split out, 3 ehet routing, 4 fused score (atomic dot with aux).
// COLSUM: accumulate column sums of output into g_mean (fc1 path).
#define L_AST   17408                    // 64*272
#define L_STAGE 52224                    // + 128*272
#define LSMEM_DYN (2 * L_STAGE + 512)

template<bool LEAKY, bool ADD, int SPLIT, bool COLSUM>
__global__ __launch_bounds__(256, 2)
void lin_mma(const __nv_bfloat16* __restrict__ A, const __nv_bfloat16* __restrict__ Bw,
             const float* __restrict__ bias, const float* __restrict__ Cin,
             float* __restrict__ C, __nv_bfloat16* __restrict__ S,
             const float* __restrict__ aux,
             int Kp, int N)
{
    extern __shared__ char smem[];
    const int tid = threadIdx.x;
    const int lane = tid & 31, wid = tid >> 5;
    const int wr = wid >> 2, wc = wid & 3;
    const int bx = blockIdx.x, by = blockIdx.y;
    uint32_t sb = smem_u32(smem);
    float* colacc = (float*)(smem + 2 * L_STAGE);
    if (COLSUM && tid < 128) colacc[tid] = 0.f;
    const int Kb = Kp * 2;
    const char* Abase = ((const char*)A)  + (size_t)(by * 64)  * Kb;
    const char* Bbase = ((const char*)Bw) + (size_t)(bx * 128) * Kb;
    const int nch = Kp / 128;            // 128-elem (256 B) chunks

    auto load_chunk = [&](int c, int s) {
        uint32_t aSt = sb + s * L_STAGE;
        uint32_t bSt = aSt + L_AST;
        int coff = c * 256;
        int r = tid >> 4, cc = tid & 15;
        #pragma unroll
        for (int j = 0; j < 4; j++) {
            int rr = r + j * 16;
            cp16(aSt + rr * 272 + cc * 16, Abase + (size_t)rr * Kb + coff + cc * 16);
        }
        #pragma unroll
        for (int j = 0; j < 8; j++) {
            int rr = r + j * 16;
            cp16(bSt + rr * 272 + cc * 16, Bbase + (size_t)rr * Kb + coff + cc * 16);
        }
    };

    float d[2][4][4];
    #pragma unroll
    for (int mf = 0; mf < 2; mf++)
        #pragma unroll
        for (int nf = 0; nf < 4; nf++)
            #pragma unroll
            for (int q = 0; q < 4; q++) d[mf][nf][q] = 0.f;

    load_chunk(0, 0); CP_COMMIT();
    if (nch > 1) load_chunk(1, 1);
    CP_COMMIT();

    const int arow_j = ((lane >> 3) & 1) * 8 + (lane & 7);
    const int akb    = (lane >> 4) * 16;
    const int bj     = lane >> 3;
    const int bn_off = (bj >> 1) * 8 + (lane & 7);
    const int bkb    = (bj & 1) * 16;

    for (int c = 0; c < nch; c++) {
        CP_WAIT1();
        __syncthreads();
        uint32_t aSt = sb + (c & 1) * L_STAGE;
        uint32_t bSt = aSt + L_AST;

        #pragma unroll
        for (int ks = 0; ks < 8; ks++) {
            uint32_t a[2][4], b[4][2];
            #pragma unroll
            for (int mf = 0; mf < 2; mf++) {
                int row = wr * 32 + mf * 16 + arow_j;
                ldsm_x4(a[mf], aSt + row * 272 + ks * 32 + akb);
            }
            {
                uint32_t bv[4];
                int row0 = wc * 32 + bn_off;
                ldsm_x4(bv, bSt + row0 * 272 + ks * 32 + bkb);
                b[0][0] = bv[0]; b[0][1] = bv[1]; b[1][0] = bv[2]; b[1][1] = bv[3];
                int row1 = row0 + 16;
                ldsm_x4(bv, bSt + row1 * 272 + ks * 32 + bkb);
                b[2][0] = bv[0]; b[2][1] = bv[1]; b[3][0] = bv[2]; b[3][1] = bv[3];
            }
            #pragma unroll
            for (int mf = 0; mf < 2; mf++)
                #pragma unroll
                for (int nf = 0; nf < 4; nf++)
                    mma_bf16(d[mf][nf], a[mf], b[nf]);
        }
        __syncthreads();
        if (c + 2 < nch) load_chunk(c + 2, c & 1);
        CP_COMMIT();
    }

    // ---- epilogue ----
    const int g = lane >> 2, tq = lane & 3;
    auto emit = [&](int r, int c, float v0, float v1) {
        v0 += bias[c]; v1 += bias[c + 1];
        if (SPLIT == 3) {
            __half2 hh = __floats2half2_rn(v0, v1);
            if (c < 256) {
                g_eh[(size_t)r * DH_ + c]     = v0;
                g_eh[(size_t)r * DH_ + c + 1] = v1;
                *(__half2*)&g_Ah[(size_t)r * DH_ + c] = hh;
            } else {
                int c2 = c - 256;
                g_et[(size_t)r * DH_ + c2]     = v0;
                g_et[(size_t)r * DH_ + c2 + 1] = v1;
                *(__half2*)&g_Bh[(size_t)r * DH_ + c2] = hh;
            }
            return;
        }
        if (LEAKY) { v0 = leaky_f(v0); v1 = leaky_f(v1); }
        if (ADD)   { v0 += Cin[(size_t)r * N + c]; v1 += Cin[(size_t)r * N + c + 1]; }
        if (SPLIT == 4) {
            atomicAdd(&g_s[r], v0 * aux[c] + v1 * aux[c + 1]);
            return;
        }
        C[(size_t)r * N + c]     = v0;
        C[(size_t)r * N + c + 1] = v1;
        if (COLSUM) {
            int cl = c - bx * 128;
            atomicAdd(&colacc[cl], v0);
            atomicAdd(&colacc[cl + 1], v1);
        }
        if (SPLIT == 1) {
            __nv_bfloat162 hh, ll;
            split_pair(v0, v1, hh, ll);
            size_t o = (size_t)r * KSP + c;
            *(__nv_bfloat162*)&S[o]       = hh;
            *(__nv_bfloat162*)&S[o + 256] = hh;
            *(__nv_bfloat162*)&S[o + 512] = ll;
        }
    };
    #pragma unroll
    for (int mf = 0; mf < 2; mf++) {
        #pragma unroll
        for (int nf = 0; nf < 4; nf++) {
            int row = by * 64 + wr * 32 + mf * 16 + g;
            int col = bx * 128 + wc * 32 + nf * 8 + tq * 2;
            emit(row,     col, d[mf][nf][0], d[mf][nf][1]);
            emit(row + 8, col, d[mf][nf][2], d[mf][nf][3]);
        }
    }
    if (COLSUM) {
        __syncthreads();
        if (tid < 128) atomicAdd(&g_mean[bx * 128 + tid], colacc[tid]);
    }
}

// ---------------- NT GEMM (fp16 in / fp16 accum, K=256): ranking logits + top-6 ----------------
#define NT_AST   34816                   // 128*272
#define NT_STAGE 104448                  // + 256*272
#define SMEM_NT  208896                  // 2 stages (epilogue 128*259*4 fits)

__global__ __launch_bounds__(256, 1)
void gemm_nt_mma() {
    extern __shared__ char smem[];
    const int tid = threadIdx.x;
    const int wid = tid >> 5, lane = tid & 31;
    const int wr = wid >> 2, wc = wid & 3;     // 2 x 4 warps, 64x64 each
    const int bx = blockIdx.x, by = blockIdx.y;
    uint32_t sb = smem_u32(smem);
    const int Kb = DH_ * 2;
    const char* Abase = ((const char*)g_Ah) + (size_t)(by * 128) * Kb;
    const char* Bbase = ((const char*)g_Bh) + (size_t)(bx * 256) * Kb;

    auto load_chunk = [&](int c, int s) {
        uint32_t aSt = sb + s * NT_STAGE;
        uint32_t bSt = aSt + NT_AST;
        int coff = c * 256;
        int r = tid >> 4, cc = tid & 15;
        #pragma unroll
        for (int j = 0; j < 8; j++) {
            int rr = r + j * 16;
            cp16(aSt + rr * 272 + cc * 16, Abase + (size_t)rr * Kb + coff + cc * 16);
        }
        #pragma unroll
        for (int j = 0; j < 16; j++) {
            int rr = r + j * 16;
            cp16(bSt + rr * 272 + cc * 16, Bbase + (size_t)rr * Kb + coff + cc * 16);
        }
    };

    uint32_t d2[4][8][2];
    #pragma unroll
    for (int mf = 0; mf < 4; mf++)
        #pragma unroll
        for (int nf = 0; nf < 8; nf++) { d2[mf][nf][0] = 0u; d2[mf][nf][1] = 0u; }

    load_chunk(0, 0); CP_COMMIT();
    load_chunk(1, 1); CP_COMMIT();

    const int arow_j = ((lane >> 3) & 1) * 8 + (lane & 7);
    const int akb    = (lane >> 4) * 16;
    const int bj     = lane >> 3;
    const int bn_off = (bj >> 1) * 8 + (lane & 7);
    const int bkb    = (bj & 1) * 16;

    #pragma unroll
    for (int c = 0; c < 2; c++) {
        if (c == 0) CP_WAIT1(); else CP_WAIT0();
        __syncthreads();
        uint32_t aSt = sb + c * NT_STAGE;
        uint32_t bSt = aSt + NT_AST;

        #pragma unroll
        for (int ks = 0; ks < 8; ks++) {
            uint32_t a[4][4], b[8][2];
            #pragma unroll
            for (int mf = 0; mf < 4; mf++) {
                int row = wr * 64 + mf * 16 + arow_j;
                ldsm_x4(a[mf], aSt + row * 272 + ks * 32 + akb);
            }
            #pragma unroll
            for (int nb = 0; nb < 4; nb++) {
                uint32_t bv[4];
                int row = wc * 64 + nb * 16 + bn_off;
                ldsm_x4(bv, bSt + row * 272 + ks * 32 + bkb);
                b[nb*2][0]   = bv[0]; b[nb*2][1]   = bv[1];
                b[nb*2+1][0] = bv[2]; b[nb*2+1][1] = bv[3];
            }
            #pragma unroll
            for (int mf = 0; mf < 4; mf++)
                #pragma unroll
                for (int nf = 0; nf < 8; nf++)
                    mma_f16acc(d2[mf][nf], a[mf], b[nf]);
        }
    }

    // ---- epilogue: unpack fp16 accums -> smem [128][259], per-(row, chunk) top-6 ----
    float* sE = (float*)smem;
    __syncthreads();
    const int g = lane >> 2, tq = lane & 3;
    #pragma unroll
    for (int mf = 0; mf < 4; mf++) {
        int r0 = wr * 64 + mf * 16 + g;
        #pragma unroll
        for (int nf = 0; nf < 8; nf++) {
            int cc = wc * 64 + nf * 8 + tq * 2;
            __half2 p0 = *(__half2*)&d2[mf][nf][0];
            __half2 p1 = *(__half2*)&d2[mf][nf][1];
            sE[r0 * 259 + cc]           = __low2float(p0);
            sE[r0 * 259 + cc + 1]       = __high2float(p0);
            sE[(r0 + 8) * 259 + cc]     = __low2float(p1);
            sE[(r0 + 8) * 259 + cc + 1] = __high2float(p1);
        }
    }
    __syncthreads();
    {
        int row = tid & 127, ch = tid >> 7;
        float v[6]; int ix[6];
        #pragma unroll
        for (int k = 0; k < 6; k++) { v[k] = NEG_INF; ix[k] = 0; }
        int cb = bx * 256 + ch * 128;
        const float* rp = sE + row * 259 + ch * 128;
        for (int j = 0; j < 128; j++) {
            float val = rp[j] * 0.0625f;
            if (val > v[5]) {
                v[5] = val; ix[5] = cb + j;
                #pragma unroll
                for (int k = 5; k > 0; k--) {
                    if (v[k] > v[k - 1]) {
                        float tv = v[k]; v[k] = v[k - 1]; v[k - 1] = tv;
                        int   ti = ix[k]; ix[k] = ix[k - 1]; ix[k - 1] = ti;
                    }
                }
            }
        }
        size_t rg = (size_t)by * 128 + row;
        size_t o = rg * CANDS + bx * 12 + ch * 6;
        #pragma unroll
        for (int k = 0; k < 6; k++) { g_candv[o + k] = v[k]; g_candi[o + k] = ix[k]; }
    }
}

// ---------------- topk: approx top-12 -> exact rescore -> exact top-6 -> messages ----------------
__global__ __launch_bounds__(128)
void topk_msg_kernel() {
    int i = blockIdx.x;
    int t = threadIdx.x;
    const float* cv = g_candv + (size_t)i * CANDS;
    const int*   ci = g_candi + (size_t)i * CANDS;

    float lv[3]; int li[3];
    #pragma unroll
    for (int k = 0; k < 3; k++) { lv[k] = NEG_INF; li[k] = 0; }
    #pragma unroll
    for (int j = 0; j < 3; j++) {
        int c = t + j * 128;
        float v = cv[c];
        if (v > lv[2]) {
            lv[2] = v; li[2] = ci[c];
            #pragma unroll
            for (int k = 2; k > 0; k--) {
                if (lv[k] > lv[k - 1]) {
                    float tv = lv[k]; lv[k] = lv[k - 1]; lv[k - 1] = tv;
                    int   tx = li[k]; li[k] = li[k - 1]; li[k - 1] = tx;
                }
            }
        }
    }

    __shared__ float sv[128]; __shared__ int si[128];
    __shared__ int topi[12];
    for (int r = 0; r < 12; r++) {
        sv[t] = lv[0]; si[t] = t;
        __syncthreads();
        #pragma unroll
        for (int o = 64; o > 0; o >>= 1) {
            if (t < o && sv[t + o] > sv[t]) { sv[t] = sv[t + o]; si[t] = si[t + o]; }
            __syncthreads();
        }
        if (t == si[0]) {
            topi[r] = li[0];
            lv[0] = lv[1]; li[0] = li[1];
            lv[1] = lv[2]; li[1] = li[2];
            lv[2] = NEG_INF;
        }
        __syncthreads();
    }

    int ti12[12];
    #pragma unroll
    for (int k = 0; k < 12; k++) ti12[k] = topi[k];

    float ehv[2];
    #pragma unroll
    for (int u = 0; u < 2; u++) ehv[u] = g_eh[(size_t)i * DH_ + t + u * 128];

    float nb12[12][2];
    #pragma unroll
    for (int k = 0; k < 12; k++)
        #pragma unroll
        for (int u = 0; u < 2; u++)
            nb12[k][u] = g_et[(size_t)ti12[k] * DH_ + t + u * 128];

    __shared__ float part[4][12];
    __shared__ float tot[12];
    int lane = t & 31, wp = t >> 5;
    #pragma unroll
    for (int k = 0; k < 12; k++) {
        float s = ehv[0] * nb12[k][0] + ehv[1] * nb12[k][1];
        s = warp_sum(s);
        if (lane == 0) part[wp][k] = s;
    }
    __syncthreads();
    if (t < 12) tot[t] = (part[0][t] + part[1][t] + part[2][t] + part[3][t]) * 0.0625f;
    __syncthreads();

    float val12[12];
    #pragma unroll
    for (int k = 0; k < 12; k++) val12[k] = tot[k];
    int sel[6];
    unsigned used = 0;
    #pragma unroll
    for (int r = 0; r < 6; r++) {
        int best = -1; float bv = NEG_INF;
        #pragma unroll
        for (int k = 0; k < 12; k++) {
            if (!(used >> k & 1) && val12[k] > bv) { bv = val12[k]; best = k; }
        }
        used |= 1u << best;
        sel[r] = best;
    }

    float tv[6];
    float nb[6][2];
    #pragma unroll
    for (int k = 0; k < 6; k++) {
        tv[k] = val12[sel[k]];
        nb[k][0] = nb12[sel[k]][0];
        nb[k][1] = nb12[sel[k]][1];
    }
    float pm = tv[0];
    #pragma unroll
    for (int k = 1; k < 6; k++) pm = fmaxf(pm, tv[k]);
    float pk[6], ps = 0.f;
    #pragma unroll
    for (int k = 0; k < 6; k++) { pk[k] = expf(tv[k] - pm); ps += pk[k]; }
    float pinv = 1.f / ps;
    #pragma unroll
    for (int k = 0; k < 6; k++) pk[k] *= pinv;

    float sN[6], sG[6];
    #pragma unroll
    for (int k = 0; k < 6; k++) { sN[k] = 0.f; sG[k] = 0.f; }
    #pragma unroll
    for (int k = 0; k < 6; k++) {
        #pragma unroll
        for (int u = 0; u < 2; u++) {
            float ehr = pk[k] * nb[k][u] + (1.f - pk[k]) * ehv[u];
            float gt  = tanhf(ehv[u] + ehr);
            sN[k] += nb[k][u];
            sG[k] += gt;
        }
    }

    __syncthreads();
    #pragma unroll
    for (int q = 0; q < 6; q++) {
        float v = warp_sum(sN[q]); if (lane == 0) part[wp][q]     = v;
        float w = warp_sum(sG[q]); if (lane == 0) part[wp][6 + q] = w;
    }
    __syncthreads();
    if (t < 12) tot[t] = part[0][t] + part[1][t] + part[2][t] + part[3][t];
    __syncthreads();

    float kw[6], km = NEG_INF;
    #pragma unroll
    for (int k = 0; k < 6; k++) { kw[k] = tot[k] * tot[6 + k]; km = fmaxf(km, kw[k]); }
    float kp[6], ks = 0.f;
    #pragma unroll
    for (int k = 0; k < 6; k++) { kp[k] = expf(kw[k] - km); ks += kp[k]; }
    float kinv = 1.f / ks;

    #pragma unroll
    for (int u = 0; u < 2; u++) {
        float eN = 0.f;
        #pragma unroll
        for (int k = 0; k < 6; k++) eN += kp[k] * kinv * nb[k][u];
        int dcol = t + u * 128;
        float e = ehv[u];
        float av = e + eN;
        float mv = e * eN;
        __nv_bfloat16 ah = __float2bfloat16(av);
        __nv_bfloat16 al = __float2bfloat16(av - __bfloat162float(ah));
        __nv_bfloat16 mh = __float2bfloat16(mv);
        __nv_bfloat16 ml = __float2bfloat16(mv - __bfloat162float(mh));
        size_t o = (size_t)i * KSP + dcol;
        g_As[o] = ah; g_As[o + 256] = ah; g_As[o + 512] = al;
        g_Ms[o] = mh; g_Ms[o + 256] = mh; g_Ms[o + 512] = ml;
    }
}

// ---------------- readout: softmax stats + weighted accumulate ----------------
__global__ __launch_bounds__(1024)
void stat_kernel() {
    int t = threadIdx.x;
    __shared__ float sm[1024];
    float m = NEG_INF;
    for (int i = t; i < NP; i += 1024) m = fmaxf(m, g_s[i]);
    sm[t] = m; __syncthreads();
    for (int o = 512; o > 0; o >>= 1) { if (t < o) sm[t] = fmaxf(sm[t], sm[t + o]); __syncthreads(); }
    float mx = sm[0];
    __syncthreads();
    float e = 0.f;
    for (int i = t; i < NP; i += 1024) e += expf(g_s[i] - mx);
    sm[t] = e; __syncthreads();
    for (int o = 512; o > 0; o >>= 1) { if (t < o) sm[t] += sm[t + o]; __syncthreads(); }
    if (t == 0) { g_stat[0] = mx; g_stat[1] = sm[0]; }
}

__global__ __launch_bounds__(256)
void accum_kernel(const float* __restrict__ emsg, float* __restrict__ eg) {
    int t = threadIdx.x;
    int r0 = blockIdx.x * 256;
    __shared__ float w[256];
    float mx = g_stat[0], inv = 1.f / g_stat[1];
    w[t] = expf(g_s[r0 + t] - mx) * inv;
    __syncthreads();
    float acc = 0.f;
    for (int r = 0; r < 256; r++) acc += w[r] * emsg[(size_t)(r0 + r) * DH_ + t];
    atomicAdd(&eg[t], acc);
}

// ---------------- launcher ----------------
extern "C" void kernel_launch(void* const* d_in, const int* in_sizes, int n_in,
                              void* d_out, int out_size) {
    const float* x_path = (const float*)d_in[0];
    const float* fc1_W  = (const float*)d_in[1];
    const float* fc1_b  = (const float*)d_in[2];
    const float* Wh     = (const float*)d_in[3];
    const float* bh     = (const float*)d_in[4];
    const float* Wt     = (const float*)d_in[5];
    const float* bt     = (const float*)d_in[6];
    const float* W1     = (const float*)d_in[7];
    const float* b1     = (const float*)d_in[8];
    const float* W2     = (const float*)d_in[9];
    const float* b2     = (const float*)d_in[10];
    const float* Ag1    = (const float*)d_in[11];
    const float* bg1    = (const float*)d_in[12];
    const float* Ag2    = (const float*)d_in[13];
    // bg2 (d_in[14]) is unused: softmax over scores is shift-invariant.

    float* out    = (float*)d_out;               // e_msg: 8192 x 256
    float* out_eg = out + (size_t)NP * DH_;      // e_g: 256

    void *px, *ph, *pPs, *pXs, *pAs, *pMs, *pEs;
    void *pWfc1, *pWcat, *pW1s, *pW2s, *pAg1s, *pbcat;
    cudaGetSymbolAddress(&px,  g_x);
    cudaGetSymbolAddress(&ph,  g_h);
    cudaGetSymbolAddress(&pPs,  g_Ps);
    cudaGetSymbolAddress(&pXs,  g_Xs);
    cudaGetSymbolAddress(&pAs,  g_As);
    cudaGetSymbolAddress(&pMs,  g_Ms);
    cudaGetSymbolAddress(&pEs,  g_Es);
    cudaGetSymbolAddress(&pWfc1, g_Wfc1s);
    cudaGetSymbolAddress(&pWcat, g_Wcat);
    cudaGetSymbolAddress(&pW1s, g_W1s);
    cudaGetSymbolAddress(&pW2s, g_W2s);
    cudaGetSymbolAddress(&pAg1s, g_Ag1s);
    cudaGetSymbolAddress(&pbcat, g_bcat);

    cudaFuncSetAttribute(gemm_nt_mma, cudaFuncAttributeMaxDynamicSharedMemorySize, SMEM_NT);
    cudaFuncSetAttribute(lin_mma<true, false, 0, true>,  cudaFuncAttributeMaxDynamicSharedMemorySize, LSMEM_DYN);
    cudaFuncSetAttribute(lin_mma<true, false, 0, false>, cudaFuncAttributeMaxDynamicSharedMemorySize, LSMEM_DYN);
    cudaFuncSetAttribute(lin_mma<false, false, 3, false>,cudaFuncAttributeMaxDynamicSharedMemorySize, LSMEM_DYN);
    cudaFuncSetAttribute(lin_mma<true, true, 1, false>,  cudaFuncAttributeMaxDynamicSharedMemorySize, LSMEM_DYN);
    cudaFuncSetAttribute(lin_mma<true, false, 4, false>, cudaFuncAttributeMaxDynamicSharedMemorySize, LSMEM_DYN);

    // 0: merged prep (weight splits + bcat + zero eg/mean/scores)
    prep_kernel<<<2209, 256>>>(fc1_W, Wh, Wt, W1, W2, Ag1, bh, bt, out_eg);
    // 1: x_path split
    splita_kernel<<<NP * (DIN_/2) / 256, 256>>>(x_path, (__nv_bfloat16*)pPs, DIN_);
    // 2: fc1 + leaky -> g_x (+fused colsum into g_mean)
    lin_mma<true, false, 0, true><<<dim3(2, 128), 256, LSMEM_DYN>>>(
        (const __nv_bfloat16*)pPs, (const __nv_bfloat16*)pWfc1, fc1_b, nullptr,
        (float*)px, nullptr, nullptr, KSP_FC, DH_);
    // 3: mean-mix (+split of x)
    mix_split_kernel<<<NP * 128 / 256, 256>>>();
    // 4: merged e_h|e_t (N=512) with routed epilogue (fp32 + fp16 operands)
    lin_mma<false, false, 3, false><<<dim3(4, 128), 256, LSMEM_DYN>>>(
        (const __nv_bfloat16*)pXs, (const __nv_bfloat16*)pWcat, (const float*)pbcat,
        nullptr, nullptr, nullptr, nullptr, KSP, 512);
    // 5: fp16-accum NT ranking GEMM + fused approx top-6 per chunk
    gemm_nt_mma<<<dim3(32, 64), 256, SMEM_NT>>>();
    // 6: approx top-12 -> exact rescore -> exact top-6 -> messages
    topk_msg_kernel<<<NP, 128>>>();
    // 7-8: e_msg = leaky(a@W1+b1) + leaky(m@W2+b2) -> out (+split for Ag1)
    lin_mma<true, false, 0, false><<<dim3(2, 128), 256, LSMEM_DYN>>>(
        (const __nv_bfloat16*)pAs, (const __nv_bfloat16*)pW1s, b1, nullptr,
        out, nullptr, nullptr, KSP, DH_);
    lin_mma<true, true, 1, false><<<dim3(2, 128), 256, LSMEM_DYN>>>(
        (const __nv_bfloat16*)pMs, (const __nv_bfloat16*)pW2s, b2, out,
        out, (__nv_bfloat16*)pEs, nullptr, KSP, DH_);
    // 9: readout hidden + fused score (s_i = leaky(e_msg@Ag1+bg1) . Ag2)
    lin_mma<true, false, 4, false><<<dim3(1, 128), 256, LSMEM_DYN>>>(
        (const __nv_bfloat16*)pEs, (const __nv_bfloat16*)pAg1s, bg1, nullptr,
        (float*)ph, nullptr, Ag2, KSP, DH_/2);
    // 10-11: softmax stats + gated readout
    stat_kernel<<<1, 1024>>>();
    accum_kernel<<<32, 256>>>(out, out_eg);
}

// round 10
// speedup vs baseline: 2.4463x; 1.0846x over previous
#include <cuda_runtime.h>
#include <cuda_bf16.h>
#include <cuda_fp16.h>
#include <math.h>
#include <stdint.h>

#define NP   8192
#define DIN_ 1024
#define DH_  256
#define CANDS 384
#define NEG_INF (-3.402823466e38f)

// ---------------- scratch (allocation-free: __device__ globals) ----------------
__device__ float g_x [NP*DH_];
__device__ float g_eh[NP*DH_];
__device__ float g_et[NP*DH_];
__device__ __nv_bfloat16 g_Ps [(size_t)NP*2048];    // x_path split [h|l]
__device__ __nv_bfloat16 g_Xs [(size_t)NP*512];     // mixed x split [h|l]
__device__ __half g_Ah [(size_t)NP*DH_];            // e_h fp16 (NT A)
__device__ __half g_Bh [(size_t)NP*DH_];            // e_t fp16 (NT B)
__device__ __nv_bfloat16 g_As [(size_t)NP*512];     // a split [h|l]
__device__ __nv_bfloat16 g_Ms [(size_t)NP*512];     // m split [h|l]
__device__ __nv_bfloat16 g_Es [(size_t)NP*512];     // e_msg split [h|l]
__device__ __nv_bfloat16 g_Wfc1s[(size_t)DH_*2048]; // fc1 W [h|l]
__device__ __nv_bfloat16 g_Wcat [512*512];          // [Wh;Wt] [h|l]
__device__ __nv_bfloat16 g_W1s [DH_*512];
__device__ __nv_bfloat16 g_W2s [DH_*512];
__device__ __nv_bfloat16 g_Ag1s[(DH_/2)*512];
__device__ float g_bcat[512];
__device__ float g_candv[(size_t)NP*CANDS];
__device__ int   g_candi[(size_t)NP*CANDS];
__device__ float g_h [NP*(DH_/2)];
__device__ float g_mean[DH_];
__device__ float g_s[NP];
__device__ float g_stat[2];

__device__ __forceinline__ float leaky_f(float v) { return v > 0.f ? v : 0.01f * v; }

__device__ __forceinline__ float warp_sum(float v) {
    #pragma unroll
    for (int o = 16; o > 0; o >>= 1) v += __shfl_down_sync(0xffffffffu, v, o);
    return v;
}

// ---------------- PTX helpers ----------------
__device__ __forceinline__ uint32_t smem_u32(const void* p) {
    uint32_t a;
    asm("{ .reg .u64 t; cvta.to.shared.u64 t, %1; cvt.u32.u64 %0, t; }" : "=r"(a) : "l"(p));
    return a;
}
__device__ __forceinline__ void cp16(uint32_t dst, const void* src) {
    asm volatile("cp.async.cg.shared.global [%0], [%1], 16;" :: "r"(dst), "l"(src));
}
#define CP_COMMIT()  asm volatile("cp.async.commit_group;" ::: "memory")
#define CP_WAIT1()   asm volatile("cp.async.wait_group 1;" ::: "memory")
#define CP_WAIT0()   asm volatile("cp.async.wait_group 0;" ::: "memory")

__device__ __forceinline__ void ldsm_x4(uint32_t (&r)[4], uint32_t addr) {
    asm volatile("ldmatrix.sync.aligned.m8n8.x4.shared.b16 {%0,%1,%2,%3}, [%4];"
                 : "=r"(r[0]), "=r"(r[1]), "=r"(r[2]), "=r"(r[3]) : "r"(addr));
}
__device__ __forceinline__ void mma_bf16(float (&d)[4], const uint32_t (&a)[4],
                                         const uint32_t* b) {
    asm volatile("mma.sync.aligned.m16n8k16.row.col.f32.bf16.bf16.f32 "
                 "{%0,%1,%2,%3}, {%4,%5,%6,%7}, {%8,%9}, {%0,%1,%2,%3};"
                 : "+f"(d[0]), "+f"(d[1]), "+f"(d[2]), "+f"(d[3])
                 : "r"(a[0]), "r"(a[1]), "r"(a[2]), "r"(a[3]), "r"(b[0]), "r"(b[1]));
}
__device__ __forceinline__ void mma_f16acc(uint32_t (&d)[2], const uint32_t (&a)[4],
                                           const uint32_t* b) {
    asm volatile("mma.sync.aligned.m16n8k16.row.col.f16.f16.f16.f16 "
                 "{%0,%1}, {%2,%3,%4,%5}, {%6,%7}, {%0,%1};"
                 : "+r"(d[0]), "+r"(d[1])
                 : "r"(a[0]), "r"(a[1]), "r"(a[2]), "r"(a[3]), "r"(b[0]), "r"(b[1]));
}

__device__ __forceinline__ void split_pair(float v0, float v1,
                                           __nv_bfloat162& hh, __nv_bfloat162& ll) {
    __nv_bfloat16 h0 = __float2bfloat16(v0), h1 = __float2bfloat16(v1);
    hh.x = h0; hh.y = h1;
    ll.x = __float2bfloat16(v0 - __bfloat162float(h0));
    ll.y = __float2bfloat16(v1 - __bfloat162float(h1));
}

// ---------------- merged prep: weight splits [h|l] + bcat + zeroing ----------------
__device__ __forceinline__ void splitw_body(const float* __restrict__ W,
                                            __nv_bfloat16* __restrict__ out,
                                            int K, int N, int baseRow, int idx) {
    int k = idx / N, n = idx - k * N;
    float v = W[idx];
    __nv_bfloat16 h = __float2bfloat16(v);
    __nv_bfloat16 l = __float2bfloat16(v - __bfloat162float(h));
    size_t o = (size_t)(n + baseRow) * (2 * K);
    out[o + k]     = h;
    out[o + K + k] = l;
}

__global__ void prep_kernel(const float* __restrict__ fc1W,
                            const float* __restrict__ Wh, const float* __restrict__ Wt,
                            const float* __restrict__ W1, const float* __restrict__ W2,
                            const float* __restrict__ Ag1,
                            const float* __restrict__ bh, const float* __restrict__ bt,
                            float* __restrict__ eg) {
    int b = blockIdx.x, t = threadIdx.x;
    if (b < 1024)       splitw_body(fc1W, g_Wfc1s, DIN_, DH_, 0,   b * 256 + t);
    else if (b < 1280)  splitw_body(Wh,   g_Wcat,  DH_, DH_, 0,   (b - 1024) * 256 + t);
    else if (b < 1536)  splitw_body(Wt,   g_Wcat,  DH_, DH_, 256, (b - 1280) * 256 + t);
    else if (b < 1792)  splitw_body(W1,   g_W1s,   DH_, DH_, 0,   (b - 1536) * 256 + t);
    else if (b < 2048)  splitw_body(W2,   g_W2s,   DH_, DH_, 0,   (b - 1792) * 256 + t);
    else if (b < 2176)  splitw_body(Ag1,  g_Ag1s,  DH_, DH_/2, 0, (b - 2048) * 256 + t);
    else if (b < 2208)  g_s[(b - 2176) * 256 + t] = 0.f;
    else {
        g_mean[t] = 0.f;
        eg[t] = 0.f;
        g_bcat[t] = bh[t];
        g_bcat[256 + t] = bt[t];
    }
}

// ---------------- A split: x_path (M x 1024 fp32) -> (M x 2048 bf16) [h|l] ----------------
__global__ __launch_bounds__(256)
void splita_kernel(const float* __restrict__ A, __nv_bfloat16* __restrict__ out, int K) {
    int idx = blockIdx.x * 256 + threadIdx.x;
    int half = K >> 1;
    int row = idx / half, c2 = idx - row * half;
    int col = c2 * 2;
    float2 v = *(const float2*)(A + (size_t)row * K + col);
    __nv_bfloat162 hh, ll;
    split_pair(v.x, v.y, hh, ll);
    size_t o = (size_t)row * (2 * K) + col;
    *(__nv_bfloat162*)&out[o]     = hh;
    *(__nv_bfloat162*)&out[o + K] = ll;
}

// ---------------- mean mix (+fused [h|l] split of x) ----------------
__global__ __launch_bounds__(256)
void mix_split_kernel() {
    int idx = blockIdx.x * 256 + threadIdx.x;
    int row = idx >> 7, c2 = idx & 127;
    int col = c2 * 2;
    float2 v = *(const float2*)(g_x + (size_t)row * DH_ + col);
    float x0 = (v.x + g_mean[col]     * (1.f / (float)NP)) * 0.5f;
    float x1 = (v.y + g_mean[col + 1] * (1.f / (float)NP)) * 0.5f;
    __nv_bfloat162 hh, ll;
    split_pair(x0, x1, hh, ll);
    size_t o = (size_t)row * 512 + col;
    *(__nv_bfloat162*)&g_Xs[o]       = hh;
    *(__nv_bfloat162*)&g_Xs[o + 256] = ll;
}

// ---------------- generic mma.sync linear (BK=128, 2-stage, occ 2, chunk-remap) --------
// Logical K = 3*K0 ([h|h|l] x [h|l|h]); storage is [h|l] (2*K0), loader remaps chunks.
// KMAP: 0 = K0=1024 (fc1, 24 logical chunks), 1 = K0=256 (DH layers, 6 chunks).
// SPLIT: 0 none, 1 A-side [h|l] out, 3 ehet routing, 4 fused score.
#define L_AST   17408                    // 64*272
#define L_STAGE 52224                    // + 128*272
#define LSMEM_DYN (2 * L_STAGE + 512)

template<bool LEAKY, bool ADD, int SPLIT, bool COLSUM, int KMAP>
__global__ __launch_bounds__(256, 2)
void lin_mma(const __nv_bfloat16* __restrict__ A, const __nv_bfloat16* __restrict__ Bw,
             const float* __restrict__ bias, const float* __restrict__ Cin,
             float* __restrict__ C, __nv_bfloat16* __restrict__ S,
             const float* __restrict__ aux, int N)
{
    extern __shared__ char smem[];
    const int tid = threadIdx.x;
    const int lane = tid & 31, wid = tid >> 5;
    const int wr = wid >> 2, wc = wid & 3;
    const int bx = blockIdx.x, by = blockIdx.y;
    uint32_t sb = smem_u32(smem);
    float* colacc = (float*)(smem + 2 * L_STAGE);
    if (COLSUM && tid < 128) colacc[tid] = 0.f;
    const int KbS = (KMAP == 0) ? 4096 : 1024;     // storage bytes per row
    const int nch = (KMAP == 0) ? 24 : 6;          // logical 128-elem chunks
    const char* Abase = ((const char*)A)  + (size_t)(by * 64)  * KbS;
    const char* Bbase = ((const char*)Bw) + (size_t)(bx * 128) * KbS;

    auto load_chunk = [&](int c, int s) {
        int srcA, srcB;
        if (KMAP == 0) { srcA = (c < 8) ? c : c - 8;  srcB = (c < 16) ? c : c - 16; }
        else           { srcA = (c < 2) ? c : c - 2;  srcB = (c < 4)  ? c : c - 4;  }
        uint32_t aSt = sb + s * L_STAGE;
        uint32_t bSt = aSt + L_AST;
        int coffA = srcA * 256, coffB = srcB * 256;
        int r = tid >> 4, cc = tid & 15;
        #pragma unroll
        for (int j = 0; j < 4; j++) {
            int rr = r + j * 16;
            cp16(aSt + rr * 272 + cc * 16, Abase + (size_t)rr * KbS + coffA + cc * 16);
        }
        #pragma unroll
        for (int j = 0; j < 8; j++) {
            int rr = r + j * 16;
            cp16(bSt + rr * 272 + cc * 16, Bbase + (size_t)rr * KbS + coffB + cc * 16);
        }
    };

    float d[2][4][4];
    #pragma unroll
    for (int mf = 0; mf < 2; mf++)
        #pragma unroll
        for (int nf = 0; nf < 4; nf++)
            #pragma unroll
            for (int q = 0; q < 4; q++) d[mf][nf][q] = 0.f;

    load_chunk(0, 0); CP_COMMIT();
    load_chunk(1, 1); CP_COMMIT();

    const int arow_j = ((lane >> 3) & 1) * 8 + (lane & 7);
    const int akb    = (lane >> 4) * 16;
    const int bj     = lane >> 3;
    const int bn_off = (bj >> 1) * 8 + (lane & 7);
    const int bkb    = (bj & 1) * 16;

    for (int c = 0; c < nch; c++) {
        if (c + 1 < nch) { CP_WAIT1(); } else { CP_WAIT0(); }
        __syncthreads();
        uint32_t aSt = sb + (c & 1) * L_STAGE;
        uint32_t bSt = aSt + L_AST;

        #pragma unroll
        for (int ks = 0; ks < 8; ks++) {
            uint32_t a[2][4], b[4][2];
            #pragma unroll
            for (int mf = 0; mf < 2; mf++) {
                int row = wr * 32 + mf * 16 + arow_j;
                ldsm_x4(a[mf], aSt + row * 272 + ks * 32 + akb);
            }
            {
                uint32_t bv[4];
                int row0 = wc * 32 + bn_off;
                ldsm_x4(bv, bSt + row0 * 272 + ks * 32 + bkb);
                b[0][0] = bv[0]; b[0][1] = bv[1]; b[1][0] = bv[2]; b[1][1] = bv[3];
                int row1 = row0 + 16;
                ldsm_x4(bv, bSt + row1 * 272 + ks * 32 + bkb);
                b[2][0] = bv[0]; b[2][1] = bv[1]; b[3][0] = bv[2]; b[3][1] = bv[3];
            }
            #pragma unroll
            for (int mf = 0; mf < 2; mf++)
                #pragma unroll
                for (int nf = 0; nf < 4; nf++)
                    mma_bf16(d[mf][nf], a[mf], b[nf]);
        }
        __syncthreads();
        if (c + 2 < nch) load_chunk(c + 2, c & 1);
        CP_COMMIT();
    }

    // ---- epilogue ----
    const int g = lane >> 2, tq = lane & 3;
    auto emit = [&](int r, int c, float v0, float v1) {
        v0 += bias[c]; v1 += bias[c + 1];
        if (SPLIT == 3) {
            __half2 hh = __floats2half2_rn(v0, v1);
            if (c < 256) {
                g_eh[(size_t)r * DH_ + c]     = v0;
                g_eh[(size_t)r * DH_ + c + 1] = v1;
                *(__half2*)&g_Ah[(size_t)r * DH_ + c] = hh;
            } else {
                int c2 = c - 256;
                g_et[(size_t)r * DH_ + c2]     = v0;
                g_et[(size_t)r * DH_ + c2 + 1] = v1;
                *(__half2*)&g_Bh[(size_t)r * DH_ + c2] = hh;
            }
            return;
        }
        if (LEAKY) { v0 = leaky_f(v0); v1 = leaky_f(v1); }
        if (ADD)   { v0 += Cin[(size_t)r * N + c]; v1 += Cin[(size_t)r * N + c + 1]; }
        if (SPLIT == 4) {
            atomicAdd(&g_s[r], v0 * aux[c] + v1 * aux[c + 1]);
            return;
        }
        C[(size_t)r * N + c]     = v0;
        C[(size_t)r * N + c + 1] = v1;
        if (COLSUM) {
            int cl = c - bx * 128;
            atomicAdd(&colacc[cl], v0);
            atomicAdd(&colacc[cl + 1], v1);
        }
        if (SPLIT == 1) {
            __nv_bfloat162 hh, ll;
            split_pair(v0, v1, hh, ll);
            size_t o = (size_t)r * 512 + c;
            *(__nv_bfloat162*)&S[o]       = hh;
            *(__nv_bfloat162*)&S[o + 256] = ll;
        }
    };
    #pragma unroll
    for (int mf = 0; mf < 2; mf++) {
        #pragma unroll
        for (int nf = 0; nf < 4; nf++) {
            int row = by * 64 + wr * 32 + mf * 16 + g;
            int col = bx * 128 + wc * 32 + nf * 8 + tq * 2;
            emit(row,     col, d[mf][nf][0], d[mf][nf][1]);
            emit(row + 8, col, d[mf][nf][2], d[mf][nf][3]);
        }
    }
    if (COLSUM) {
        __syncthreads();
        if (tid < 128) atomicAdd(&g_mean[bx * 128 + tid], colacc[tid]);
    }
}

// ---------------- NT GEMM (fp16, K=256, BK=64, 2-stage, occ 2): ranking + top-6 --------
// Stage: (128 A + 256 B) rows x 144 B = 55296 B; 2 stages = 110592 <= 113.5 KB -> occ 2.
#define NT_AST   18432                   // 128*144
#define NT_STAGE 55296
#define SMEM_NT  110592                  // epilogue 64x259x4 = 66304 reuses stage mem

__global__ __launch_bounds__(256, 2)
void gemm_nt_mma() {
    extern __shared__ char smem[];
    const int tid = threadIdx.x;
    const int wid = tid >> 5, lane = tid & 31;
    const int wr = wid >> 2, wc = wid & 3;     // 2 x 4 warps, 64x64 each
    const int bx = blockIdx.x, by = blockIdx.y;
    uint32_t sb = smem_u32(smem);
    const int Kb = DH_ * 2;
    const char* Abase = ((const char*)g_Ah) + (size_t)(by * 128) * Kb;
    const char* Bbase = ((const char*)g_Bh) + (size_t)(bx * 256) * Kb;

    auto load_chunk = [&](int c, int s) {
        uint32_t aSt = sb + s * NT_STAGE;
        uint32_t bSt = aSt + NT_AST;
        int coff = c * 128;
        int r = tid >> 3, cc = tid & 7;        // 32 rows per pass, 8 x 16B cols
        #pragma unroll
        for (int j = 0; j < 4; j++) {          // A: 128 rows
            int rr = r + j * 32;
            cp16(aSt + rr * 144 + cc * 16, Abase + (size_t)rr * Kb + coff + cc * 16);
        }
        #pragma unroll
        for (int j = 0; j < 8; j++) {          // B: 256 rows
            int rr = r + j * 32;
            cp16(bSt + rr * 144 + cc * 16, Bbase + (size_t)rr * Kb + coff + cc * 16);
        }
    };

    uint32_t d2[4][8][2];
    #pragma unroll
    for (int mf = 0; mf < 4; mf++)
        #pragma unroll
        for (int nf = 0; nf < 8; nf++) { d2[mf][nf][0] = 0u; d2[mf][nf][1] = 0u; }

    load_chunk(0, 0); CP_COMMIT();
    load_chunk(1, 1); CP_COMMIT();

    const int arow_j = ((lane >> 3) & 1) * 8 + (lane & 7);
    const int akb    = (lane >> 4) * 16;
    const int bj     = lane >> 3;
    const int bn_off = (bj >> 1) * 8 + (lane & 7);
    const int bkb    = (bj & 1) * 16;

    for (int c = 0; c < 4; c++) {
        if (c < 3) { CP_WAIT1(); } else { CP_WAIT0(); }
        __syncthreads();
        uint32_t aSt = sb + (c & 1) * NT_STAGE;
        uint32_t bSt = aSt + NT_AST;

        #pragma unroll
        for (int ks = 0; ks < 4; ks++) {
            uint32_t a[4][4], b[8][2];
            #pragma unroll
            for (int mf = 0; mf < 4; mf++) {
                int row = wr * 64 + mf * 16 + arow_j;
                ldsm_x4(a[mf], aSt + row * 144 + ks * 32 + akb);
            }
            #pragma unroll
            for (int nb = 0; nb < 4; nb++) {
                uint32_t bv[4];
                int row = wc * 64 + nb * 16 + bn_off;
                ldsm_x4(bv, bSt + row * 144 + ks * 32 + bkb);
                b[nb*2][0]   = bv[0]; b[nb*2][1]   = bv[1];
                b[nb*2+1][0] = bv[2]; b[nb*2+1][1] = bv[3];
            }
            #pragma unroll
            for (int mf = 0; mf < 4; mf++)
                #pragma unroll
                for (int nf = 0; nf < 8; nf++)
                    mma_f16acc(d2[mf][nf], a[mf], b[nf]);
        }
        __syncthreads();
        if (c + 2 < 4) load_chunk(c + 2, c & 1);
        CP_COMMIT();
    }

    // ---- epilogue in two 64-row phases: smem [64][259], per-(row, 128-col chunk) top-6 ----
    float* sE = (float*)smem;
    const int g = lane >> 2, tq = lane & 3;
    #pragma unroll
    for (int ph = 0; ph < 2; ph++) {
        __syncthreads();
        if (wr == ph) {
            #pragma unroll
            for (int mf = 0; mf < 4; mf++) {
                int lr = mf * 16 + g;          // local row within phase
                #pragma unroll
                for (int nf = 0; nf < 8; nf++) {
                    int cc = wc * 64 + nf * 8 + tq * 2;
                    __half2 p0 = *(__half2*)&d2[mf][nf][0];
                    __half2 p1 = *(__half2*)&d2[mf][nf][1];
                    sE[lr * 259 + cc]           = __low2float(p0);
                    sE[lr * 259 + cc + 1]       = __high2float(p0);
                    sE[(lr + 8) * 259 + cc]     = __low2float(p1);
                    sE[(lr + 8) * 259 + cc + 1] = __high2float(p1);
                }
            }
        }
        __syncthreads();
        if (tid < 128) {
            int row = tid & 63, ch = tid >> 6;
            float v[6]; int ix[6];
            #pragma unroll
            for (int k = 0; k < 6; k++) { v[k] = NEG_INF; ix[k] = 0; }
            int cb = bx * 256 + ch * 128;
            const float* rp = sE + row * 259 + ch * 128;
            for (int j = 0; j < 128; j++) {
                float val = rp[j] * 0.0625f;
                if (val > v[5]) {
                    v[5] = val; ix[5] = cb + j;
                    #pragma unroll
                    for (int k = 5; k > 0; k--) {
                        if (v[k] > v[k - 1]) {
                            float tv = v[k]; v[k] = v[k - 1]; v[k - 1] = tv;
                            int   ti = ix[k]; ix[k] = ix[k - 1]; ix[k - 1] = ti;
                        }
                    }
                }
            }
            size_t rg = (size_t)by * 128 + ph * 64 + row;
            size_t o = rg * CANDS + bx * 12 + ch * 6;
            #pragma unroll
            for (int k = 0; k < 6; k++) { g_candv[o + k] = v[k]; g_candi[o + k] = ix[k]; }
        }
    }
}

// ---------------- topk: approx top-12 -> exact rescore -> exact top-6 -> messages ------
__global__ __launch_bounds__(128)
void topk_msg_kernel() {
    int i = blockIdx.x;
    int t = threadIdx.x;
    const float* cv = g_candv + (size_t)i * CANDS;
    const int*   ci = g_candi + (size_t)i * CANDS;

    float lv[3]; int li[3];
    #pragma unroll
    for (int k = 0; k < 3; k++) { lv[k] = NEG_INF; li[k] = 0; }
    #pragma unroll
    for (int j = 0; j < 3; j++) {
        int c = t + j * 128;
        float v = cv[c];
        if (v > lv[2]) {
            lv[2] = v; li[2] = ci[c];
            #pragma unroll
            for (int k = 2; k > 0; k--) {
                if (lv[k] > lv[k - 1]) {
                    float tv = lv[k]; lv[k] = lv[k - 1]; lv[k - 1] = tv;
                    int   tx = li[k]; li[k] = li[k - 1]; li[k - 1] = tx;
                }
            }
        }
    }

    __shared__ float sv[128]; __shared__ int si[128];
    __shared__ int topi[12];
    for (int r = 0; r < 12; r++) {
        sv[t] = lv[0]; si[t] = t;
        __syncthreads();
        #pragma unroll
        for (int o = 64; o > 0; o >>= 1) {
            if (t < o && sv[t + o] > sv[t]) { sv[t] = sv[t + o]; si[t] = si[t + o]; }
            __syncthreads();
        }
        if (t == si[0]) {
            topi[r] = li[0];
            lv[0] = lv[1]; li[0] = li[1];
            lv[1] = lv[2]; li[1] = li[2];
            lv[2] = NEG_INF;
        }
        __syncthreads();
    }

    int ti12[12];
    #pragma unroll
    for (int k = 0; k < 12; k++) ti12[k] = topi[k];

    float ehv[2];
    #pragma unroll
    for (int u = 0; u < 2; u++) ehv[u] = g_eh[(size_t)i * DH_ + t + u * 128];

    float nb12[12][2];
    #pragma unroll
    for (int k = 0; k < 12; k++)
        #pragma unroll
        for (int u = 0; u < 2; u++)
            nb12[k][u] = g_et[(size_t)ti12[k] * DH_ + t + u * 128];

    __shared__ float part[4][12];
    __shared__ float tot[12];
    int lane = t & 31, wp = t >> 5;
    #pragma unroll
    for (int k = 0; k < 12; k++) {
        float s = ehv[0] * nb12[k][0] + ehv[1] * nb12[k][1];
        s = warp_sum(s);
        if (lane == 0) part[wp][k] = s;
    }
    __syncthreads();
    if (t < 12) tot[t] = (part[0][t] + part[1][t] + part[2][t] + part[3][t]) * 0.0625f;
    __syncthreads();

    float val12[12];
    #pragma unroll
    for (int k = 0; k < 12; k++) val12[k] = tot[k];
    int sel[6];
    unsigned used = 0;
    #pragma unroll
    for (int r = 0; r < 6; r++) {
        int best = -1; float bv = NEG_INF;
        #pragma unroll
        for (int k = 0; k < 12; k++) {
            if (!(used >> k & 1) && val12[k] > bv) { bv = val12[k]; best = k; }
        }
        used |= 1u << best;
        sel[r] = best;
    }

    float tv[6];
    float nb[6][2];
    #pragma unroll
    for (int k = 0; k < 6; k++) {
        tv[k] = val12[sel[k]];
        nb[k][0] = nb12[sel[k]][0];
        nb[k][1] = nb12[sel[k]][1];
    }
    float pm = tv[0];
    #pragma unroll
    for (int k = 1; k < 6; k++) pm = fmaxf(pm, tv[k]);
    float pk[6], ps = 0.f;
    #pragma unroll
    for (int k = 0; k < 6; k++) { pk[k] = expf(tv[k] - pm); ps += pk[k]; }
    float pinv = 1.f / ps;
    #pragma unroll
    for (int k = 0; k < 6; k++) pk[k] *= pinv;

    float sN[6], sG[6];
    #pragma unroll
    for (int k = 0; k < 6; k++) { sN[k] = 0.f; sG[k] = 0.f; }
    #pragma unroll
    for (int k = 0; k < 6; k++) {
        #pragma unroll
        for (int u = 0; u < 2; u++) {
            float ehr = pk[k] * nb[k][u] + (1.f - pk[k]) * ehv[u];
            float gt  = tanhf(ehv[u] + ehr);
            sN[k] += nb[k][u];
            sG[k] += gt;
        }
    }

    __syncthreads();
    #pragma unroll
    for (int q = 0; q < 6; q++) {
        float v = warp_sum(sN[q]); if (lane == 0) part[wp][q]     = v;
        float w = warp_sum(sG[q]); if (lane == 0) part[wp][6 + q] = w;
    }
    __syncthreads();
    if (t < 12) tot[t] = part[0][t] + part[1][t] + part[2][t] + part[3][t];
    __syncthreads();

    float kw[6], km = NEG_INF;
    #pragma unroll
    for (int k = 0; k < 6; k++) { kw[k] = tot[k] * tot[6 + k]; km = fmaxf(km, kw[k]); }
    float kp[6], ks = 0.f;
    #pragma unroll
    for (int k = 0; k < 6; k++) { kp[k] = expf(kw[k] - km); ks += kp[k]; }
    float kinv = 1.f / ks;

    #pragma unroll
    for (int u = 0; u < 2; u++) {
        float eN = 0.f;
        #pragma unroll
        for (int k = 0; k < 6; k++) eN += kp[k] * kinv * nb[k][u];
        int dcol = t + u * 128;
        float e = ehv[u];
        float av = e + eN;
        float mv = e * eN;
        __nv_bfloat16 ah = __float2bfloat16(av);
        __nv_bfloat16 al = __float2bfloat16(av - __bfloat162float(ah));
        __nv_bfloat16 mh = __float2bfloat16(mv);
        __nv_bfloat16 ml = __float2bfloat16(mv - __bfloat162float(mh));
        size_t o = (size_t)i * 512 + dcol;
        g_As[o] = ah; g_As[o + 256] = al;
        g_Ms[o] = mh; g_Ms[o + 256] = ml;
    }
}

// ---------------- readout: softmax stats + weighted accumulate ----------------
__global__ __launch_bounds__(1024)
void stat_kernel() {
    int t = threadIdx.x;
    __shared__ float sm[1024];
    float m = NEG_INF;
    for (int i = t; i < NP; i += 1024) m = fmaxf(m, g_s[i]);
    sm[t] = m; __syncthreads();
    for (int o = 512; o > 0; o >>= 1) { if (t < o) sm[t] = fmaxf(sm[t], sm[t + o]); __syncthreads(); }
    float mx = sm[0];
    __syncthreads();
    float e = 0.f;
    for (int i = t; i < NP; i += 1024) e += expf(g_s[i] - mx);
    sm[t] = e; __syncthreads();
    for (int o = 512; o > 0; o >>= 1) { if (t < o) sm[t] += sm[t + o]; __syncthreads(); }
    if (t == 0) { g_stat[0] = mx; g_stat[1] = sm[0]; }
}

__global__ __launch_bounds__(256)
void accum_kernel(const float* __restrict__ emsg, float* __restrict__ eg) {
    int t = threadIdx.x;
    int r0 = blockIdx.x * 256;
    __shared__ float w[256];
    float mx = g_stat[0], inv = 1.f / g_stat[1];
    w[t] = expf(g_s[r0 + t] - mx) * inv;
    __syncthreads();
    float acc = 0.f;
    for (int r = 0; r < 256; r++) acc += w[r] * emsg[(size_t)(r0 + r) * DH_ + t];
    atomicAdd(&eg[t], acc);
}

// ---------------- launcher ----------------
extern "C" void kernel_launch(void* const* d_in, const int* in_sizes, int n_in,
                              void* d_out, int out_size) {
    const float* x_path = (const float*)d_in[0];
    const float* fc1_W  = (const float*)d_in[1];
    const float* fc1_b  = (const float*)d_in[2];
    const float* Wh     = (const float*)d_in[3];
    const float* bh     = (const float*)d_in[4];
    const float* Wt     = (const float*)d_in[5];
    const float* bt     = (const float*)d_in[6];
    const float* W1     = (const float*)d_in[7];
    const float* b1     = (const float*)d_in[8];
    const float* W2     = (const float*)d_in[9];
    const float* b2     = (const float*)d_in[10];
    const float* Ag1    = (const float*)d_in[11];
    const float* bg1    = (const float*)d_in[12];
    const float* Ag2    = (const float*)d_in[13];
    // bg2 unused: softmax over scores is shift-invariant.

    float* out    = (float*)d_out;               // e_msg: 8192 x 256
    float* out_eg = out + (size_t)NP * DH_;      // e_g: 256

    void *px, *ph, *pPs, *pXs, *pAs, *pMs, *pEs;
    void *pWfc1, *pWcat, *pW1s, *pW2s, *pAg1s, *pbcat;
    cudaGetSymbolAddress(&px,  g_x);
    cudaGetSymbolAddress(&ph,  g_h);
    cudaGetSymbolAddress(&pPs,  g_Ps);
    cudaGetSymbolAddress(&pXs,  g_Xs);
    cudaGetSymbolAddress(&pAs,  g_As);
    cudaGetSymbolAddress(&pMs,  g_Ms);
    cudaGetSymbolAddress(&pEs,  g_Es);
    cudaGetSymbolAddress(&pWfc1, g_Wfc1s);
    cudaGetSymbolAddress(&pWcat, g_Wcat);
    cudaGetSymbolAddress(&pW1s, g_W1s);
    cudaGetSymbolAddress(&pW2s, g_W2s);
    cudaGetSymbolAddress(&pAg1s, g_Ag1s);
    cudaGetSymbolAddress(&pbcat, g_bcat);

    cudaFuncSetAttribute(gemm_nt_mma, cudaFuncAttributeMaxDynamicSharedMemorySize, SMEM_NT);
    cudaFuncSetAttribute(lin_mma<true, false, 0, true, 0>,  cudaFuncAttributeMaxDynamicSharedMemorySize, LSMEM_DYN);
    cudaFuncSetAttribute(lin_mma<true, false, 0, false, 1>, cudaFuncAttributeMaxDynamicSharedMemorySize, LSMEM_DYN);
    cudaFuncSetAttribute(lin_mma<false, false, 3, false, 1>,cudaFuncAttributeMaxDynamicSharedMemorySize, LSMEM_DYN);
    cudaFuncSetAttribute(lin_mma<true, true, 1, false, 1>,  cudaFuncAttributeMaxDynamicSharedMemorySize, LSMEM_DYN);
    cudaFuncSetAttribute(lin_mma<true, false, 4, false, 1>, cudaFuncAttributeMaxDynamicSharedMemorySize, LSMEM_DYN);

    // 0: merged prep (weight [h|l] splits + bcat + zero)
    prep_kernel<<<2209, 256>>>(fc1_W, Wh, Wt, W1, W2, Ag1, bh, bt, out_eg);
    // 1: x_path [h|l] split
    splita_kernel<<<NP * (DIN_/2) / 256, 256>>>(x_path, (__nv_bfloat16*)pPs, DIN_);
    // 2: fc1 + leaky -> g_x (+fused colsum)
    lin_mma<true, false, 0, true, 0><<<dim3(2, 128), 256, LSMEM_DYN>>>(
        (const __nv_bfloat16*)pPs, (const __nv_bfloat16*)pWfc1, fc1_b, nullptr,
        (float*)px, nullptr, nullptr, DH_);
    // 3: mean-mix (+[h|l] split of x)
    mix_split_kernel<<<NP * 128 / 256, 256>>>();
    // 4: merged e_h|e_t (N=512) with routed epilogue (fp32 + fp16 operands)
    lin_mma<false, false, 3, false, 1><<<dim3(4, 128), 256, LSMEM_DYN>>>(
        (const __nv_bfloat16*)pXs, (const __nv_bfloat16*)pWcat, (const float*)pbcat,
        nullptr, nullptr, nullptr, nullptr, 512);
    // 5: fp16 NT ranking GEMM (occ 2) + fused approx top-6 per chunk
    gemm_nt_mma<<<dim3(32, 64), 256, SMEM_NT>>>();
    // 6: approx top-12 -> exact rescore -> exact top-6 -> messages
    topk_msg_kernel<<<NP, 128>>>();
    // 7-8: e_msg = leaky(a@W1+b1) + leaky(m@W2+b2) -> out (+[h|l] split for Ag1)
    lin_mma<true, false, 0, false, 1><<<dim3(2, 128), 256, LSMEM_DYN>>>(
        (const __nv_bfloat16*)pAs, (const __nv_bfloat16*)pW1s, b1, nullptr,
        out, nullptr, nullptr, DH_);
    lin_mma<true, true, 1, false, 1><<<dim3(2, 128), 256, LSMEM_DYN>>>(
        (const __nv_bfloat16*)pMs, (const __nv_bfloat16*)pW2s, b2, out,
        out, (__nv_bfloat16*)pEs, nullptr, DH_);
    // 9: readout hidden + fused score (s_i = leaky(e_msg@Ag1+bg1) . Ag2)
    lin_mma<true, false, 4, false, 1><<<dim3(1, 128), 256, LSMEM_DYN>>>(
        (const __nv_bfloat16*)pEs, (const __nv_bfloat16*)pAg1s, bg1, nullptr,
        (float*)ph, nullptr, Ag2, DH_/2);
    // 10-11: softmax stats + gated readout
    stat_kernel<<<1, 1024>>>();
    accum_kernel<<<32, 256>>>(out, out_eg);
}